// round 6
// baseline (speedup 1.0000x reference)
#include <cuda_runtime.h>

#define NVEH 4096
#define NT 256
#define PAST 25
#define LEADLEN (NT + PAST - 1)   // 280
#define NPAIR (NVEH / 2)          // 2048 vehicle pairs
#define WARPS_PER_CTA 14
#define NCTA ((NPAIR + WARPS_PER_CTA - 1) / WARPS_PER_CTA)   // 147
#define NTHREADS (WARPS_PER_CTA * 32)                         // 448

typedef unsigned long long ull;

// ---- shared memory layout (float offsets) ----
#define W1_OFF    0        // 288  : conv1_w [3][3][32]
#define B1_OFF    288      // 32
#define B2P_OFF   320      // 64   : ull pair {b2[c], b2[c+32]}
#define W2X_OFF   384      // 4096 : ull2 [ci][lane] = {k0pair, k1pair}
#define W2K2_OFF  4480     // 2048 : ull  [ci][lane] = k2pair
#define WD2X_OFF  6528     // 3840 : ull2 [(q*6+jj)][lane] = {pair_i, pair_{i+32}}, i=jj*64+lane
#define BD2_OFF   10368    // 10
#define WD1_OFF   10378    // 10
#define BD1_OFF   10388    // 1 (+3 pad)
#define XBUF_OFF  10392    // 28 veh-slots * 27 pos * 4 floats (zero-padded borders)
#define P1_OFF    13416    // 28 veh-slots * 13*32 ull (dup pairs, m-major)
#define SMEM_FLOATS (P1_OFF + 28 * 13 * 32 * 2)   // 36712 floats = 146848 B

__device__ __forceinline__ ull ffma2(ull a, ull b, ull c) {
    ull d;
    asm("fma.rn.f32x2 %0, %1, %2, %3;" : "=l"(d) : "l"(a), "l"(b), "l"(c));
    return d;
}
__device__ __forceinline__ void unpk(ull v, float& lo, float& hi) {
    asm("mov.b64 {%0, %1}, %2;" : "=f"(lo), "=f"(hi) : "l"(v));
}
__device__ __forceinline__ ull pkdup(float x) {
    ull d;
    asm("mov.b64 %0, {%1, %1};" : "=l"(d) : "f"(x));
    return d;
}

__global__ void __launch_bounds__(NTHREADS, 1)
rnncf_kernel(const float* __restrict__ lead, const float* __restrict__ cur,
             const float* __restrict__ w1g, const float* __restrict__ b1g,
             const float* __restrict__ w2g, const float* __restrict__ b2g,
             const float* __restrict__ wd2g, const float* __restrict__ bd2g,
             const float* __restrict__ wd1g, const float* __restrict__ bd1g,
             float* __restrict__ out)
{
    extern __shared__ float sm[];
    const int tid = threadIdx.x;

    // ---------- cooperative weight staging ----------
    for (int i = tid; i < 288; i += NTHREADS) sm[W1_OFF + i] = w1g[i];
    for (int i = tid; i < 32;  i += NTHREADS) sm[B1_OFF + i] = b1g[i];
    {
        float2* b2p = (float2*)(sm + B2P_OFF);
        for (int i = tid; i < 32; i += NTHREADS)
            b2p[i] = make_float2(b2g[i], b2g[i + 32]);
        // conv2 weights: w2g[(k*32+ci)*64 + c]
        float4* w2x = (float4*)(sm + W2X_OFF);
        float2* w2k2 = (float2*)(sm + W2K2_OFF);
        for (int i = tid; i < 1024; i += NTHREADS) {
            int ci = i >> 5, c = i & 31;
            w2x[i] = make_float4(w2g[ci * 64 + c],        w2g[ci * 64 + c + 32],
                                 w2g[(32 + ci) * 64 + c], w2g[(32 + ci) * 64 + c + 32]);
            w2k2[i] = make_float2(w2g[(64 + ci) * 64 + c], w2g[(64 + ci) * 64 + c + 32]);
        }
        // dense2 weights: wd2g[i*10 + o], flat i = jj*64 + c (+32 for second half)
        float4* wdx = (float4*)(sm + WD2X_OFF);
        for (int i = tid; i < 960; i += NTHREADS) {
            int q = i / 192, r = i - q * 192;
            int jj = r >> 5, c = r & 31;
            int ii = jj * 64 + c;
            wdx[i] = make_float4(wd2g[ii * 10 + 2 * q],        wd2g[ii * 10 + 2 * q + 1],
                                 wd2g[(ii + 32) * 10 + 2 * q], wd2g[(ii + 32) * 10 + 2 * q + 1]);
        }
    }
    for (int i = tid; i < 10; i += NTHREADS) sm[BD2_OFF + i] = bd2g[i];
    for (int i = tid; i < 10; i += NTHREADS) sm[WD1_OFF + i] = wd1g[i];
    if (tid == 0) sm[BD1_OFF] = bd1g[0];
    // zero xbuf: border slots (0 and 26) must stay 0; per-step writes touch 1..25 only
    for (int i = tid; i < 28 * 27 * 4; i += NTHREADS) sm[XBUF_OFF + i] = 0.0f;
    __syncthreads();

    const int wid = tid >> 5, lane = tid & 31;
    const int pairIdx = blockIdx.x * WARPS_PER_CTA + wid;
    if (pairIdx >= NPAIR) return;
    const int vA = 2 * pairIdx, vB = vA + 1;
    const int slotA = wid * 2, slotB = slotA + 1;

    float* xbA = sm + XBUF_OFF + slotA * (27 * 4);
    float* xbB = sm + XBUF_OFF + slotB * (27 * 4);
    ull* p1A = (ull*)(sm + P1_OFF) + slotA * (13 * 32);
    ull* p1B = (ull*)(sm + P1_OFF) + slotB * (13 * 32);
    const ulonglong2* w2x  = (const ulonglong2*)(sm + W2X_OFF);
    const ull*        w2k2 = (const ull*)(sm + W2K2_OFF);
    const ulonglong2* wdx  = (const ulonglong2*)(sm + WD2X_OFF);
    const ull*        b2p  = (const ull*)(sm + B2P_OFF);

    const float2* lead2A = (const float2*)lead + (size_t)vA * LEADLEN;
    const float2* lead2B = (const float2*)lead + (size_t)vB * LEADLEN;
    const float2* cur2A  = (const float2*)cur  + (size_t)vA * PAST;
    const float2* cur2B  = (const float2*)cur  + (size_t)vB * PAST;
    float2* out2A = (float2*)out + (size_t)vA * NT;
    float2* out2B = (float2*)out + (size_t)vB * NT;

    // ---------- initial windows: lane i (<25) holds CNN input column i ----------
    float x0a = 0.f, x1a = 0.f, x2a = 0.f, x0b = 0.f, x1b = 0.f, x2b = 0.f;
    float tpA = 0.f, tsA = 0.f, tpB = 0.f, tsB = 0.f;
    if (lane < PAST) {
        float2 csA = cur2A[lane], ldA = lead2A[lane];
        float2 csB = cur2B[lane], ldB = lead2B[lane];
        x0a = (ldA.x - csA.x) * (1.0f / 200.0f);
        x1a = csA.y * (1.0f / 40.0f);
        x2a = ldA.y * (1.0f / 40.0f);
        x0b = (ldB.x - csB.x) * (1.0f / 200.0f);
        x1b = csB.y * (1.0f / 40.0f);
        x2b = ldB.y * (1.0f / 40.0f);
        tpA = csA.x; tsA = csA.y; tpB = csB.x; tsB = csB.y;
    }
    float p24A = __shfl_sync(0xffffffffu, tpA, 24);
    float s24A = __shfl_sync(0xffffffffu, tsA, 24);
    float p24B = __shfl_sync(0xffffffffu, tpB, 24);
    float s24B = __shfl_sync(0xffffffffu, tsB, 24);

    #pragma unroll 1
    for (int t = 0; t < NT; ++t) {
        // prefetch next lead pairs (hide GMEM latency behind this step's CNN)
        float2 ldnA = make_float2(0.f, 0.f), ldnB = make_float2(0.f, 0.f);
        if (lane == 24 && t < NT - 1) {
            ldnA = lead2A[t + PAST];
            ldnB = lead2B[t + PAST];
        }

        // publish windows (index lane+1; slots 0 and 26 remain zero pad)
        if (lane < PAST) {
            *(float4*)(xbA + (lane + 1) * 4) = make_float4(x0a, x1a, x2a, 0.0f);
            *(float4*)(xbB + (lane + 1) * 4) = make_float4(x0b, x1b, x2b, 0.0f);
        }
        __syncwarp();

        // ---------- conv1 (lane = out channel) + relu + pool1, both vehicles ----------
        float w1r[9];
        #pragma unroll
        for (int i = 0; i < 9; ++i) w1r[i] = sm[W1_OFF + i * 32 + lane];
        float b1r = sm[B1_OFF + lane];

        auto conv1pool = [&](const float* xb, ull* p1) {
            float4 a = *(const float4*)(xb);
            float4 b = *(const float4*)(xb + 4);
            #pragma unroll
            for (int m = 0; m < 12; ++m) {
                float4 c1 = *(const float4*)(xb + (2 * m + 2) * 4);
                float4 c2 = *(const float4*)(xb + (2 * m + 3) * 4);
                float h0 = b1r;
                h0 = fmaf(a.x,  w1r[0], h0); h0 = fmaf(a.y,  w1r[1], h0); h0 = fmaf(a.z,  w1r[2], h0);
                h0 = fmaf(b.x,  w1r[3], h0); h0 = fmaf(b.y,  w1r[4], h0); h0 = fmaf(b.z,  w1r[5], h0);
                h0 = fmaf(c1.x, w1r[6], h0); h0 = fmaf(c1.y, w1r[7], h0); h0 = fmaf(c1.z, w1r[8], h0);
                float h1 = b1r;
                h1 = fmaf(b.x,  w1r[0], h1); h1 = fmaf(b.y,  w1r[1], h1); h1 = fmaf(b.z,  w1r[2], h1);
                h1 = fmaf(c1.x, w1r[3], h1); h1 = fmaf(c1.y, w1r[4], h1); h1 = fmaf(c1.z, w1r[5], h1);
                h1 = fmaf(c2.x, w1r[6], h1); h1 = fmaf(c2.y, w1r[7], h1); h1 = fmaf(c2.z, w1r[8], h1);
                float p = fmaxf(fmaxf(h0, 0.0f), fmaxf(h1, 0.0f));
                p1[m * 32 + lane] = pkdup(p);   // duplicated {p,p} for packed conv2
                a = c1; b = c2;
            }
            {   // pool slot 12: conv position 24 alone (SAME pool right pad)
                float4 c1 = *(const float4*)(xb + 26 * 4);   // zero pad column
                float h0 = b1r;
                h0 = fmaf(a.x,  w1r[0], h0); h0 = fmaf(a.y,  w1r[1], h0); h0 = fmaf(a.z,  w1r[2], h0);
                h0 = fmaf(b.x,  w1r[3], h0); h0 = fmaf(b.y,  w1r[4], h0); h0 = fmaf(b.z,  w1r[5], h0);
                h0 = fmaf(c1.x, w1r[6], h0); h0 = fmaf(c1.y, w1r[7], h0); h0 = fmaf(c1.z, w1r[8], h0);
                p1[12 * 32 + lane] = pkdup(fmaxf(h0, 0.0f));
            }
        };
        conv1pool(xbA, p1A);
        conv1pool(xbB, p1B);
        __syncwarp();

        // ---------- conv2: lane -> out channels {lane, lane+32}, both vehicles ----------
        // Activations read as broadcast LDS.128 channel-pairs {q_ci, q_ci+1}.
        // Weights loaded once per channel-pair, shared across both vehicles.
        ull accA[11], accB[11];
        {
            ull b2pair = b2p[lane];
            #pragma unroll
            for (int j = 0; j < 11; ++j) { accA[j] = b2pair; accB[j] = b2pair; }
        }
        const ulonglong2* p1vA = (const ulonglong2*)p1A;
        const ulonglong2* p1vB = (const ulonglong2*)p1B;
        #pragma unroll 1
        for (int cp = 0; cp < 16; ++cp) {
            ulonglong2 wk01_0 = w2x[(2 * cp)     * 32 + lane];   // ci=2cp:   {k0, k1}
            ulonglong2 wk01_1 = w2x[(2 * cp + 1) * 32 + lane];   // ci=2cp+1: {k0, k1}
            ull wk2_0 = w2k2[(2 * cp)     * 32 + lane];
            ull wk2_1 = w2k2[(2 * cp + 1) * 32 + lane];
            // vehicle A: stream positions, each qp used for (k=0,1,2) then dead
            #pragma unroll
            for (int m = 0; m < 13; ++m) {
                ulonglong2 qp = p1vA[m * 16 + cp];
                if (m <= 10) {
                    accA[m] = ffma2(qp.x, wk01_0.x, accA[m]);
                    accA[m] = ffma2(qp.y, wk01_1.x, accA[m]);
                }
                if (m >= 1 && m <= 11) {
                    accA[m-1] = ffma2(qp.x, wk01_0.y, accA[m-1]);
                    accA[m-1] = ffma2(qp.y, wk01_1.y, accA[m-1]);
                }
                if (m >= 2) {
                    accA[m-2] = ffma2(qp.x, wk2_0, accA[m-2]);
                    accA[m-2] = ffma2(qp.y, wk2_1, accA[m-2]);
                }
            }
            // vehicle B
            #pragma unroll
            for (int m = 0; m < 13; ++m) {
                ulonglong2 qp = p1vB[m * 16 + cp];
                if (m <= 10) {
                    accB[m] = ffma2(qp.x, wk01_0.x, accB[m]);
                    accB[m] = ffma2(qp.y, wk01_1.x, accB[m]);
                }
                if (m >= 1 && m <= 11) {
                    accB[m-1] = ffma2(qp.x, wk01_0.y, accB[m-1]);
                    accB[m-1] = ffma2(qp.y, wk01_1.y, accB[m-1]);
                }
                if (m >= 2) {
                    accB[m-2] = ffma2(qp.x, wk2_0, accB[m-2]);
                    accB[m-2] = ffma2(qp.y, wk2_1, accB[m-2]);
                }
            }
        }

        // ---------- relu + pool2 -> packed activations for dense2 ----------
        ull fapA[6], fbpA[6], fapB[6], fbpB[6];
        auto pool2 = [&](const ull* acc, ull* fap, ull* fbp) {
            #pragma unroll
            for (int jj = 0; jj < 5; ++jj) {
                float l0, h0c, l1, h1c;
                unpk(acc[2 * jj],     l0, h0c);
                unpk(acc[2 * jj + 1], l1, h1c);
                fap[jj] = pkdup(fmaxf(fmaxf(l0, 0.f), fmaxf(l1, 0.f)));
                fbp[jj] = pkdup(fmaxf(fmaxf(h0c, 0.f), fmaxf(h1c, 0.f)));
            }
            float l0, h0c;
            unpk(acc[10], l0, h0c);   // position 10, window of one
            fap[5] = pkdup(fmaxf(l0, 0.f));
            fbp[5] = pkdup(fmaxf(h0c, 0.f));
        };
        pool2(accA, fapA, fbpA);
        pool2(accB, fapB, fbpB);

        // ---------- dense2: weights loaded once, applied to both vehicles ----------
        float dA[10], dB[10];
        #pragma unroll
        for (int q = 0; q < 5; ++q) {
            ull sA = 0ull, sB = 0ull;   // packed {0.f, 0.f}
            #pragma unroll
            for (int jj = 0; jj < 6; ++jj) {
                ulonglong2 w = wdx[(q * 6 + jj) * 32 + lane];  // {pair_i, pair_{i+32}}
                sA = ffma2(fapA[jj], w.x, sA);
                sA = ffma2(fbpA[jj], w.y, sA);
                sB = ffma2(fapB[jj], w.x, sB);
                sB = ffma2(fbpB[jj], w.y, sB);
            }
            unpk(sA, dA[2 * q], dA[2 * q + 1]);
            unpk(sB, dB[2 * q], dB[2 * q + 1]);
        }
        #pragma unroll
        for (int off = 16; off > 0; off >>= 1) {
            #pragma unroll
            for (int o = 0; o < 10; ++o) {
                dA[o] += __shfl_xor_sync(0xffffffffu, dA[o], off);
                dB[o] += __shfl_xor_sync(0xffffffffu, dB[o], off);
            }
        }

        // ---------- dense1 + output scaling ----------
        float bd1v = sm[BD1_OFF];
        float yA = bd1v, yB = bd1v;
        #pragma unroll
        for (int o = 0; o < 10; ++o) {
            float bd = sm[BD2_OFF + o];
            float wd = sm[WD1_OFF + o];
            yA = fmaf(fmaxf(dA[o] + bd, 0.0f), wd, yA);
            yB = fmaf(fmaxf(dB[o] + bd, 0.0f), wd, yB);
        }
        float accvA = fmaf(10.0f, yA, -6.0f);   // (MAXA-MINA)*y + MINA
        float accvB = fmaf(10.0f, yB, -6.0f);

        // ---------- recurrence + output ----------
        float ppA = fmaf(0.1f, s24A,  p24A);
        float psA = fmaf(0.1f, accvA, s24A);
        float ppB = fmaf(0.1f, s24B,  p24B);
        float psB = fmaf(0.1f, accvB, s24B);
        if (lane == 0) out2A[t] = make_float2(ppA, psA);
        if (lane == 1) out2B[t] = make_float2(ppB, psB);

        x0a = __shfl_down_sync(0xffffffffu, x0a, 1);
        x1a = __shfl_down_sync(0xffffffffu, x1a, 1);
        x2a = __shfl_down_sync(0xffffffffu, x2a, 1);
        x0b = __shfl_down_sync(0xffffffffu, x0b, 1);
        x1b = __shfl_down_sync(0xffffffffu, x1b, 1);
        x2b = __shfl_down_sync(0xffffffffu, x2b, 1);
        if (lane == 24) {
            x0a = (ldnA.x - ppA) * (1.0f / 200.0f);
            x1a = psA * (1.0f / 40.0f);
            x2a = ldnA.y * (1.0f / 40.0f);
            x0b = (ldnB.x - ppB) * (1.0f / 200.0f);
            x1b = psB * (1.0f / 40.0f);
            x2b = ldnB.y * (1.0f / 40.0f);
        }
        p24A = ppA; s24A = psA;
        p24B = ppB; s24B = psB;
    }
}

extern "C" void kernel_launch(void* const* d_in, const int* in_sizes, int n_in,
                              void* d_out, int out_size)
{
    const float* lead = (const float*)d_in[0];   // (4096, 280, 2)
    const float* cur  = (const float*)d_in[1];   // (4096, 25, 2)
    // d_in[2] = mask (unused by the reference computation)
    const float* w1  = (const float*)d_in[3];
    const float* b1  = (const float*)d_in[4];
    const float* w2  = (const float*)d_in[5];
    const float* b2  = (const float*)d_in[6];
    const float* wd2 = (const float*)d_in[7];
    const float* bd2 = (const float*)d_in[8];
    const float* wd1 = (const float*)d_in[9];
    const float* bd1 = (const float*)d_in[10];
    float* out = (float*)d_out;                   // (4096, 256, 2)

    (void)in_sizes; (void)n_in; (void)out_size;

    size_t smem_bytes = (size_t)SMEM_FLOATS * sizeof(float);
    cudaFuncSetAttribute(rnncf_kernel,
                         cudaFuncAttributeMaxDynamicSharedMemorySize,
                         (int)smem_bytes);
    rnncf_kernel<<<NCTA, NTHREADS, smem_bytes>>>(
        lead, cur, w1, b1, w2, b2, wd2, bd2, wd1, bd1, out);
}

// round 7
// speedup vs baseline: 1.7659x; 1.7659x over previous
#include <cuda_runtime.h>

#define NVEH 4096
#define NT 256
#define PAST 25
#define LEADLEN (NT + PAST - 1)   // 280
#define WARPS_PER_CTA 28
#define NCTA ((NVEH + WARPS_PER_CTA - 1) / WARPS_PER_CTA)   // 147
#define NTHREADS (WARPS_PER_CTA * 32)                        // 896

typedef unsigned long long ull;

// ---- shared memory layout (float offsets) ----
#define W1_OFF    0        // 288  : conv1_w [3][3][32]
#define B1_OFF    288      // 32
#define B2P_OFF   320      // 64   : ull pair {b2[c], b2[c+32]}
#define W2X_OFF   384      // 4096 : ull2 [ci][lane] = {k0pair, k1pair}
#define W2K2_OFF  4480     // 2048 : ull  [ci][lane] = k2pair
#define WD2X_OFF  6528     // 3840 : ull2 [(q*6+jj)][lane] = {pair_i, pair_{i+32}}
#define BD2_OFF   10368    // 10
#define WD1_OFF   10378    // 10
#define BD1_OFF   10388    // 1 (+3 pad)
#define XBUF_OFF  10392    // 28 * 27 * 4 floats (zero-padded borders)
#define P1_OFF    13416    // 28 * 13*32 ull (dup pairs)
#define S_OFF     (P1_OFF + 28 * 13 * 32 * 2)    // 36712 : odd-parity conv2 state, 28 * 11*32 ull
#define SMEM_FLOATS (S_OFF + 28 * 11 * 32 * 2)   // 56424 floats = 225696 B

__device__ __forceinline__ ull ffma2(ull a, ull b, ull c) {
    ull d;
    asm("fma.rn.f32x2 %0, %1, %2, %3;" : "=l"(d) : "l"(a), "l"(b), "l"(c));
    return d;
}
__device__ __forceinline__ void unpk(ull v, float& lo, float& hi) {
    asm("mov.b64 {%0, %1}, %2;" : "=f"(lo), "=f"(hi) : "l"(v));
}
__device__ __forceinline__ ull pkdup(float x) {
    ull d;
    asm("mov.b64 %0, {%1, %1};" : "=l"(d) : "f"(x));
    return d;
}

__global__ void __launch_bounds__(NTHREADS, 1)
rnncf_kernel(const float* __restrict__ lead, const float* __restrict__ cur,
             const float* __restrict__ w1g, const float* __restrict__ b1g,
             const float* __restrict__ w2g, const float* __restrict__ b2g,
             const float* __restrict__ wd2g, const float* __restrict__ bd2g,
             const float* __restrict__ wd1g, const float* __restrict__ bd1g,
             float* __restrict__ out)
{
    extern __shared__ float sm[];
    const int tid = threadIdx.x;

    // ---------- cooperative weight staging ----------
    for (int i = tid; i < 288; i += NTHREADS) sm[W1_OFF + i] = w1g[i];
    for (int i = tid; i < 32;  i += NTHREADS) sm[B1_OFF + i] = b1g[i];
    {
        float2* b2p_s = (float2*)(sm + B2P_OFF);
        for (int i = tid; i < 32; i += NTHREADS)
            b2p_s[i] = make_float2(b2g[i], b2g[i + 32]);
        // conv2 weights: w2g[(k*32+ci)*64 + c]
        float4* w2x_s = (float4*)(sm + W2X_OFF);
        float2* w2k2_s = (float2*)(sm + W2K2_OFF);
        for (int i = tid; i < 1024; i += NTHREADS) {
            int ci = i >> 5, c = i & 31;
            w2x_s[i] = make_float4(w2g[ci * 64 + c],        w2g[ci * 64 + c + 32],
                                   w2g[(32 + ci) * 64 + c], w2g[(32 + ci) * 64 + c + 32]);
            w2k2_s[i] = make_float2(w2g[(64 + ci) * 64 + c], w2g[(64 + ci) * 64 + c + 32]);
        }
        // dense2 weights: wd2g[i*10 + o], flat i = jj*64 + c (+32 second half)
        float4* wdx_s = (float4*)(sm + WD2X_OFF);
        for (int i = tid; i < 960; i += NTHREADS) {
            int q = i / 192, r = i - q * 192;
            int jj = r >> 5, c = r & 31;
            int ii = jj * 64 + c;
            wdx_s[i] = make_float4(wd2g[ii * 10 + 2 * q],        wd2g[ii * 10 + 2 * q + 1],
                                   wd2g[(ii + 32) * 10 + 2 * q], wd2g[(ii + 32) * 10 + 2 * q + 1]);
        }
    }
    for (int i = tid; i < 10; i += NTHREADS) sm[BD2_OFF + i] = bd2g[i];
    for (int i = tid; i < 10; i += NTHREADS) sm[WD1_OFF + i] = wd1g[i];
    if (tid == 0) sm[BD1_OFF] = bd1g[0];
    // zero xbuf: border slots (0 and 26) must stay 0; per-step writes touch 1..25 only
    for (int i = tid; i < WARPS_PER_CTA * 27 * 4; i += NTHREADS) sm[XBUF_OFF + i] = 0.0f;
    __syncthreads();

    const int wid = tid >> 5, lane = tid & 31;
    const int v = blockIdx.x * WARPS_PER_CTA + wid;
    if (v >= NVEH) return;

    float* xb = sm + XBUF_OFF + wid * (27 * 4);
    ull* p1 = (ull*)(sm + P1_OFF) + wid * (13 * 32);
    const ulonglong2* p1v = (const ulonglong2*)p1;
    ull* Ssm = (ull*)(sm + S_OFF) + wid * (11 * 32);
    const ulonglong2* w2x  = (const ulonglong2*)(sm + W2X_OFF);
    const ull*        w2k2 = (const ull*)(sm + W2K2_OFF);
    const ulonglong2* wdx  = (const ulonglong2*)(sm + WD2X_OFF);
    const ull*        b2p  = (const ull*)(sm + B2P_OFF);

    const float2* lead2 = (const float2*)lead + (size_t)v * LEADLEN;
    const float2* cur2  = (const float2*)cur  + (size_t)v * PAST;
    float2* out2 = (float2*)out + (size_t)v * NT;

    // conv1 weights hoisted (constant across steps)
    float w1r[9];
    #pragma unroll
    for (int i = 0; i < 9; ++i) w1r[i] = sm[W1_OFF + i * 32 + lane];
    const float b1r = sm[B1_OFF + lane];

    // ---------- initial window: lane i (<25) holds CNN input column i ----------
    float x0 = 0.f, x1 = 0.f, x2 = 0.f, tp = 0.f, ts = 0.f;
    if (lane < PAST) {
        float2 cs = cur2[lane];
        float2 ld = lead2[lane];
        x0 = (ld.x - cs.x) * (1.0f / 200.0f);
        x1 = cs.y * (1.0f / 40.0f);
        x2 = ld.y * (1.0f / 40.0f);
        tp = cs.x; ts = cs.y;
    }
    float p24 = __shfl_sync(0xffffffffu, tp, 24);
    float s24 = __shfl_sync(0xffffffffu, ts, 24);
    float2 ldn = make_float2(0.f, 0.f);

    // ---------- helpers ----------
    auto conv1pos = [&](float4 a, float4 b, float4 c) -> float {
        float h = b1r;
        h = fmaf(a.x, w1r[0], h); h = fmaf(a.y, w1r[1], h); h = fmaf(a.z, w1r[2], h);
        h = fmaf(b.x, w1r[3], h); h = fmaf(b.y, w1r[4], h); h = fmaf(b.z, w1r[5], h);
        h = fmaf(c.x, w1r[6], h); h = fmaf(c.y, w1r[7], h); h = fmaf(c.z, w1r[8], h);
        return h;
    };

    auto publish = [&]() {
        if (lane < PAST)
            *(float4*)(xb + (lane + 1) * 4) = make_float4(x0, x1, x2, 0.0f);
        __syncwarp();
    };

    auto conv1_full = [&]() {   // all 13 pool1 slots (seed steps)
        float4 a = *(const float4*)(xb);
        float4 b = *(const float4*)(xb + 4);
        #pragma unroll
        for (int m = 0; m < 12; ++m) {
            float4 c1 = *(const float4*)(xb + (2 * m + 2) * 4);
            float4 c2 = *(const float4*)(xb + (2 * m + 3) * 4);
            float h0 = conv1pos(a, b, c1);
            float h1 = conv1pos(b, c1, c2);
            p1[m * 32 + lane] = pkdup(fmaxf(fmaxf(h0, 0.f), fmaxf(h1, 0.f)));
            a = c1; b = c2;
        }
        float4 c1 = *(const float4*)(xb + 26 * 4);   // zero pad
        p1[12 * 32 + lane] = pkdup(fmaxf(conv1pos(a, b, c1), 0.f));
        __syncwarp();
    };

    auto conv1_inc = [&]() {    // boundary pool1 slots 0..2 and 9..12 only
        {   // slots 0..2 from conv positions 0..5
            float4 a = *(const float4*)(xb);
            float4 b = *(const float4*)(xb + 4);
            #pragma unroll
            for (int m = 0; m < 3; ++m) {
                float4 c1 = *(const float4*)(xb + (2 * m + 2) * 4);
                float4 c2 = *(const float4*)(xb + (2 * m + 3) * 4);
                float h0 = conv1pos(a, b, c1);
                float h1 = conv1pos(b, c1, c2);
                p1[m * 32 + lane] = pkdup(fmaxf(fmaxf(h0, 0.f), fmaxf(h1, 0.f)));
                a = c1; b = c2;
            }
        }
        {   // slots 9..12 from conv positions 18..24
            float4 a = *(const float4*)(xb + 18 * 4);   // col 17
            float4 b = *(const float4*)(xb + 19 * 4);   // col 18
            #pragma unroll
            for (int m = 9; m < 12; ++m) {
                float4 c1 = *(const float4*)(xb + (2 * m + 2) * 4);
                float4 c2 = *(const float4*)(xb + (2 * m + 3) * 4);
                float h0 = conv1pos(a, b, c1);
                float h1 = conv1pos(b, c1, c2);
                p1[m * 32 + lane] = pkdup(fmaxf(fmaxf(h0, 0.f), fmaxf(h1, 0.f)));
                a = c1; b = c2;
            }
            float4 c1 = *(const float4*)(xb + 26 * 4);  // zero pad
            p1[12 * 32 + lane] = pkdup(fmaxf(conv1pos(a, b, c1), 0.f));
        }
        __syncwarp();
    };

    auto conv2_full = [&](ull* acc) {   // seed: all 11 positions
        ull bp = b2p[lane];
        #pragma unroll
        for (int j = 0; j < 11; ++j) acc[j] = bp;
        #pragma unroll 1
        for (int cp = 0; cp < 16; ++cp) {
            ulonglong2 wa = w2x[(2 * cp)     * 32 + lane];   // ci=2cp   {k0,k1}
            ulonglong2 wb = w2x[(2 * cp + 1) * 32 + lane];   // ci=2cp+1 {k0,k1}
            ull wc = w2k2[(2 * cp)     * 32 + lane];
            ull wd = w2k2[(2 * cp + 1) * 32 + lane];
            #pragma unroll
            for (int m = 0; m < 13; ++m) {
                ulonglong2 qp = p1v[m * 16 + cp];
                if (m <= 10) { acc[m] = ffma2(qp.x, wa.x, acc[m]); acc[m] = ffma2(qp.y, wb.x, acc[m]); }
                if (m >= 1 && m <= 11) { acc[m-1] = ffma2(qp.x, wa.y, acc[m-1]); acc[m-1] = ffma2(qp.y, wb.y, acc[m-1]); }
                if (m >= 2) { acc[m-2] = ffma2(qp.x, wc, acc[m-2]); acc[m-2] = ffma2(qp.y, wd, acc[m-2]); }
            }
        }
    };

    auto conv2_inc = [&](ull& n0, ull& n9, ull& n10) {   // fresh positions 0, 9, 10
        ull bp = b2p[lane];
        n0 = bp; n9 = bp; n10 = bp;
        #pragma unroll
        for (int cp = 0; cp < 16; ++cp) {
            ulonglong2 wa = w2x[(2 * cp)     * 32 + lane];
            ulonglong2 wb = w2x[(2 * cp + 1) * 32 + lane];
            ull wc = w2k2[(2 * cp)     * 32 + lane];
            ull wd = w2k2[(2 * cp + 1) * 32 + lane];
            ulonglong2 q0  = p1v[0 * 16 + cp],  q1  = p1v[1 * 16 + cp],  q2  = p1v[2 * 16 + cp];
            ulonglong2 q9  = p1v[9 * 16 + cp],  q10 = p1v[10 * 16 + cp];
            ulonglong2 q11 = p1v[11 * 16 + cp], q12 = p1v[12 * 16 + cp];
            n0  = ffma2(q0.x,  wa.x, n0);  n0  = ffma2(q0.y,  wb.x, n0);
            n0  = ffma2(q1.x,  wa.y, n0);  n0  = ffma2(q1.y,  wb.y, n0);
            n0  = ffma2(q2.x,  wc,   n0);  n0  = ffma2(q2.y,  wd,   n0);
            n9  = ffma2(q9.x,  wa.x, n9);  n9  = ffma2(q9.y,  wb.x, n9);
            n9  = ffma2(q10.x, wa.y, n9);  n9  = ffma2(q10.y, wb.y, n9);
            n9  = ffma2(q11.x, wc,   n9);  n9  = ffma2(q11.y, wd,   n9);
            n10 = ffma2(q10.x, wa.x, n10); n10 = ffma2(q10.y, wb.x, n10);
            n10 = ffma2(q11.x, wa.y, n10); n10 = ffma2(q11.y, wb.y, n10);
            n10 = ffma2(q12.x, wc,   n10); n10 = ffma2(q12.y, wd,   n10);
        }
    };

    // pool2 + dense2 + reduce + dense1 + recurrence + window shift
    auto tail_adv = [&](const ull* s, int t) {
        float fa[6], fb[6];
        #pragma unroll
        for (int jj = 0; jj < 5; ++jj) {
            float l0, h0c, l1, h1c;
            unpk(s[2 * jj], l0, h0c);
            unpk(s[2 * jj + 1], l1, h1c);
            fa[jj] = fmaxf(fmaxf(l0, 0.f), fmaxf(l1, 0.f));
            fb[jj] = fmaxf(fmaxf(h0c, 0.f), fmaxf(h1c, 0.f));
        }
        {
            float l0, h0c;
            unpk(s[10], l0, h0c);
            fa[5] = fmaxf(l0, 0.f);
            fb[5] = fmaxf(h0c, 0.f);
        }
        ull sacc[5] = {0ull, 0ull, 0ull, 0ull, 0ull};
        #pragma unroll
        for (int jj = 0; jj < 6; ++jj) {
            ull fap = pkdup(fa[jj]), fbp = pkdup(fb[jj]);
            #pragma unroll
            for (int q = 0; q < 5; ++q) {
                ulonglong2 w = wdx[(q * 6 + jj) * 32 + lane];
                sacc[q] = ffma2(fap, w.x, sacc[q]);
                sacc[q] = ffma2(fbp, w.y, sacc[q]);
            }
        }
        float d[10];
        #pragma unroll
        for (int q = 0; q < 5; ++q) unpk(sacc[q], d[2 * q], d[2 * q + 1]);
        #pragma unroll
        for (int off = 16; off > 0; off >>= 1) {
            #pragma unroll
            for (int o = 0; o < 10; ++o)
                d[o] += __shfl_xor_sync(0xffffffffu, d[o], off);
        }
        float y = sm[BD1_OFF];
        #pragma unroll
        for (int o = 0; o < 10; ++o)
            y = fmaf(fmaxf(d[o] + sm[BD2_OFF + o], 0.0f), sm[WD1_OFF + o], y);
        float accv = fmaf(10.0f, y, -6.0f);

        float pp = fmaf(0.1f, s24, p24);
        float ps = fmaf(0.1f, accv, s24);
        if (lane == 0) out2[t] = make_float2(pp, ps);

        x0 = __shfl_down_sync(0xffffffffu, x0, 1);
        x1 = __shfl_down_sync(0xffffffffu, x1, 1);
        x2 = __shfl_down_sync(0xffffffffu, x2, 1);
        if (lane == 24) {
            x0 = (ldn.x - pp) * (1.0f / 200.0f);
            x1 = ps * (1.0f / 40.0f);
            x2 = ldn.y * (1.0f / 40.0f);
        }
        p24 = pp; s24 = ps;
    };

    // ---------- seed steps (full compute) ----------
    ull R[11];   // even-parity conv2 state (registers)
    if (lane == 24) ldn = lead2[0 + PAST];
    publish(); conv1_full(); conv2_full(R);
    tail_adv(R, 0);

    {
        if (lane == 24) ldn = lead2[1 + PAST];
        publish(); conv1_full();
        ull A[11];
        conv2_full(A);
        #pragma unroll
        for (int j = 0; j < 11; ++j) Ssm[j * 32 + lane] = A[j];   // odd-parity state -> smem
        tail_adv(A, 1);
    }

    // ---------- main incremental loop ----------
    #pragma unroll 1
    for (int t = 2; t < NT; t += 2) {
        // even step t : register state, shift-left + 3 fresh positions
        if (lane == 24) ldn = lead2[t + PAST];   // t <= 254 -> index <= 279, in range
        publish(); conv1_inc();
        ull n0, n9, n10;
        conv2_inc(n0, n9, n10);
        R[0] = n0;
        #pragma unroll
        for (int j = 1; j <= 8; ++j) R[j] = R[j + 1];
        R[9] = n9; R[10] = n10;
        tail_adv(R, t);

        // odd step t+1 : smem state
        ldn = make_float2(0.f, 0.f);
        if (lane == 24 && (t + 1) < NT - 1) ldn = lead2[t + 1 + PAST];
        publish(); conv1_inc();
        ull m0, m9, m10;
        conv2_inc(m0, m9, m10);
        ull B[11];
        B[0] = m0;
        #pragma unroll
        for (int j = 1; j <= 8; ++j) B[j] = Ssm[(j + 1) * 32 + lane];   // new[j] = old[j+1]
        B[9] = m9; B[10] = m10;
        #pragma unroll
        for (int j = 0; j < 11; ++j) Ssm[j * 32 + lane] = B[j];
        tail_adv(B, t + 1);
    }
}

extern "C" void kernel_launch(void* const* d_in, const int* in_sizes, int n_in,
                              void* d_out, int out_size)
{
    const float* lead = (const float*)d_in[0];   // (4096, 280, 2)
    const float* cur  = (const float*)d_in[1];   // (4096, 25, 2)
    // d_in[2] = mask (unused by the reference computation)
    const float* w1  = (const float*)d_in[3];
    const float* b1  = (const float*)d_in[4];
    const float* w2  = (const float*)d_in[5];
    const float* b2  = (const float*)d_in[6];
    const float* wd2 = (const float*)d_in[7];
    const float* bd2 = (const float*)d_in[8];
    const float* wd1 = (const float*)d_in[9];
    const float* bd1 = (const float*)d_in[10];
    float* out = (float*)d_out;                   // (4096, 256, 2)

    (void)in_sizes; (void)n_in; (void)out_size;

    size_t smem_bytes = (size_t)SMEM_FLOATS * sizeof(float);   // 225696 B
    cudaFuncSetAttribute(rnncf_kernel,
                         cudaFuncAttributeMaxDynamicSharedMemorySize,
                         (int)smem_bytes);
    rnncf_kernel<<<NCTA, NTHREADS, smem_bytes>>>(
        lead, cur, w1, b1, w2, b2, wd2, bd2, wd1, bd1, out);
}

// round 8
// speedup vs baseline: 2.1473x; 1.2160x over previous
#include <cuda_runtime.h>

#define NVEH 4096
#define NT 256
#define PAST 25
#define LEADLEN (NT + PAST - 1)   // 280
#define NPAIR (NVEH / 2)          // 2048
#define WARPS_PER_CTA 14
#define NCTA ((NPAIR + WARPS_PER_CTA - 1) / WARPS_PER_CTA)   // 147
#define NTHREADS (WARPS_PER_CTA * 32)                         // 448

typedef unsigned long long ull;

// ---- shared memory layout (float offsets) ----
#define W1_OFF    0        // 288  : conv1_w [3][3][32]
#define B1_OFF    288      // 32
#define B2P_OFF   320      // 64   : ull pair {b2[c], b2[c+32]}
#define W2X_OFF   384      // 4096 : ull2 [ci][lane] = {k0pair, k1pair}
#define W2K2_OFF  4480     // 2048 : ull  [ci][lane] = k2pair
#define WD2X_OFF  6528     // 3840 : ull2 [(q*6+jj)][lane] = {pair_i, pair_{i+32}}
#define BD2_OFF   10368    // 10
#define WD1_OFF   10378    // 10
#define BD1_OFF   10388    // 1 (+3 pad)
#define XBUF_OFF  10392    // 28 veh-slots * 27 * 4 floats (zero-padded borders)
#define P1_OFF    13416    // 28 veh-slots * 13*32 ull (dup pairs)
#define S_OFF     (P1_OFF + 28 * 13 * 32 * 2)    // odd-parity conv2 state, 28 * 11*32 ull
#define SMEM_FLOATS (S_OFF + 28 * 11 * 32 * 2)   // 56424 floats = 225696 B

__device__ __forceinline__ ull ffma2(ull a, ull b, ull c) {
    ull d;
    asm("fma.rn.f32x2 %0, %1, %2, %3;" : "=l"(d) : "l"(a), "l"(b), "l"(c));
    return d;
}
__device__ __forceinline__ void unpk(ull v, float& lo, float& hi) {
    asm("mov.b64 {%0, %1}, %2;" : "=f"(lo), "=f"(hi) : "l"(v));
}
__device__ __forceinline__ ull pkdup(float x) {
    ull d;
    asm("mov.b64 %0, {%1, %1};" : "=l"(d) : "f"(x));
    return d;
}

__global__ void __launch_bounds__(NTHREADS, 1)
rnncf_kernel(const float* __restrict__ lead, const float* __restrict__ cur,
             const float* __restrict__ w1g, const float* __restrict__ b1g,
             const float* __restrict__ w2g, const float* __restrict__ b2g,
             const float* __restrict__ wd2g, const float* __restrict__ bd2g,
             const float* __restrict__ wd1g, const float* __restrict__ bd1g,
             float* __restrict__ out)
{
    extern __shared__ float sm[];
    const int tid = threadIdx.x;

    // ---------- cooperative weight staging ----------
    for (int i = tid; i < 288; i += NTHREADS) sm[W1_OFF + i] = w1g[i];
    for (int i = tid; i < 32;  i += NTHREADS) sm[B1_OFF + i] = b1g[i];
    {
        float2* b2p_s = (float2*)(sm + B2P_OFF);
        for (int i = tid; i < 32; i += NTHREADS)
            b2p_s[i] = make_float2(b2g[i], b2g[i + 32]);
        float4* w2x_s = (float4*)(sm + W2X_OFF);
        float2* w2k2_s = (float2*)(sm + W2K2_OFF);
        for (int i = tid; i < 1024; i += NTHREADS) {
            int ci = i >> 5, c = i & 31;
            w2x_s[i] = make_float4(w2g[ci * 64 + c],        w2g[ci * 64 + c + 32],
                                   w2g[(32 + ci) * 64 + c], w2g[(32 + ci) * 64 + c + 32]);
            w2k2_s[i] = make_float2(w2g[(64 + ci) * 64 + c], w2g[(64 + ci) * 64 + c + 32]);
        }
        float4* wdx_s = (float4*)(sm + WD2X_OFF);
        for (int i = tid; i < 960; i += NTHREADS) {
            int q = i / 192, r = i - q * 192;
            int jj = r >> 5, c = r & 31;
            int ii = jj * 64 + c;
            wdx_s[i] = make_float4(wd2g[ii * 10 + 2 * q],        wd2g[ii * 10 + 2 * q + 1],
                                   wd2g[(ii + 32) * 10 + 2 * q], wd2g[(ii + 32) * 10 + 2 * q + 1]);
        }
    }
    for (int i = tid; i < 10; i += NTHREADS) sm[BD2_OFF + i] = bd2g[i];
    for (int i = tid; i < 10; i += NTHREADS) sm[WD1_OFF + i] = wd1g[i];
    if (tid == 0) sm[BD1_OFF] = bd1g[0];
    for (int i = tid; i < 28 * 27 * 4; i += NTHREADS) sm[XBUF_OFF + i] = 0.0f;
    __syncthreads();

    const int wid = tid >> 5, lane = tid & 31;
    const int pairIdx = blockIdx.x * WARPS_PER_CTA + wid;
    if (pairIdx >= NPAIR) return;
    const int vA = 2 * pairIdx, vB = vA + 1;
    const int slotA = wid * 2, slotB = slotA + 1;

    float* xbA = sm + XBUF_OFF + slotA * (27 * 4);
    float* xbB = sm + XBUF_OFF + slotB * (27 * 4);
    ull* p1A = (ull*)(sm + P1_OFF) + slotA * (13 * 32);
    ull* p1B = (ull*)(sm + P1_OFF) + slotB * (13 * 32);
    const ulonglong2* p1vA = (const ulonglong2*)p1A;
    const ulonglong2* p1vB = (const ulonglong2*)p1B;
    ull* SsmA = (ull*)(sm + S_OFF) + slotA * (11 * 32);
    ull* SsmB = (ull*)(sm + S_OFF) + slotB * (11 * 32);
    const ulonglong2* w2x  = (const ulonglong2*)(sm + W2X_OFF);
    const ull*        w2k2 = (const ull*)(sm + W2K2_OFF);
    const ulonglong2* wdx  = (const ulonglong2*)(sm + WD2X_OFF);
    const ull*        b2p  = (const ull*)(sm + B2P_OFF);

    const float2* lead2A = (const float2*)lead + (size_t)vA * LEADLEN;
    const float2* lead2B = (const float2*)lead + (size_t)vB * LEADLEN;
    const float2* cur2A  = (const float2*)cur  + (size_t)vA * PAST;
    const float2* cur2B  = (const float2*)cur  + (size_t)vB * PAST;
    float2* out2A = (float2*)out + (size_t)vA * NT;
    float2* out2B = (float2*)out + (size_t)vB * NT;

    // conv1 weights hoisted (constant across steps)
    float w1r[9];
    #pragma unroll
    for (int i = 0; i < 9; ++i) w1r[i] = sm[W1_OFF + i * 32 + lane];
    const float b1r = sm[B1_OFF + lane];

    // ---------- initial windows: lane i (<25) holds CNN input column i ----------
    float x0a = 0.f, x1a = 0.f, x2a = 0.f, x0b = 0.f, x1b = 0.f, x2b = 0.f;
    float tpA = 0.f, tsA = 0.f, tpB = 0.f, tsB = 0.f;
    if (lane < PAST) {
        float2 csA = cur2A[lane], ldA = lead2A[lane];
        float2 csB = cur2B[lane], ldB = lead2B[lane];
        x0a = (ldA.x - csA.x) * (1.0f / 200.0f);
        x1a = csA.y * (1.0f / 40.0f);
        x2a = ldA.y * (1.0f / 40.0f);
        x0b = (ldB.x - csB.x) * (1.0f / 200.0f);
        x1b = csB.y * (1.0f / 40.0f);
        x2b = ldB.y * (1.0f / 40.0f);
        tpA = csA.x; tsA = csA.y; tpB = csB.x; tsB = csB.y;
    }
    float p24A = __shfl_sync(0xffffffffu, tpA, 24);
    float s24A = __shfl_sync(0xffffffffu, tsA, 24);
    float p24B = __shfl_sync(0xffffffffu, tpB, 24);
    float s24B = __shfl_sync(0xffffffffu, tsB, 24);
    float2 ldnA = make_float2(0.f, 0.f), ldnB = make_float2(0.f, 0.f);

    // ---------- helpers ----------
    auto conv1pos = [&](float4 a, float4 b, float4 c) -> float {
        float h = b1r;
        h = fmaf(a.x, w1r[0], h); h = fmaf(a.y, w1r[1], h); h = fmaf(a.z, w1r[2], h);
        h = fmaf(b.x, w1r[3], h); h = fmaf(b.y, w1r[4], h); h = fmaf(b.z, w1r[5], h);
        h = fmaf(c.x, w1r[6], h); h = fmaf(c.y, w1r[7], h); h = fmaf(c.z, w1r[8], h);
        return h;
    };

    auto publish2 = [&]() {
        if (lane < PAST) {
            *(float4*)(xbA + (lane + 1) * 4) = make_float4(x0a, x1a, x2a, 0.0f);
            *(float4*)(xbB + (lane + 1) * 4) = make_float4(x0b, x1b, x2b, 0.0f);
        }
        __syncwarp();
    };

    auto conv1_full = [&](const float* xb, ull* p1) {   // all 13 pool1 slots (seeds)
        float4 a = *(const float4*)(xb);
        float4 b = *(const float4*)(xb + 4);
        #pragma unroll
        for (int m = 0; m < 12; ++m) {
            float4 c1 = *(const float4*)(xb + (2 * m + 2) * 4);
            float4 c2 = *(const float4*)(xb + (2 * m + 3) * 4);
            float h0 = conv1pos(a, b, c1);
            float h1 = conv1pos(b, c1, c2);
            p1[m * 32 + lane] = pkdup(fmaxf(fmaxf(h0, 0.f), fmaxf(h1, 0.f)));
            a = c1; b = c2;
        }
        float4 c1 = *(const float4*)(xb + 26 * 4);
        p1[12 * 32 + lane] = pkdup(fmaxf(conv1pos(a, b, c1), 0.f));
    };

    auto conv1_inc = [&](const float* xb, ull* p1) {    // boundary slots 0..2, 9..12
        {
            float4 a = *(const float4*)(xb);
            float4 b = *(const float4*)(xb + 4);
            #pragma unroll
            for (int m = 0; m < 3; ++m) {
                float4 c1 = *(const float4*)(xb + (2 * m + 2) * 4);
                float4 c2 = *(const float4*)(xb + (2 * m + 3) * 4);
                float h0 = conv1pos(a, b, c1);
                float h1 = conv1pos(b, c1, c2);
                p1[m * 32 + lane] = pkdup(fmaxf(fmaxf(h0, 0.f), fmaxf(h1, 0.f)));
                a = c1; b = c2;
            }
        }
        {
            float4 a = *(const float4*)(xb + 18 * 4);
            float4 b = *(const float4*)(xb + 19 * 4);
            #pragma unroll
            for (int m = 9; m < 12; ++m) {
                float4 c1 = *(const float4*)(xb + (2 * m + 2) * 4);
                float4 c2 = *(const float4*)(xb + (2 * m + 3) * 4);
                float h0 = conv1pos(a, b, c1);
                float h1 = conv1pos(b, c1, c2);
                p1[m * 32 + lane] = pkdup(fmaxf(fmaxf(h0, 0.f), fmaxf(h1, 0.f)));
                a = c1; b = c2;
            }
            float4 c1 = *(const float4*)(xb + 26 * 4);
            p1[12 * 32 + lane] = pkdup(fmaxf(conv1pos(a, b, c1), 0.f));
        }
    };

    auto conv2_full = [&](const ulonglong2* p1v, ull* acc) {   // seeds: all 11 positions
        ull bp = b2p[lane];
        #pragma unroll
        for (int j = 0; j < 11; ++j) acc[j] = bp;
        #pragma unroll 1
        for (int cp = 0; cp < 16; ++cp) {
            ulonglong2 wa = w2x[(2 * cp)     * 32 + lane];
            ulonglong2 wb = w2x[(2 * cp + 1) * 32 + lane];
            ull wc = w2k2[(2 * cp)     * 32 + lane];
            ull wd = w2k2[(2 * cp + 1) * 32 + lane];
            #pragma unroll
            for (int m = 0; m < 13; ++m) {
                ulonglong2 qp = p1v[m * 16 + cp];
                if (m <= 10) { acc[m] = ffma2(qp.x, wa.x, acc[m]); acc[m] = ffma2(qp.y, wb.x, acc[m]); }
                if (m >= 1 && m <= 11) { acc[m-1] = ffma2(qp.x, wa.y, acc[m-1]); acc[m-1] = ffma2(qp.y, wb.y, acc[m-1]); }
                if (m >= 2) { acc[m-2] = ffma2(qp.x, wc, acc[m-2]); acc[m-2] = ffma2(qp.y, wd, acc[m-2]); }
            }
        }
    };

    // fresh positions {0, 9, 10} for both vehicles; weight loads shared
    auto conv2_inc2 = [&](ull* nA, ull* nB) {
        ull bp = b2p[lane];
        nA[0] = nA[1] = nA[2] = bp;
        nB[0] = nB[1] = nB[2] = bp;
        #pragma unroll
        for (int cp = 0; cp < 16; ++cp) {
            ulonglong2 wa = w2x[(2 * cp)     * 32 + lane];
            ulonglong2 wb = w2x[(2 * cp + 1) * 32 + lane];
            ull wc = w2k2[(2 * cp)     * 32 + lane];
            ull wd = w2k2[(2 * cp + 1) * 32 + lane];
            {
                ulonglong2 q0 = p1vA[0*16+cp], q1 = p1vA[1*16+cp], q2 = p1vA[2*16+cp];
                nA[0] = ffma2(q0.x, wa.x, nA[0]); nA[0] = ffma2(q0.y, wb.x, nA[0]);
                nA[0] = ffma2(q1.x, wa.y, nA[0]); nA[0] = ffma2(q1.y, wb.y, nA[0]);
                nA[0] = ffma2(q2.x, wc,   nA[0]); nA[0] = ffma2(q2.y, wd,   nA[0]);
                ulonglong2 q9 = p1vA[9*16+cp], q10 = p1vA[10*16+cp], q11 = p1vA[11*16+cp], q12 = p1vA[12*16+cp];
                nA[1] = ffma2(q9.x,  wa.x, nA[1]); nA[1] = ffma2(q9.y,  wb.x, nA[1]);
                nA[1] = ffma2(q10.x, wa.y, nA[1]); nA[1] = ffma2(q10.y, wb.y, nA[1]);
                nA[1] = ffma2(q11.x, wc,   nA[1]); nA[1] = ffma2(q11.y, wd,   nA[1]);
                nA[2] = ffma2(q10.x, wa.x, nA[2]); nA[2] = ffma2(q10.y, wb.x, nA[2]);
                nA[2] = ffma2(q11.x, wa.y, nA[2]); nA[2] = ffma2(q11.y, wb.y, nA[2]);
                nA[2] = ffma2(q12.x, wc,   nA[2]); nA[2] = ffma2(q12.y, wd,   nA[2]);
            }
            {
                ulonglong2 q0 = p1vB[0*16+cp], q1 = p1vB[1*16+cp], q2 = p1vB[2*16+cp];
                nB[0] = ffma2(q0.x, wa.x, nB[0]); nB[0] = ffma2(q0.y, wb.x, nB[0]);
                nB[0] = ffma2(q1.x, wa.y, nB[0]); nB[0] = ffma2(q1.y, wb.y, nB[0]);
                nB[0] = ffma2(q2.x, wc,   nB[0]); nB[0] = ffma2(q2.y, wd,   nB[0]);
                ulonglong2 q9 = p1vB[9*16+cp], q10 = p1vB[10*16+cp], q11 = p1vB[11*16+cp], q12 = p1vB[12*16+cp];
                nB[1] = ffma2(q9.x,  wa.x, nB[1]); nB[1] = ffma2(q9.y,  wb.x, nB[1]);
                nB[1] = ffma2(q10.x, wa.y, nB[1]); nB[1] = ffma2(q10.y, wb.y, nB[1]);
                nB[1] = ffma2(q11.x, wc,   nB[1]); nB[1] = ffma2(q11.y, wd,   nB[1]);
                nB[2] = ffma2(q10.x, wa.x, nB[2]); nB[2] = ffma2(q10.y, wb.x, nB[2]);
                nB[2] = ffma2(q11.x, wa.y, nB[2]); nB[2] = ffma2(q11.y, wb.y, nB[2]);
                nB[2] = ffma2(q12.x, wc,   nB[2]); nB[2] = ffma2(q12.y, wd,   nB[2]);
            }
        }
    };

    // pool2 + dense2 + reduce + dense1 + recurrence for both vehicles.
    // s*[j*st*] indexes the conv2 state (st=1 registers, st=32 smem+lane).
    auto tail2 = [&](const ull* sA, int stA, const ull* sB, int stB, int t) {
        ull fapA[6], fbpA[6], fapB[6], fbpB[6];
        {
            #pragma unroll
            for (int jj = 0; jj < 5; ++jj) {
                float l0, h0, l1, h1;
                unpk(sA[(2 * jj) * stA], l0, h0);
                unpk(sA[(2 * jj + 1) * stA], l1, h1);
                fapA[jj] = pkdup(fmaxf(fmaxf(l0, 0.f), fmaxf(l1, 0.f)));
                fbpA[jj] = pkdup(fmaxf(fmaxf(h0, 0.f), fmaxf(h1, 0.f)));
            }
            float l0, h0;
            unpk(sA[10 * stA], l0, h0);
            fapA[5] = pkdup(fmaxf(l0, 0.f));
            fbpA[5] = pkdup(fmaxf(h0, 0.f));
        }
        {
            #pragma unroll
            for (int jj = 0; jj < 5; ++jj) {
                float l0, h0, l1, h1;
                unpk(sB[(2 * jj) * stB], l0, h0);
                unpk(sB[(2 * jj + 1) * stB], l1, h1);
                fapB[jj] = pkdup(fmaxf(fmaxf(l0, 0.f), fmaxf(l1, 0.f)));
                fbpB[jj] = pkdup(fmaxf(fmaxf(h0, 0.f), fmaxf(h1, 0.f)));
            }
            float l0, h0;
            unpk(sB[10 * stB], l0, h0);
            fapB[5] = pkdup(fmaxf(l0, 0.f));
            fbpB[5] = pkdup(fmaxf(h0, 0.f));
        }

        ull saccA[5] = {0,0,0,0,0}, saccB[5] = {0,0,0,0,0};
        #pragma unroll
        for (int jj = 0; jj < 6; ++jj) {
            #pragma unroll
            for (int q = 0; q < 5; ++q) {
                ulonglong2 w = wdx[(q * 6 + jj) * 32 + lane];   // shared load
                saccA[q] = ffma2(fapA[jj], w.x, saccA[q]);
                saccA[q] = ffma2(fbpA[jj], w.y, saccA[q]);
                saccB[q] = ffma2(fapB[jj], w.x, saccB[q]);
                saccB[q] = ffma2(fbpB[jj], w.y, saccB[q]);
            }
        }
        float dA[10], dB[10];
        #pragma unroll
        for (int q = 0; q < 5; ++q) {
            unpk(saccA[q], dA[2 * q], dA[2 * q + 1]);
            unpk(saccB[q], dB[2 * q], dB[2 * q + 1]);
        }
        #pragma unroll
        for (int off = 16; off > 0; off >>= 1) {
            #pragma unroll
            for (int o = 0; o < 10; ++o) {
                dA[o] += __shfl_xor_sync(0xffffffffu, dA[o], off);
                dB[o] += __shfl_xor_sync(0xffffffffu, dB[o], off);
            }
        }
        float bd1v = sm[BD1_OFF];
        float yA = bd1v, yB = bd1v;
        #pragma unroll
        for (int o = 0; o < 10; ++o) {
            float bd = sm[BD2_OFF + o];
            float wd = sm[WD1_OFF + o];
            yA = fmaf(fmaxf(dA[o] + bd, 0.0f), wd, yA);
            yB = fmaf(fmaxf(dB[o] + bd, 0.0f), wd, yB);
        }
        float accvA = fmaf(10.0f, yA, -6.0f);
        float accvB = fmaf(10.0f, yB, -6.0f);

        float ppA = fmaf(0.1f, s24A,  p24A);
        float psA = fmaf(0.1f, accvA, s24A);
        float ppB = fmaf(0.1f, s24B,  p24B);
        float psB = fmaf(0.1f, accvB, s24B);
        if (lane == 0) out2A[t] = make_float2(ppA, psA);
        if (lane == 1) out2B[t] = make_float2(ppB, psB);

        x0a = __shfl_down_sync(0xffffffffu, x0a, 1);
        x1a = __shfl_down_sync(0xffffffffu, x1a, 1);
        x2a = __shfl_down_sync(0xffffffffu, x2a, 1);
        x0b = __shfl_down_sync(0xffffffffu, x0b, 1);
        x1b = __shfl_down_sync(0xffffffffu, x1b, 1);
        x2b = __shfl_down_sync(0xffffffffu, x2b, 1);
        if (lane == 24) {
            x0a = (ldnA.x - ppA) * (1.0f / 200.0f);
            x1a = psA * (1.0f / 40.0f);
            x2a = ldnA.y * (1.0f / 40.0f);
            x0b = (ldnB.x - ppB) * (1.0f / 200.0f);
            x1b = psB * (1.0f / 40.0f);
            x2b = ldnB.y * (1.0f / 40.0f);
        }
        p24A = ppA; s24A = psA;
        p24B = ppB; s24B = psB;
    };

    // ---------- seed steps (full compute) ----------
    ull RA[11], RB[11];   // even-parity conv2 state (registers)
    if (lane == 24) { ldnA = lead2A[0 + PAST]; ldnB = lead2B[0 + PAST]; }
    publish2();
    conv1_full(xbA, p1A); conv1_full(xbB, p1B);
    __syncwarp();
    conv2_full(p1vA, RA); conv2_full(p1vB, RB);
    tail2(RA, 1, RB, 1, 0);

    {
        if (lane == 24) { ldnA = lead2A[1 + PAST]; ldnB = lead2B[1 + PAST]; }
        publish2();
        conv1_full(xbA, p1A); conv1_full(xbB, p1B);
        __syncwarp();
        ull T[11];
        conv2_full(p1vA, T);
        #pragma unroll
        for (int j = 0; j < 11; ++j) SsmA[j * 32 + lane] = T[j];
        conv2_full(p1vB, T);
        #pragma unroll
        for (int j = 0; j < 11; ++j) SsmB[j * 32 + lane] = T[j];
        tail2(SsmA + lane, 32, SsmB + lane, 32, 1);
    }

    // ---------- main incremental loop ----------
    #pragma unroll 1
    for (int t = 2; t < NT; t += 2) {
        // even step t : register state
        if (lane == 24) { ldnA = lead2A[t + PAST]; ldnB = lead2B[t + PAST]; }
        publish2();
        conv1_inc(xbA, p1A); conv1_inc(xbB, p1B);
        __syncwarp();
        ull nA[3], nB[3];
        conv2_inc2(nA, nB);
        RA[0] = nA[0];
        RB[0] = nB[0];
        #pragma unroll
        for (int j = 1; j <= 8; ++j) { RA[j] = RA[j + 1]; RB[j] = RB[j + 1]; }
        RA[9] = nA[1]; RA[10] = nA[2];
        RB[9] = nB[1]; RB[10] = nB[2];
        tail2(RA, 1, RB, 1, t);

        // odd step t+1 : smem state, shifted in place (lane-private slots)
        ldnA = make_float2(0.f, 0.f); ldnB = make_float2(0.f, 0.f);
        if (lane == 24 && (t + 1) < NT - 1) {
            ldnA = lead2A[t + 1 + PAST];
            ldnB = lead2B[t + 1 + PAST];
        }
        publish2();
        conv1_inc(xbA, p1A); conv1_inc(xbB, p1B);
        __syncwarp();
        ull mA[3], mB[3];
        conv2_inc2(mA, mB);
        #pragma unroll
        for (int j = 1; j <= 8; ++j) {   // ascending: read j+1 before slot j+1 is overwritten
            SsmA[j * 32 + lane] = SsmA[(j + 1) * 32 + lane];
            SsmB[j * 32 + lane] = SsmB[(j + 1) * 32 + lane];
        }
        SsmA[0 * 32 + lane] = mA[0]; SsmA[9 * 32 + lane] = mA[1]; SsmA[10 * 32 + lane] = mA[2];
        SsmB[0 * 32 + lane] = mB[0]; SsmB[9 * 32 + lane] = mB[1]; SsmB[10 * 32 + lane] = mB[2];
        tail2(SsmA + lane, 32, SsmB + lane, 32, t + 1);
    }
}

extern "C" void kernel_launch(void* const* d_in, const int* in_sizes, int n_in,
                              void* d_out, int out_size)
{
    const float* lead = (const float*)d_in[0];   // (4096, 280, 2)
    const float* cur  = (const float*)d_in[1];   // (4096, 25, 2)
    // d_in[2] = mask (unused by the reference computation)
    const float* w1  = (const float*)d_in[3];
    const float* b1  = (const float*)d_in[4];
    const float* w2  = (const float*)d_in[5];
    const float* b2  = (const float*)d_in[6];
    const float* wd2 = (const float*)d_in[7];
    const float* bd2 = (const float*)d_in[8];
    const float* wd1 = (const float*)d_in[9];
    const float* bd1 = (const float*)d_in[10];
    float* out = (float*)d_out;                   // (4096, 256, 2)

    (void)in_sizes; (void)n_in; (void)out_size;

    size_t smem_bytes = (size_t)SMEM_FLOATS * sizeof(float);   // 225696 B
    cudaFuncSetAttribute(rnncf_kernel,
                         cudaFuncAttributeMaxDynamicSharedMemorySize,
                         (int)smem_bytes);
    rnncf_kernel<<<NCTA, NTHREADS, smem_bytes>>>(
        lead, cur, w1, b1, w2, b2, wd2, bd2, wd1, bd1, out);
}

// round 9
// speedup vs baseline: 2.7023x; 1.2585x over previous
#include <cuda_runtime.h>

#define NVEH 4096
#define NT 256
#define PAST 25
#define LEADLEN (NT + PAST - 1)   // 280
#define NPAIR (NVEH / 2)          // 2048
#define WARPS_PER_CTA 14
#define NCTA ((NPAIR + WARPS_PER_CTA - 1) / WARPS_PER_CTA)   // 147
#define NTHREADS (WARPS_PER_CTA * 32)                         // 448

typedef unsigned long long ull;

// ---- shared memory layout (float offsets) ----
#define W1_OFF    0        // 288  : conv1_w [3][3][32]
#define B1_OFF    288      // 32
#define B2P_OFF   320      // 64   : float2 {b2[c], b2[c+32]}
#define W2X_OFF   384      // 4096 : float4 [ci*32+c] = {w0[c], w0[c+32], w1[c], w1[c+32]}
#define W2K2_OFF  4480     // 2048 : float2 [ci*32+c] = {w2[c], w2[c+32]}
#define WD2X_OFF  6528     // 3840 : ull2 [(q*6+jj)*32+c] = {pair_i, pair_{i+32}}
#define BD2_OFF   10368    // 10
#define WD1_OFF   10378    // 10
#define BD1_OFF   10388    // 1 (+3 pad)
#define XBUF_OFF  10392    // 28 veh-slots * 27 * 4 floats (zero-padded borders)
#define PAB_OFF   13416    // 14 warps * 13*32 float2 {pA, pB}  (832 floats/warp)
#define S_OFF     (PAB_OFF + 14 * 13 * 32 * 2)   // 25064 : odd-parity packed state, 14 * 22*32 ull
#define SMEM_FLOATS (S_OFF + 14 * 22 * 32 * 2)   // 44776 floats = 179104 B

__device__ __forceinline__ ull ffma2(ull a, ull b, ull c) {
    ull d;
    asm("fma.rn.f32x2 %0, %1, %2, %3;" : "=l"(d) : "l"(a), "l"(b), "l"(c));
    return d;
}
__device__ __forceinline__ ull addf32x2(ull a, ull b) {
    ull d;
    asm("add.rn.f32x2 %0, %1, %2;" : "=l"(d) : "l"(a), "l"(b));
    return d;
}
__device__ __forceinline__ void unpk(ull v, float& lo, float& hi) {
    asm("mov.b64 {%0, %1}, %2;" : "=f"(lo), "=f"(hi) : "l"(v));
}
__device__ __forceinline__ ull pkdup(float x) {
    ull d;
    asm("mov.b64 %0, {%1, %1};" : "=l"(d) : "f"(x));
    return d;
}

__global__ void __launch_bounds__(NTHREADS, 1)
rnncf_kernel(const float* __restrict__ lead, const float* __restrict__ cur,
             const float* __restrict__ w1g, const float* __restrict__ b1g,
             const float* __restrict__ w2g, const float* __restrict__ b2g,
             const float* __restrict__ wd2g, const float* __restrict__ bd2g,
             const float* __restrict__ wd1g, const float* __restrict__ bd1g,
             float* __restrict__ out)
{
    extern __shared__ float sm[];
    const int tid = threadIdx.x;

    // ---------- cooperative weight staging ----------
    for (int i = tid; i < 288; i += NTHREADS) sm[W1_OFF + i] = w1g[i];
    for (int i = tid; i < 32;  i += NTHREADS) sm[B1_OFF + i] = b1g[i];
    {
        float2* b2p_s = (float2*)(sm + B2P_OFF);
        for (int i = tid; i < 32; i += NTHREADS)
            b2p_s[i] = make_float2(b2g[i], b2g[i + 32]);
        float4* w2x_s = (float4*)(sm + W2X_OFF);
        float2* w2k2_s = (float2*)(sm + W2K2_OFF);
        for (int i = tid; i < 1024; i += NTHREADS) {
            int ci = i >> 5, c = i & 31;
            w2x_s[i] = make_float4(w2g[ci * 64 + c],        w2g[ci * 64 + c + 32],
                                   w2g[(32 + ci) * 64 + c], w2g[(32 + ci) * 64 + c + 32]);
            w2k2_s[i] = make_float2(w2g[(64 + ci) * 64 + c], w2g[(64 + ci) * 64 + c + 32]);
        }
        float4* wdx_s = (float4*)(sm + WD2X_OFF);
        for (int i = tid; i < 960; i += NTHREADS) {
            int q = i / 192, r = i - q * 192;
            int jj = r >> 5, c = r & 31;
            int ii = jj * 64 + c;
            wdx_s[i] = make_float4(wd2g[ii * 10 + 2 * q],        wd2g[ii * 10 + 2 * q + 1],
                                   wd2g[(ii + 32) * 10 + 2 * q], wd2g[(ii + 32) * 10 + 2 * q + 1]);
        }
    }
    for (int i = tid; i < 10; i += NTHREADS) sm[BD2_OFF + i] = bd2g[i];
    for (int i = tid; i < 10; i += NTHREADS) sm[WD1_OFF + i] = wd1g[i];
    if (tid == 0) sm[BD1_OFF] = bd1g[0];
    for (int i = tid; i < 28 * 27 * 4; i += NTHREADS) sm[XBUF_OFF + i] = 0.0f;
    __syncthreads();

    const int wid = tid >> 5, lane = tid & 31;
    const int pairIdx = blockIdx.x * WARPS_PER_CTA + wid;
    if (pairIdx >= NPAIR) return;
    const int vA = 2 * pairIdx, vB = vA + 1;
    const int slotA = wid * 2, slotB = slotA + 1;

    float* xbA = sm + XBUF_OFF + slotA * (27 * 4);
    float* xbB = sm + XBUF_OFF + slotB * (27 * 4);
    float* pABf = sm + PAB_OFF + wid * (13 * 32 * 2);          // float2 {pA,pB} per (m,ci)
    const ulonglong2* qv = (const ulonglong2*)pABf;            // [m*16 + cp]
    ull* Slo = (ull*)(sm + S_OFF) + wid * (22 * 32);           // odd-parity state c=lane
    ull* Shi = Slo + 11 * 32;                                  // c=lane+32
    const float4* w2xf  = (const float4*)(sm + W2X_OFF);
    const float2* w2k2f = (const float2*)(sm + W2K2_OFF);
    const ulonglong2* wdx = (const ulonglong2*)(sm + WD2X_OFF);

    const float2* lead2A = (const float2*)lead + (size_t)vA * LEADLEN;
    const float2* lead2B = (const float2*)lead + (size_t)vB * LEADLEN;
    const float2* cur2A  = (const float2*)cur  + (size_t)vA * PAST;
    const float2* cur2B  = (const float2*)cur  + (size_t)vB * PAST;
    float2* out2A = (float2*)out + (size_t)vA * NT;
    float2* out2B = (float2*)out + (size_t)vB * NT;

    // conv1 weights + conv2 bias dups hoisted (constant across steps)
    float w1r[9];
    #pragma unroll
    for (int i = 0; i < 9; ++i) w1r[i] = sm[W1_OFF + i * 32 + lane];
    const float b1r = sm[B1_OFF + lane];
    ull b2lo, b2hi;
    {
        float2 b2v = ((const float2*)(sm + B2P_OFF))[lane];
        b2lo = pkdup(b2v.x);   // bias for channel lane, both vehicles
        b2hi = pkdup(b2v.y);   // channel lane+32
    }

    // ---------- initial windows: lane i (<25) holds CNN input column i ----------
    float x0a = 0.f, x1a = 0.f, x2a = 0.f, x0b = 0.f, x1b = 0.f, x2b = 0.f;
    float tpA = 0.f, tsA = 0.f, tpB = 0.f, tsB = 0.f;
    if (lane < PAST) {
        float2 csA = cur2A[lane], ldA = lead2A[lane];
        float2 csB = cur2B[lane], ldB = lead2B[lane];
        x0a = (ldA.x - csA.x) * (1.0f / 200.0f);
        x1a = csA.y * (1.0f / 40.0f);
        x2a = ldA.y * (1.0f / 40.0f);
        x0b = (ldB.x - csB.x) * (1.0f / 200.0f);
        x1b = csB.y * (1.0f / 40.0f);
        x2b = ldB.y * (1.0f / 40.0f);
        tpA = csA.x; tsA = csA.y; tpB = csB.x; tsB = csB.y;
    }
    float p24A = __shfl_sync(0xffffffffu, tpA, 24);
    float s24A = __shfl_sync(0xffffffffu, tsA, 24);
    float p24B = __shfl_sync(0xffffffffu, tpB, 24);
    float s24B = __shfl_sync(0xffffffffu, tsB, 24);
    float2 ldnA = make_float2(0.f, 0.f), ldnB = make_float2(0.f, 0.f);

    // ---------- helpers ----------
    auto conv1pos = [&](float4 a, float4 b, float4 c) -> float {
        float h = b1r;
        h = fmaf(a.x, w1r[0], h); h = fmaf(a.y, w1r[1], h); h = fmaf(a.z, w1r[2], h);
        h = fmaf(b.x, w1r[3], h); h = fmaf(b.y, w1r[4], h); h = fmaf(b.z, w1r[5], h);
        h = fmaf(c.x, w1r[6], h); h = fmaf(c.y, w1r[7], h); h = fmaf(c.z, w1r[8], h);
        return h;
    };

    auto publish2 = [&]() {
        if (lane < PAST) {
            *(float4*)(xbA + (lane + 1) * 4) = make_float4(x0a, x1a, x2a, 0.0f);
            *(float4*)(xbB + (lane + 1) * 4) = make_float4(x0b, x1b, x2b, 0.0f);
        }
        __syncwarp();
    };

    // h = 0 for vehicle A, 1 for B; stores the scalar half of the {A,B} pair
    auto conv1_full = [&](const float* xb, int h) {
        float* pd = pABf + h;
        float4 a = *(const float4*)(xb);
        float4 b = *(const float4*)(xb + 4);
        #pragma unroll
        for (int m = 0; m < 12; ++m) {
            float4 c1 = *(const float4*)(xb + (2 * m + 2) * 4);
            float4 c2 = *(const float4*)(xb + (2 * m + 3) * 4);
            float h0 = conv1pos(a, b, c1);
            float h1 = conv1pos(b, c1, c2);
            pd[(m * 32 + lane) * 2] = fmaxf(fmaxf(h0, 0.f), fmaxf(h1, 0.f));
            a = c1; b = c2;
        }
        float4 c1 = *(const float4*)(xb + 26 * 4);
        pd[(12 * 32 + lane) * 2] = fmaxf(conv1pos(a, b, c1), 0.f);
    };

    auto conv1_inc = [&](const float* xb, int h) {    // boundary slots 0..2, 9..12
        float* pd = pABf + h;
        {
            float4 a = *(const float4*)(xb);
            float4 b = *(const float4*)(xb + 4);
            #pragma unroll
            for (int m = 0; m < 3; ++m) {
                float4 c1 = *(const float4*)(xb + (2 * m + 2) * 4);
                float4 c2 = *(const float4*)(xb + (2 * m + 3) * 4);
                float h0 = conv1pos(a, b, c1);
                float h1 = conv1pos(b, c1, c2);
                pd[(m * 32 + lane) * 2] = fmaxf(fmaxf(h0, 0.f), fmaxf(h1, 0.f));
                a = c1; b = c2;
            }
        }
        {
            float4 a = *(const float4*)(xb + 18 * 4);
            float4 b = *(const float4*)(xb + 19 * 4);
            #pragma unroll
            for (int m = 9; m < 12; ++m) {
                float4 c1 = *(const float4*)(xb + (2 * m + 2) * 4);
                float4 c2 = *(const float4*)(xb + (2 * m + 3) * 4);
                float h0 = conv1pos(a, b, c1);
                float h1 = conv1pos(b, c1, c2);
                pd[(m * 32 + lane) * 2] = fmaxf(fmaxf(h0, 0.f), fmaxf(h1, 0.f));
                a = c1; b = c2;
            }
            float4 c1 = *(const float4*)(xb + 26 * 4);
            pd[(12 * 32 + lane) * 2] = fmaxf(conv1pos(a, b, c1), 0.f);
        }
    };

    // seeds: all 11 conv2 positions, {A,B}-packed accumulators
    auto conv2_full_pk = [&](ull* Lo, ull* Hi) {
        #pragma unroll
        for (int j = 0; j < 11; ++j) { Lo[j] = b2lo; Hi[j] = b2hi; }
        #pragma unroll 1
        for (int cp = 0; cp < 16; ++cp) {
            float4 wa0 = w2xf[(2 * cp)     * 32 + lane];
            float4 wa1 = w2xf[(2 * cp + 1) * 32 + lane];
            float2 k0  = w2k2f[(2 * cp)     * 32 + lane];
            float2 k1  = w2k2f[(2 * cp + 1) * 32 + lane];
            ull d00 = pkdup(wa0.x), d01 = pkdup(wa0.y), d10 = pkdup(wa0.z), d11 = pkdup(wa0.w);
            ull e00 = pkdup(wa1.x), e01 = pkdup(wa1.y), e10 = pkdup(wa1.z), e11 = pkdup(wa1.w);
            ull d20 = pkdup(k0.x),  d21 = pkdup(k0.y);
            ull e20 = pkdup(k1.x),  e21 = pkdup(k1.y);
            #pragma unroll
            for (int m = 0; m < 13; ++m) {
                ulonglong2 q = qv[m * 16 + cp];   // .x: {A,B} ci=2cp ; .y: ci=2cp+1
                if (m <= 10) {
                    Lo[m] = ffma2(q.x, d00, Lo[m]); Lo[m] = ffma2(q.y, e00, Lo[m]);
                    Hi[m] = ffma2(q.x, d01, Hi[m]); Hi[m] = ffma2(q.y, e01, Hi[m]);
                }
                if (m >= 1 && m <= 11) {
                    Lo[m-1] = ffma2(q.x, d10, Lo[m-1]); Lo[m-1] = ffma2(q.y, e10, Lo[m-1]);
                    Hi[m-1] = ffma2(q.x, d11, Hi[m-1]); Hi[m-1] = ffma2(q.y, e11, Hi[m-1]);
                }
                if (m >= 2) {
                    Lo[m-2] = ffma2(q.x, d20, Lo[m-2]); Lo[m-2] = ffma2(q.y, e20, Lo[m-2]);
                    Hi[m-2] = ffma2(q.x, d21, Hi[m-2]); Hi[m-2] = ffma2(q.y, e21, Hi[m-2]);
                }
            }
        }
    };

    // incremental: fresh positions {0, 9, 10}, {A,B}-packed
    auto conv2_inc_pk = [&](ull* nlo, ull* nhi) {   // nlo/nhi: [0]=pos0, [1]=pos9, [2]=pos10
        nlo[0] = nlo[1] = nlo[2] = b2lo;
        nhi[0] = nhi[1] = nhi[2] = b2hi;
        #pragma unroll 4
        for (int cp = 0; cp < 16; ++cp) {
            float4 wa0 = w2xf[(2 * cp)     * 32 + lane];
            float4 wa1 = w2xf[(2 * cp + 1) * 32 + lane];
            float2 k0  = w2k2f[(2 * cp)     * 32 + lane];
            float2 k1  = w2k2f[(2 * cp + 1) * 32 + lane];
            ull d00 = pkdup(wa0.x), d01 = pkdup(wa0.y), d10 = pkdup(wa0.z), d11 = pkdup(wa0.w);
            ull e00 = pkdup(wa1.x), e01 = pkdup(wa1.y), e10 = pkdup(wa1.z), e11 = pkdup(wa1.w);
            ull d20 = pkdup(k0.x),  d21 = pkdup(k0.y);
            ull e20 = pkdup(k1.x),  e21 = pkdup(k1.y);

            ulonglong2 q0 = qv[0 * 16 + cp], q1 = qv[1 * 16 + cp], q2 = qv[2 * 16 + cp];
            nlo[0] = ffma2(q0.x, d00, nlo[0]); nlo[0] = ffma2(q0.y, e00, nlo[0]);
            nhi[0] = ffma2(q0.x, d01, nhi[0]); nhi[0] = ffma2(q0.y, e01, nhi[0]);
            nlo[0] = ffma2(q1.x, d10, nlo[0]); nlo[0] = ffma2(q1.y, e10, nlo[0]);
            nhi[0] = ffma2(q1.x, d11, nhi[0]); nhi[0] = ffma2(q1.y, e11, nhi[0]);
            nlo[0] = ffma2(q2.x, d20, nlo[0]); nlo[0] = ffma2(q2.y, e20, nlo[0]);
            nhi[0] = ffma2(q2.x, d21, nhi[0]); nhi[0] = ffma2(q2.y, e21, nhi[0]);

            ulonglong2 q9  = qv[9 * 16 + cp],  q10 = qv[10 * 16 + cp];
            ulonglong2 q11 = qv[11 * 16 + cp], q12 = qv[12 * 16 + cp];
            nlo[1] = ffma2(q9.x,  d00, nlo[1]); nlo[1] = ffma2(q9.y,  e00, nlo[1]);
            nhi[1] = ffma2(q9.x,  d01, nhi[1]); nhi[1] = ffma2(q9.y,  e01, nhi[1]);
            nlo[1] = ffma2(q10.x, d10, nlo[1]); nlo[1] = ffma2(q10.y, e10, nlo[1]);
            nhi[1] = ffma2(q10.x, d11, nhi[1]); nhi[1] = ffma2(q10.y, e11, nhi[1]);
            nlo[1] = ffma2(q11.x, d20, nlo[1]); nlo[1] = ffma2(q11.y, e20, nlo[1]);
            nhi[1] = ffma2(q11.x, d21, nhi[1]); nhi[1] = ffma2(q11.y, e21, nhi[1]);

            nlo[2] = ffma2(q10.x, d00, nlo[2]); nlo[2] = ffma2(q10.y, e00, nlo[2]);
            nhi[2] = ffma2(q10.x, d01, nhi[2]); nhi[2] = ffma2(q10.y, e01, nhi[2]);
            nlo[2] = ffma2(q11.x, d10, nlo[2]); nlo[2] = ffma2(q11.y, e10, nlo[2]);
            nhi[2] = ffma2(q11.x, d11, nhi[2]); nhi[2] = ffma2(q11.y, e11, nhi[2]);
            nlo[2] = ffma2(q12.x, d20, nlo[2]); nlo[2] = ffma2(q12.y, e20, nlo[2]);
            nhi[2] = ffma2(q12.x, d21, nhi[2]); nhi[2] = ffma2(q12.y, e21, nhi[2]);
        }
    };

    // pool2 + dense2 + packed reduce + dense1 + recurrence; state packed {A,B}
    auto tail2pk = [&](const ull* lo, const ull* hi, int st, int t) {
        ull saccA[5] = {0,0,0,0,0}, saccB[5] = {0,0,0,0,0};
        #pragma unroll
        for (int jj = 0; jj < 6; ++jj) {
            float aA, aB, bA, bB;
            ull fapA, fbpA, fapB, fbpB;
            if (jj < 5) {
                unpk(lo[(2 * jj) * st], aA, aB); unpk(lo[(2 * jj + 1) * st], bA, bB);
                fapA = pkdup(fmaxf(fmaxf(aA, 0.f), fmaxf(bA, 0.f)));
                fapB = pkdup(fmaxf(fmaxf(aB, 0.f), fmaxf(bB, 0.f)));
                unpk(hi[(2 * jj) * st], aA, aB); unpk(hi[(2 * jj + 1) * st], bA, bB);
                fbpA = pkdup(fmaxf(fmaxf(aA, 0.f), fmaxf(bA, 0.f)));
                fbpB = pkdup(fmaxf(fmaxf(aB, 0.f), fmaxf(bB, 0.f)));
            } else {
                unpk(lo[10 * st], aA, aB);
                fapA = pkdup(fmaxf(aA, 0.f)); fapB = pkdup(fmaxf(aB, 0.f));
                unpk(hi[10 * st], aA, aB);
                fbpA = pkdup(fmaxf(aA, 0.f)); fbpB = pkdup(fmaxf(aB, 0.f));
            }
            #pragma unroll
            for (int q = 0; q < 5; ++q) {
                ulonglong2 w = wdx[(q * 6 + jj) * 32 + lane];   // shared load
                saccA[q] = ffma2(fapA, w.x, saccA[q]);
                saccA[q] = ffma2(fbpA, w.y, saccA[q]);
                saccB[q] = ffma2(fapB, w.x, saccB[q]);
                saccB[q] = ffma2(fbpB, w.y, saccB[q]);
            }
        }
        #pragma unroll
        for (int off = 16; off > 0; off >>= 1) {
            #pragma unroll
            for (int q = 0; q < 5; ++q) {
                saccA[q] = addf32x2(saccA[q], __shfl_xor_sync(0xffffffffu, saccA[q], off));
                saccB[q] = addf32x2(saccB[q], __shfl_xor_sync(0xffffffffu, saccB[q], off));
            }
        }
        float dA[10], dB[10];
        #pragma unroll
        for (int q = 0; q < 5; ++q) {
            unpk(saccA[q], dA[2 * q], dA[2 * q + 1]);
            unpk(saccB[q], dB[2 * q], dB[2 * q + 1]);
        }
        float bd1v = sm[BD1_OFF];
        float yA = bd1v, yB = bd1v;
        #pragma unroll
        for (int o = 0; o < 10; ++o) {
            float bd = sm[BD2_OFF + o];
            float wd = sm[WD1_OFF + o];
            yA = fmaf(fmaxf(dA[o] + bd, 0.0f), wd, yA);
            yB = fmaf(fmaxf(dB[o] + bd, 0.0f), wd, yB);
        }
        float accvA = fmaf(10.0f, yA, -6.0f);
        float accvB = fmaf(10.0f, yB, -6.0f);

        float ppA = fmaf(0.1f, s24A,  p24A);
        float psA = fmaf(0.1f, accvA, s24A);
        float ppB = fmaf(0.1f, s24B,  p24B);
        float psB = fmaf(0.1f, accvB, s24B);
        if (lane == 0) out2A[t] = make_float2(ppA, psA);
        if (lane == 1) out2B[t] = make_float2(ppB, psB);

        x0a = __shfl_down_sync(0xffffffffu, x0a, 1);
        x1a = __shfl_down_sync(0xffffffffu, x1a, 1);
        x2a = __shfl_down_sync(0xffffffffu, x2a, 1);
        x0b = __shfl_down_sync(0xffffffffu, x0b, 1);
        x1b = __shfl_down_sync(0xffffffffu, x1b, 1);
        x2b = __shfl_down_sync(0xffffffffu, x2b, 1);
        if (lane == 24) {
            x0a = (ldnA.x - ppA) * (1.0f / 200.0f);
            x1a = psA * (1.0f / 40.0f);
            x2a = ldnA.y * (1.0f / 40.0f);
            x0b = (ldnB.x - ppB) * (1.0f / 200.0f);
            x1b = psB * (1.0f / 40.0f);
            x2b = ldnB.y * (1.0f / 40.0f);
        }
        p24A = ppA; s24A = psA;
        p24B = ppB; s24B = psB;
    };

    // ---------- seed steps (full compute) ----------
    ull Rlo[11], Rhi[11];   // even-parity packed state (registers)
    if (lane == 24) { ldnA = lead2A[0 + PAST]; ldnB = lead2B[0 + PAST]; }
    publish2();
    conv1_full(xbA, 0); conv1_full(xbB, 1);
    __syncwarp();
    conv2_full_pk(Rlo, Rhi);
    tail2pk(Rlo, Rhi, 1, 0);

    {
        if (lane == 24) { ldnA = lead2A[1 + PAST]; ldnB = lead2B[1 + PAST]; }
        publish2();
        conv1_full(xbA, 0); conv1_full(xbB, 1);
        __syncwarp();
        ull Tlo[11], Thi[11];
        conv2_full_pk(Tlo, Thi);
        #pragma unroll
        for (int j = 0; j < 11; ++j) {
            Slo[j * 32 + lane] = Tlo[j];
            Shi[j * 32 + lane] = Thi[j];
        }
        tail2pk(Tlo, Thi, 1, 1);
    }

    // ---------- main incremental loop ----------
    #pragma unroll 1
    for (int t = 2; t < NT; t += 2) {
        // even step t : register state
        if (lane == 24) { ldnA = lead2A[t + PAST]; ldnB = lead2B[t + PAST]; }
        publish2();
        conv1_inc(xbA, 0); conv1_inc(xbB, 1);
        __syncwarp();
        ull nlo[3], nhi[3];
        conv2_inc_pk(nlo, nhi);
        Rlo[0] = nlo[0]; Rhi[0] = nhi[0];
        #pragma unroll
        for (int j = 1; j <= 8; ++j) { Rlo[j] = Rlo[j + 1]; Rhi[j] = Rhi[j + 1]; }
        Rlo[9] = nlo[1]; Rlo[10] = nlo[2];
        Rhi[9] = nhi[1]; Rhi[10] = nhi[2];
        tail2pk(Rlo, Rhi, 1, t);

        // odd step t+1 : smem packed state, shifted in place (lane-private)
        ldnA = make_float2(0.f, 0.f); ldnB = make_float2(0.f, 0.f);
        if (lane == 24 && (t + 1) < NT - 1) {
            ldnA = lead2A[t + 1 + PAST];
            ldnB = lead2B[t + 1 + PAST];
        }
        publish2();
        conv1_inc(xbA, 0); conv1_inc(xbB, 1);
        __syncwarp();
        ull mlo[3], mhi[3];
        conv2_inc_pk(mlo, mhi);
        #pragma unroll
        for (int j = 1; j <= 8; ++j) {   // ascending: read j+1 before overwrite
            Slo[j * 32 + lane] = Slo[(j + 1) * 32 + lane];
            Shi[j * 32 + lane] = Shi[(j + 1) * 32 + lane];
        }
        Slo[0 * 32 + lane] = mlo[0]; Slo[9 * 32 + lane] = mlo[1]; Slo[10 * 32 + lane] = mlo[2];
        Shi[0 * 32 + lane] = mhi[0]; Shi[9 * 32 + lane] = mhi[1]; Shi[10 * 32 + lane] = mhi[2];
        tail2pk(Slo + lane, Shi + lane, 32, t + 1);
    }
}

extern "C" void kernel_launch(void* const* d_in, const int* in_sizes, int n_in,
                              void* d_out, int out_size)
{
    const float* lead = (const float*)d_in[0];   // (4096, 280, 2)
    const float* cur  = (const float*)d_in[1];   // (4096, 25, 2)
    // d_in[2] = mask (unused by the reference computation)
    const float* w1  = (const float*)d_in[3];
    const float* b1  = (const float*)d_in[4];
    const float* w2  = (const float*)d_in[5];
    const float* b2  = (const float*)d_in[6];
    const float* wd2 = (const float*)d_in[7];
    const float* bd2 = (const float*)d_in[8];
    const float* wd1 = (const float*)d_in[9];
    const float* bd1 = (const float*)d_in[10];
    float* out = (float*)d_out;                   // (4096, 256, 2)

    (void)in_sizes; (void)n_in; (void)out_size;

    size_t smem_bytes = (size_t)SMEM_FLOATS * sizeof(float);   // 179104 B
    cudaFuncSetAttribute(rnncf_kernel,
                         cudaFuncAttributeMaxDynamicSharedMemorySize,
                         (int)smem_bytes);
    rnncf_kernel<<<NCTA, NTHREADS, smem_bytes>>>(
        lead, cur, w1, b1, w2, b2, wd2, bd2, wd1, bd1, out);
}

// round 10
// speedup vs baseline: 3.0478x; 1.1278x over previous
#include <cuda_runtime.h>

#define NVEH 4096
#define NT 256
#define PAST 25
#define LEADLEN (NT + PAST - 1)   // 280
#define NQUAD (NVEH / 4)          // 1024
#define WARPS_PER_CTA 7
#define NCTA ((NQUAD + WARPS_PER_CTA - 1) / WARPS_PER_CTA)   // 147
#define NTHREADS (WARPS_PER_CTA * 32)                         // 224

typedef unsigned long long ull;

// ---- shared memory layout (float offsets) ----
#define W1_OFF    0        // 288  : conv1_w [3][3][32]
#define B1_OFF    288      // 32
#define B2P_OFF   320      // 64   : float2 {b2[c], b2[c+32]}
#define W2X_OFF   384      // 4096 : float4 [ci*32+c] = {w0[c], w0[c+32], w1[c], w1[c+32]}
#define W2K2_OFF  4480     // 2048 : float4 [cp*32+c] = {k2[2cp][c], k2[2cp][c+32], k2[2cp+1][c], k2[2cp+1][c+32]}
#define WD2X_OFF  6528     // 3840 : ull2 [(q*6+jj)*32+c] = {pair_i, pair_{i+32}}
#define BD2_OFF   10368    // 10
#define WD1_OFF   10378    // 10
#define BD1_OFF   10388    // 1 (+3 pad)
#define XBUF_OFF  10392    // 14 sets * 27 pos * 8 floats {x0A,x0B,x1A,x1B,x2A,x2B,0,0} -> 3024
#define PAB_OFF   13416    // 14 sets * 13*32 float2 {pA,pB} -> 11648
#define S_OFF     (PAB_OFF + 14 * 13 * 32 * 2)   // 25064 : odd-parity packed state, 14 sets * 22*32 ull
#define SMEM_FLOATS (S_OFF + 14 * 22 * 32 * 2)   // 44776 floats = 179104 B

__device__ __forceinline__ ull ffma2(ull a, ull b, ull c) {
    ull d;
    asm("fma.rn.f32x2 %0, %1, %2, %3;" : "=l"(d) : "l"(a), "l"(b), "l"(c));
    return d;
}
__device__ __forceinline__ ull addf32x2(ull a, ull b) {
    ull d;
    asm("add.rn.f32x2 %0, %1, %2;" : "=l"(d) : "l"(a), "l"(b));
    return d;
}
__device__ __forceinline__ void unpk(ull v, float& lo, float& hi) {
    asm("mov.b64 {%0, %1}, %2;" : "=f"(lo), "=f"(hi) : "l"(v));
}
__device__ __forceinline__ ull pkdup(float x) {
    ull d;
    asm("mov.b64 %0, {%1, %1};" : "=l"(d) : "f"(x));
    return d;
}

__global__ void __launch_bounds__(NTHREADS, 1)
rnncf_kernel(const float* __restrict__ lead, const float* __restrict__ cur,
             const float* __restrict__ w1g, const float* __restrict__ b1g,
             const float* __restrict__ w2g, const float* __restrict__ b2g,
             const float* __restrict__ wd2g, const float* __restrict__ bd2g,
             const float* __restrict__ wd1g, const float* __restrict__ bd1g,
             float* __restrict__ out)
{
    extern __shared__ float sm[];
    const int tid = threadIdx.x;

    // ---------- cooperative weight staging ----------
    for (int i = tid; i < 288; i += NTHREADS) sm[W1_OFF + i] = w1g[i];
    for (int i = tid; i < 32;  i += NTHREADS) sm[B1_OFF + i] = b1g[i];
    {
        float2* b2p_s = (float2*)(sm + B2P_OFF);
        for (int i = tid; i < 32; i += NTHREADS)
            b2p_s[i] = make_float2(b2g[i], b2g[i + 32]);
        float4* w2x_s = (float4*)(sm + W2X_OFF);
        for (int i = tid; i < 1024; i += NTHREADS) {
            int ci = i >> 5, c = i & 31;
            w2x_s[i] = make_float4(w2g[ci * 64 + c],        w2g[ci * 64 + c + 32],
                                   w2g[(32 + ci) * 64 + c], w2g[(32 + ci) * 64 + c + 32]);
        }
        float4* w2k2_s = (float4*)(sm + W2K2_OFF);
        for (int i = tid; i < 512; i += NTHREADS) {
            int cp = i >> 5, c = i & 31;
            w2k2_s[i] = make_float4(w2g[(64 + 2 * cp) * 64 + c],     w2g[(64 + 2 * cp) * 64 + c + 32],
                                    w2g[(64 + 2 * cp + 1) * 64 + c], w2g[(64 + 2 * cp + 1) * 64 + c + 32]);
        }
        float4* wdx_s = (float4*)(sm + WD2X_OFF);
        for (int i = tid; i < 960; i += NTHREADS) {
            int q = i / 192, r = i - q * 192;
            int jj = r >> 5, c = r & 31;
            int ii = jj * 64 + c;
            wdx_s[i] = make_float4(wd2g[ii * 10 + 2 * q],        wd2g[ii * 10 + 2 * q + 1],
                                   wd2g[(ii + 32) * 10 + 2 * q], wd2g[(ii + 32) * 10 + 2 * q + 1]);
        }
    }
    for (int i = tid; i < 10; i += NTHREADS) sm[BD2_OFF + i] = bd2g[i];
    for (int i = tid; i < 10; i += NTHREADS) sm[WD1_OFF + i] = wd1g[i];
    if (tid == 0) sm[BD1_OFF] = bd1g[0];
    // zero xbuf: borders (pos 0 and 26) and pad floats must stay zero forever
    for (int i = tid; i < 14 * 27 * 8; i += NTHREADS) sm[XBUF_OFF + i] = 0.0f;
    __syncthreads();

    const int wid = tid >> 5, lane = tid & 31;
    const int quad = blockIdx.x * WARPS_PER_CTA + wid;
    if (quad >= NQUAD) return;

    // per-warp smem regions (two vehicle-pair sets)
    float* xbuf0 = sm + XBUF_OFF + (wid * 2 + 0) * (27 * 8);
    float* xbuf1 = sm + XBUF_OFF + (wid * 2 + 1) * (27 * 8);
    float2* pab0 = (float2*)(sm + PAB_OFF) + (wid * 2 + 0) * (13 * 32);
    float2* pab1 = (float2*)(sm + PAB_OFF) + (wid * 2 + 1) * (13 * 32);
    const ulonglong2* qv0 = (const ulonglong2*)pab0;
    const ulonglong2* qv1 = (const ulonglong2*)pab1;
    ull* Slo0 = (ull*)(sm + S_OFF) + (wid * 2 + 0) * (22 * 32);
    ull* Shi0 = Slo0 + 11 * 32;
    ull* Slo1 = (ull*)(sm + S_OFF) + (wid * 2 + 1) * (22 * 32);
    ull* Shi1 = Slo1 + 11 * 32;
    const float4* w2xf   = (const float4*)(sm + W2X_OFF);
    const float4* w2k2f4 = (const float4*)(sm + W2K2_OFF);
    const ulonglong2* wdx = (const ulonglong2*)(sm + WD2X_OFF);

    const float2* lead2v[4];
    const float2* cur2v[4];
    float2* out2v[4];
    #pragma unroll
    for (int i = 0; i < 4; ++i) {
        int v = 4 * quad + i;
        lead2v[i] = (const float2*)lead + (size_t)v * LEADLEN;
        cur2v[i]  = (const float2*)cur  + (size_t)v * PAST;
        out2v[i]  = (float2*)out + (size_t)v * NT;
    }

    // hoisted constants
    ull w1d[9];
    #pragma unroll
    for (int i = 0; i < 9; ++i) w1d[i] = pkdup(sm[W1_OFF + i * 32 + lane]);
    const ull b1d = pkdup(sm[B1_OFF + lane]);
    ull b2lo, b2hi;
    {
        float2 b2v = ((const float2*)(sm + B2P_OFF))[lane];
        b2lo = pkdup(b2v.x);
        b2hi = pkdup(b2v.y);
    }

    // ---------- initial windows: lane i (<25) holds column i, packed {A,B} ----------
    float2 xw0[2], xw1[2], xw2[2];
    #pragma unroll
    for (int s = 0; s < 2; ++s) {
        xw0[s] = make_float2(0.f, 0.f);
        xw1[s] = make_float2(0.f, 0.f);
        xw2[s] = make_float2(0.f, 0.f);
    }
    float p24v[4], s24v[4];
    {
        float tp[4] = {0.f, 0.f, 0.f, 0.f}, ts[4] = {0.f, 0.f, 0.f, 0.f};
        if (lane < PAST) {
            #pragma unroll
            for (int i = 0; i < 4; ++i) {
                float2 cs = cur2v[i][lane];
                float2 ld = lead2v[i][lane];
                float X0 = (ld.x - cs.x) * (1.0f / 200.0f);
                float X1 = cs.y * (1.0f / 40.0f);
                float X2 = ld.y * (1.0f / 40.0f);
                int s = i >> 1;
                if ((i & 1) == 0) { xw0[s].x = X0; xw1[s].x = X1; xw2[s].x = X2; }
                else              { xw0[s].y = X0; xw1[s].y = X1; xw2[s].y = X2; }
                tp[i] = cs.x; ts[i] = cs.y;
            }
        }
        #pragma unroll
        for (int i = 0; i < 4; ++i) {
            p24v[i] = __shfl_sync(0xffffffffu, tp[i], 24);
            s24v[i] = __shfl_sync(0xffffffffu, ts[i], 24);
        }
    }
    float2 ldnv[4];
    #pragma unroll
    for (int i = 0; i < 4; ++i) ldnv[i] = make_float2(0.f, 0.f);

    // ---------- helpers ----------
    auto publish = [&]() {
        if (lane < PAST) {
            *(float4*)(xbuf0 + (lane + 1) * 8)     = make_float4(xw0[0].x, xw0[0].y, xw1[0].x, xw1[0].y);
            *(float2*)(xbuf0 + (lane + 1) * 8 + 4) = xw2[0];
            *(float4*)(xbuf1 + (lane + 1) * 8)     = make_float4(xw0[1].x, xw0[1].y, xw1[1].x, xw1[1].y);
            *(float2*)(xbuf1 + (lane + 1) * 8 + 4) = xw2[1];
        }
        __syncwarp();
    };

    // packed conv1 position: a/b/c are {x0A,x0B,x1A,x1B} + {x2A,x2B}
    auto c1pos = [&](ulonglong2 a01, ull a2, ulonglong2 b01, ull b2_,
                     ulonglong2 c01, ull c2) -> ull {
        ull h = b1d;
        h = ffma2(a01.x, w1d[0], h); h = ffma2(a01.y, w1d[1], h); h = ffma2(a2,  w1d[2], h);
        h = ffma2(b01.x, w1d[3], h); h = ffma2(b01.y, w1d[4], h); h = ffma2(b2_, w1d[5], h);
        h = ffma2(c01.x, w1d[6], h); h = ffma2(c01.y, w1d[7], h); h = ffma2(c2,  w1d[8], h);
        return h;
    };
    auto poolpair = [&](ull h0, ull h1) -> float2 {
        float f0A, f0B, f1A, f1B;
        unpk(h0, f0A, f0B); unpk(h1, f1A, f1B);
        return make_float2(fmaxf(fmaxf(f0A, 0.f), fmaxf(f1A, 0.f)),
                           fmaxf(fmaxf(f0B, 0.f), fmaxf(f1B, 0.f)));
    };
    auto poolone = [&](ull h0) -> float2 {
        float f0A, f0B;
        unpk(h0, f0A, f0B);
        return make_float2(fmaxf(f0A, 0.f), fmaxf(f0B, 0.f));
    };

    auto conv1_full = [&](const float* xb, float2* pd) {   // all 13 pool1 slots (seeds)
        ulonglong2 a01 = *(const ulonglong2*)(xb);
        ull        a2  = *(const ull*)(xb + 4);
        ulonglong2 b01 = *(const ulonglong2*)(xb + 8);
        ull        b2_ = *(const ull*)(xb + 12);
        #pragma unroll
        for (int m = 0; m < 12; ++m) {
            ulonglong2 c01 = *(const ulonglong2*)(xb + (2 * m + 2) * 8);
            ull        c2  = *(const ull*)(xb + (2 * m + 2) * 8 + 4);
            ulonglong2 d01 = *(const ulonglong2*)(xb + (2 * m + 3) * 8);
            ull        d2  = *(const ull*)(xb + (2 * m + 3) * 8 + 4);
            ull h0 = c1pos(a01, a2, b01, b2_, c01, c2);
            ull h1 = c1pos(b01, b2_, c01, c2, d01, d2);
            pd[m * 32 + lane] = poolpair(h0, h1);
            a01 = c01; a2 = c2; b01 = d01; b2_ = d2;
        }
        ulonglong2 c01 = *(const ulonglong2*)(xb + 26 * 8);
        ull        c2  = *(const ull*)(xb + 26 * 8 + 4);
        pd[12 * 32 + lane] = poolone(c1pos(a01, a2, b01, b2_, c01, c2));
    };

    auto conv1_inc = [&](const float* xb, float2* pd) {    // boundary slots 0..2, 9..12
        {
            ulonglong2 a01 = *(const ulonglong2*)(xb);
            ull        a2  = *(const ull*)(xb + 4);
            ulonglong2 b01 = *(const ulonglong2*)(xb + 8);
            ull        b2_ = *(const ull*)(xb + 12);
            #pragma unroll
            for (int m = 0; m < 3; ++m) {
                ulonglong2 c01 = *(const ulonglong2*)(xb + (2 * m + 2) * 8);
                ull        c2  = *(const ull*)(xb + (2 * m + 2) * 8 + 4);
                ulonglong2 d01 = *(const ulonglong2*)(xb + (2 * m + 3) * 8);
                ull        d2  = *(const ull*)(xb + (2 * m + 3) * 8 + 4);
                ull h0 = c1pos(a01, a2, b01, b2_, c01, c2);
                ull h1 = c1pos(b01, b2_, c01, c2, d01, d2);
                pd[m * 32 + lane] = poolpair(h0, h1);
                a01 = c01; a2 = c2; b01 = d01; b2_ = d2;
            }
        }
        {
            ulonglong2 a01 = *(const ulonglong2*)(xb + 18 * 8);
            ull        a2  = *(const ull*)(xb + 18 * 8 + 4);
            ulonglong2 b01 = *(const ulonglong2*)(xb + 19 * 8);
            ull        b2_ = *(const ull*)(xb + 19 * 8 + 4);
            #pragma unroll
            for (int m = 9; m < 12; ++m) {
                ulonglong2 c01 = *(const ulonglong2*)(xb + (2 * m + 2) * 8);
                ull        c2  = *(const ull*)(xb + (2 * m + 2) * 8 + 4);
                ulonglong2 d01 = *(const ulonglong2*)(xb + (2 * m + 3) * 8);
                ull        d2  = *(const ull*)(xb + (2 * m + 3) * 8 + 4);
                ull h0 = c1pos(a01, a2, b01, b2_, c01, c2);
                ull h1 = c1pos(b01, b2_, c01, c2, d01, d2);
                pd[m * 32 + lane] = poolpair(h0, h1);
                a01 = c01; a2 = c2; b01 = d01; b2_ = d2;
            }
            ulonglong2 c01 = *(const ulonglong2*)(xb + 26 * 8);
            ull        c2  = *(const ull*)(xb + 26 * 8 + 4);
            pd[12 * 32 + lane] = poolone(c1pos(a01, a2, b01, b2_, c01, c2));
        }
    };

    // seeds: all 11 conv2 positions for one set
    auto conv2_full = [&](const ulonglong2* q, ull* Lo, ull* Hi) {
        #pragma unroll
        for (int j = 0; j < 11; ++j) { Lo[j] = b2lo; Hi[j] = b2hi; }
        #pragma unroll 1
        for (int cp = 0; cp < 16; ++cp) {
            float4 wa0 = w2xf[(2 * cp)     * 32 + lane];
            float4 wa1 = w2xf[(2 * cp + 1) * 32 + lane];
            float4 kk  = w2k2f4[cp * 32 + lane];
            ull d00 = pkdup(wa0.x), d01 = pkdup(wa0.y), d10 = pkdup(wa0.z), d11 = pkdup(wa0.w);
            ull e00 = pkdup(wa1.x), e01 = pkdup(wa1.y), e10 = pkdup(wa1.z), e11 = pkdup(wa1.w);
            ull d20 = pkdup(kk.x),  d21 = pkdup(kk.y),  e20 = pkdup(kk.z),  e21 = pkdup(kk.w);
            #pragma unroll
            for (int m = 0; m < 13; ++m) {
                ulonglong2 qp = q[m * 16 + cp];
                if (m <= 10) {
                    Lo[m] = ffma2(qp.x, d00, Lo[m]); Lo[m] = ffma2(qp.y, e00, Lo[m]);
                    Hi[m] = ffma2(qp.x, d01, Hi[m]); Hi[m] = ffma2(qp.y, e01, Hi[m]);
                }
                if (m >= 1 && m <= 11) {
                    Lo[m-1] = ffma2(qp.x, d10, Lo[m-1]); Lo[m-1] = ffma2(qp.y, e10, Lo[m-1]);
                    Hi[m-1] = ffma2(qp.x, d11, Hi[m-1]); Hi[m-1] = ffma2(qp.y, e11, Hi[m-1]);
                }
                if (m >= 2) {
                    Lo[m-2] = ffma2(qp.x, d20, Lo[m-2]); Lo[m-2] = ffma2(qp.y, e20, Lo[m-2]);
                    Hi[m-2] = ffma2(qp.x, d21, Hi[m-2]); Hi[m-2] = ffma2(qp.y, e21, Hi[m-2]);
                }
            }
        }
    };

    // incremental: fresh positions {0,9,10}, both sets, weights loaded once
    auto conv2_inc2 = [&](ull (&nlo)[2][3], ull (&nhi)[2][3]) {
        #pragma unroll
        for (int s = 0; s < 2; ++s) {
            nlo[s][0] = nlo[s][1] = nlo[s][2] = b2lo;
            nhi[s][0] = nhi[s][1] = nhi[s][2] = b2hi;
        }
        #pragma unroll 4
        for (int cp = 0; cp < 16; ++cp) {
            float4 wa0 = w2xf[(2 * cp)     * 32 + lane];
            float4 wa1 = w2xf[(2 * cp + 1) * 32 + lane];
            float4 kk  = w2k2f4[cp * 32 + lane];
            ull d00 = pkdup(wa0.x), d01 = pkdup(wa0.y), d10 = pkdup(wa0.z), d11 = pkdup(wa0.w);
            ull e00 = pkdup(wa1.x), e01 = pkdup(wa1.y), e10 = pkdup(wa1.z), e11 = pkdup(wa1.w);
            ull d20 = pkdup(kk.x),  d21 = pkdup(kk.y),  e20 = pkdup(kk.z),  e21 = pkdup(kk.w);
            #pragma unroll
            for (int s = 0; s < 2; ++s) {
                const ulonglong2* q = s ? qv1 : qv0;
                ulonglong2 q0 = q[0 * 16 + cp], q1 = q[1 * 16 + cp], q2 = q[2 * 16 + cp];
                nlo[s][0] = ffma2(q0.x, d00, nlo[s][0]); nlo[s][0] = ffma2(q0.y, e00, nlo[s][0]);
                nhi[s][0] = ffma2(q0.x, d01, nhi[s][0]); nhi[s][0] = ffma2(q0.y, e01, nhi[s][0]);
                nlo[s][0] = ffma2(q1.x, d10, nlo[s][0]); nlo[s][0] = ffma2(q1.y, e10, nlo[s][0]);
                nhi[s][0] = ffma2(q1.x, d11, nhi[s][0]); nhi[s][0] = ffma2(q1.y, e11, nhi[s][0]);
                nlo[s][0] = ffma2(q2.x, d20, nlo[s][0]); nlo[s][0] = ffma2(q2.y, e20, nlo[s][0]);
                nhi[s][0] = ffma2(q2.x, d21, nhi[s][0]); nhi[s][0] = ffma2(q2.y, e21, nhi[s][0]);

                ulonglong2 q9  = q[9 * 16 + cp],  q10 = q[10 * 16 + cp];
                ulonglong2 q11 = q[11 * 16 + cp], q12 = q[12 * 16 + cp];
                nlo[s][1] = ffma2(q9.x,  d00, nlo[s][1]); nlo[s][1] = ffma2(q9.y,  e00, nlo[s][1]);
                nhi[s][1] = ffma2(q9.x,  d01, nhi[s][1]); nhi[s][1] = ffma2(q9.y,  e01, nhi[s][1]);
                nlo[s][1] = ffma2(q10.x, d10, nlo[s][1]); nlo[s][1] = ffma2(q10.y, e10, nlo[s][1]);
                nhi[s][1] = ffma2(q10.x, d11, nhi[s][1]); nhi[s][1] = ffma2(q10.y, e11, nhi[s][1]);
                nlo[s][1] = ffma2(q11.x, d20, nlo[s][1]); nlo[s][1] = ffma2(q11.y, e20, nlo[s][1]);
                nhi[s][1] = ffma2(q11.x, d21, nhi[s][1]); nhi[s][1] = ffma2(q11.y, e21, nhi[s][1]);

                nlo[s][2] = ffma2(q10.x, d00, nlo[s][2]); nlo[s][2] = ffma2(q10.y, e00, nlo[s][2]);
                nhi[s][2] = ffma2(q10.x, d01, nhi[s][2]); nhi[s][2] = ffma2(q10.y, e01, nhi[s][2]);
                nlo[s][2] = ffma2(q11.x, d10, nlo[s][2]); nlo[s][2] = ffma2(q11.y, e10, nlo[s][2]);
                nhi[s][2] = ffma2(q11.x, d11, nhi[s][2]); nhi[s][2] = ffma2(q11.y, e11, nhi[s][2]);
                nlo[s][2] = ffma2(q12.x, d20, nlo[s][2]); nlo[s][2] = ffma2(q12.y, e20, nlo[s][2]);
                nhi[s][2] = ffma2(q12.x, d21, nhi[s][2]); nhi[s][2] = ffma2(q12.y, e21, nhi[s][2]);
            }
        }
    };

    // pool2 + dense2 + parity-merged reduce + dense1 + recurrence for one set
    auto tail_pk = [&](const ull* lo, const ull* hi, int st, int s, int t) {
        ull saccA[5] = {0,0,0,0,0}, saccB[5] = {0,0,0,0,0};
        #pragma unroll
        for (int jj = 0; jj < 6; ++jj) {
            float aA, aB, bA, bB;
            ull fapA, fbpA, fapB, fbpB;
            if (jj < 5) {
                unpk(lo[(2 * jj) * st], aA, aB); unpk(lo[(2 * jj + 1) * st], bA, bB);
                fapA = pkdup(fmaxf(fmaxf(aA, 0.f), fmaxf(bA, 0.f)));
                fapB = pkdup(fmaxf(fmaxf(aB, 0.f), fmaxf(bB, 0.f)));
                unpk(hi[(2 * jj) * st], aA, aB); unpk(hi[(2 * jj + 1) * st], bA, bB);
                fbpA = pkdup(fmaxf(fmaxf(aA, 0.f), fmaxf(bA, 0.f)));
                fbpB = pkdup(fmaxf(fmaxf(aB, 0.f), fmaxf(bB, 0.f)));
            } else {
                unpk(lo[10 * st], aA, aB);
                fapA = pkdup(fmaxf(aA, 0.f)); fapB = pkdup(fmaxf(aB, 0.f));
                unpk(hi[10 * st], aA, aB);
                fbpA = pkdup(fmaxf(aA, 0.f)); fbpB = pkdup(fmaxf(aB, 0.f));
            }
            #pragma unroll
            for (int q = 0; q < 5; ++q) {
                ulonglong2 w = wdx[(q * 6 + jj) * 32 + lane];
                saccA[q] = ffma2(fapA, w.x, saccA[q]);
                saccA[q] = ffma2(fbpA, w.y, saccA[q]);
                saccB[q] = ffma2(fapB, w.x, saccB[q]);
                saccB[q] = ffma2(fbpB, w.y, saccB[q]);
            }
        }
        // parity merge: even lanes carry vehicle A, odd lanes vehicle B
        ull s5[5];
        const bool odd = (lane & 1);
        #pragma unroll
        for (int q = 0; q < 5; ++q) {
            ull z = odd ? saccB[q] : saccA[q];
            ull x = odd ? saccA[q] : saccB[q];
            ull w = __shfl_xor_sync(0xffffffffu, x, 1);
            s5[q] = addf32x2(z, w);
        }
        #pragma unroll
        for (int off = 2; off <= 16; off <<= 1) {
            #pragma unroll
            for (int q = 0; q < 5; ++q)
                s5[q] = addf32x2(s5[q], __shfl_xor_sync(0xffffffffu, s5[q], off));
        }
        float d[10];
        #pragma unroll
        for (int q = 0; q < 5; ++q) unpk(s5[q], d[2 * q], d[2 * q + 1]);
        float y = sm[BD1_OFF];
        #pragma unroll
        for (int o = 0; o < 10; ++o)
            y = fmaf(fmaxf(d[o] + sm[BD2_OFF + o], 0.0f), sm[WD1_OFF + o], y);
        float accv = fmaf(10.0f, y, -6.0f);
        float accvA = __shfl_sync(0xffffffffu, accv, 0);
        float accvB = __shfl_sync(0xffffffffu, accv, 1);

        int iA = 2 * s, iB = 2 * s + 1;
        float ppA = fmaf(0.1f, s24v[iA], p24v[iA]);
        float psA = fmaf(0.1f, accvA,   s24v[iA]);
        float ppB = fmaf(0.1f, s24v[iB], p24v[iB]);
        float psB = fmaf(0.1f, accvB,   s24v[iB]);
        if (lane == iA) out2v[iA][t] = make_float2(ppA, psA);
        if (lane == iB) out2v[iB][t] = make_float2(ppB, psB);

        xw0[s].x = __shfl_down_sync(0xffffffffu, xw0[s].x, 1);
        xw0[s].y = __shfl_down_sync(0xffffffffu, xw0[s].y, 1);
        xw1[s].x = __shfl_down_sync(0xffffffffu, xw1[s].x, 1);
        xw1[s].y = __shfl_down_sync(0xffffffffu, xw1[s].y, 1);
        xw2[s].x = __shfl_down_sync(0xffffffffu, xw2[s].x, 1);
        xw2[s].y = __shfl_down_sync(0xffffffffu, xw2[s].y, 1);
        if (lane == 24) {
            xw0[s] = make_float2((ldnv[iA].x - ppA) * (1.0f / 200.0f),
                                 (ldnv[iB].x - ppB) * (1.0f / 200.0f));
            xw1[s] = make_float2(psA * (1.0f / 40.0f), psB * (1.0f / 40.0f));
            xw2[s] = make_float2(ldnv[iA].y * (1.0f / 40.0f), ldnv[iB].y * (1.0f / 40.0f));
        }
        p24v[iA] = ppA; s24v[iA] = psA;
        p24v[iB] = ppB; s24v[iB] = psB;
    };

    // ---------- seed steps (full compute) ----------
    ull Rlo0[11], Rhi0[11], Rlo1[11], Rhi1[11];   // even-parity state (registers)
    if (lane == 24) {
        #pragma unroll
        for (int i = 0; i < 4; ++i) ldnv[i] = lead2v[i][0 + PAST];
    }
    publish();
    conv1_full(xbuf0, pab0); conv1_full(xbuf1, pab1);
    __syncwarp();
    conv2_full(qv0, Rlo0, Rhi0);
    conv2_full(qv1, Rlo1, Rhi1);
    tail_pk(Rlo0, Rhi0, 1, 0, 0);
    tail_pk(Rlo1, Rhi1, 1, 1, 0);

    {
        if (lane == 24) {
            #pragma unroll
            for (int i = 0; i < 4; ++i) ldnv[i] = lead2v[i][1 + PAST];
        }
        publish();
        conv1_full(xbuf0, pab0); conv1_full(xbuf1, pab1);
        __syncwarp();
        ull Tlo[11], Thi[11];
        conv2_full(qv0, Tlo, Thi);
        #pragma unroll
        for (int j = 0; j < 11; ++j) { Slo0[j * 32 + lane] = Tlo[j]; Shi0[j * 32 + lane] = Thi[j]; }
        tail_pk(Tlo, Thi, 1, 0, 1);
        conv2_full(qv1, Tlo, Thi);
        #pragma unroll
        for (int j = 0; j < 11; ++j) { Slo1[j * 32 + lane] = Tlo[j]; Shi1[j * 32 + lane] = Thi[j]; }
        tail_pk(Tlo, Thi, 1, 1, 1);
    }

    // ---------- main incremental loop ----------
    #pragma unroll 1
    for (int t = 2; t < NT; t += 2) {
        // even step t : register state
        if (lane == 24) {
            #pragma unroll
            for (int i = 0; i < 4; ++i) ldnv[i] = lead2v[i][t + PAST];
        }
        publish();
        conv1_inc(xbuf0, pab0); conv1_inc(xbuf1, pab1);
        __syncwarp();
        {
            ull nlo[2][3], nhi[2][3];
            conv2_inc2(nlo, nhi);
            Rlo0[0] = nlo[0][0]; Rhi0[0] = nhi[0][0];
            Rlo1[0] = nlo[1][0]; Rhi1[0] = nhi[1][0];
            #pragma unroll
            for (int j = 1; j <= 8; ++j) {
                Rlo0[j] = Rlo0[j + 1]; Rhi0[j] = Rhi0[j + 1];
                Rlo1[j] = Rlo1[j + 1]; Rhi1[j] = Rhi1[j + 1];
            }
            Rlo0[9] = nlo[0][1]; Rlo0[10] = nlo[0][2];
            Rhi0[9] = nhi[0][1]; Rhi0[10] = nhi[0][2];
            Rlo1[9] = nlo[1][1]; Rlo1[10] = nlo[1][2];
            Rhi1[9] = nhi[1][1]; Rhi1[10] = nhi[1][2];
        }
        tail_pk(Rlo0, Rhi0, 1, 0, t);
        tail_pk(Rlo1, Rhi1, 1, 1, t);

        // odd step t+1 : smem state, shifted in place (lane-private)
        #pragma unroll
        for (int i = 0; i < 4; ++i) ldnv[i] = make_float2(0.f, 0.f);
        if (lane == 24 && (t + 1) < NT - 1) {
            #pragma unroll
            for (int i = 0; i < 4; ++i) ldnv[i] = lead2v[i][t + 1 + PAST];
        }
        publish();
        conv1_inc(xbuf0, pab0); conv1_inc(xbuf1, pab1);
        __syncwarp();
        {
            ull mlo[2][3], mhi[2][3];
            conv2_inc2(mlo, mhi);
            #pragma unroll
            for (int j = 1; j <= 8; ++j) {   // ascending: read j+1 before overwrite
                Slo0[j * 32 + lane] = Slo0[(j + 1) * 32 + lane];
                Shi0[j * 32 + lane] = Shi0[(j + 1) * 32 + lane];
                Slo1[j * 32 + lane] = Slo1[(j + 1) * 32 + lane];
                Shi1[j * 32 + lane] = Shi1[(j + 1) * 32 + lane];
            }
            Slo0[0 * 32 + lane] = mlo[0][0]; Slo0[9 * 32 + lane] = mlo[0][1]; Slo0[10 * 32 + lane] = mlo[0][2];
            Shi0[0 * 32 + lane] = mhi[0][0]; Shi0[9 * 32 + lane] = mhi[0][1]; Shi0[10 * 32 + lane] = mhi[0][2];
            Slo1[0 * 32 + lane] = mlo[1][0]; Slo1[9 * 32 + lane] = mlo[1][1]; Slo1[10 * 32 + lane] = mlo[1][2];
            Shi1[0 * 32 + lane] = mhi[1][0]; Shi1[9 * 32 + lane] = mhi[1][1]; Shi1[10 * 32 + lane] = mhi[1][2];
        }
        tail_pk(Slo0 + lane, Shi0 + lane, 32, 0, t + 1);
        tail_pk(Slo1 + lane, Shi1 + lane, 32, 1, t + 1);
    }
}

extern "C" void kernel_launch(void* const* d_in, const int* in_sizes, int n_in,
                              void* d_out, int out_size)
{
    const float* lead = (const float*)d_in[0];   // (4096, 280, 2)
    const float* cur  = (const float*)d_in[1];   // (4096, 25, 2)
    // d_in[2] = mask (unused by the reference computation)
    const float* w1  = (const float*)d_in[3];
    const float* b1  = (const float*)d_in[4];
    const float* w2  = (const float*)d_in[5];
    const float* b2  = (const float*)d_in[6];
    const float* wd2 = (const float*)d_in[7];
    const float* bd2 = (const float*)d_in[8];
    const float* wd1 = (const float*)d_in[9];
    const float* bd1 = (const float*)d_in[10];
    float* out = (float*)d_out;                   // (4096, 256, 2)

    (void)in_sizes; (void)n_in; (void)out_size;

    size_t smem_bytes = (size_t)SMEM_FLOATS * sizeof(float);   // 179104 B
    cudaFuncSetAttribute(rnncf_kernel,
                         cudaFuncAttributeMaxDynamicSharedMemorySize,
                         (int)smem_bytes);
    rnncf_kernel<<<NCTA, NTHREADS, smem_bytes>>>(
        lead, cur, w1, b1, w2, b2, wd2, bd2, wd1, bd1, out);
}

// round 11
// speedup vs baseline: 3.3510x; 1.0995x over previous
#include <cuda_runtime.h>

#define NVEH 4096
#define NT 256
#define PAST 25
#define LEADLEN (NT + PAST - 1)   // 280
#define NQUAD (NVEH / 4)          // 1024
#define WARPS_PER_CTA 7
#define NCTA ((NQUAD + WARPS_PER_CTA - 1) / WARPS_PER_CTA)   // 147
#define NTHREADS (WARPS_PER_CTA * 32)                         // 224

typedef unsigned long long ull;

// ---- shared memory layout (float offsets) ----
#define W1_OFF    0        // 288  : conv1_w [3][3][32]
#define B1_OFF    288      // 32
#define B2P_OFF   320      // 64   : float2 {b2[c], b2[c+32]}
#define W2X_OFF   384      // 4096 : float4 [ci*32+c] = {w0[c], w0[c+32], w1[c], w1[c+32]}
#define W2K2_OFF  4480     // 2048 : float4 [cp*32+c] = {k2[2cp][c], k2[2cp][c+32], k2[2cp+1][c], k2[2cp+1][c+32]}
#define WD2X_OFF  6528     // 3840 : ull2 [(q*6+jj)*32+c] = {pair_i, pair_{i+32}}
#define BD2_OFF   10368    // 10
#define WD1_OFF   10378    // 10
#define BD1_OFF   10388    // 1 (+3 pad)
#define XBUF_OFF  10392    // 14 sets * 27 pos * 8 floats
#define PAB_OFF   13416    // 14 sets * 13*32 float2 {pA,pB}
#define S_OFF     (PAB_OFF + 14 * 13 * 32 * 2)        // 25064 : circular odd-parity state
// state: 14 sets * 2 arrays(lo,hi) * 16 slots * 32 lanes * 1 ull
#define SMEM_FLOATS (S_OFF + 14 * 2 * 16 * 32 * 2)    // 53736 floats = 214944 B

__device__ __forceinline__ ull ffma2(ull a, ull b, ull c) {
    ull d;
    asm("fma.rn.f32x2 %0, %1, %2, %3;" : "=l"(d) : "l"(a), "l"(b), "l"(c));
    return d;
}
__device__ __forceinline__ ull addf32x2(ull a, ull b) {
    ull d;
    asm("add.rn.f32x2 %0, %1, %2;" : "=l"(d) : "l"(a), "l"(b));
    return d;
}
__device__ __forceinline__ void unpk(ull v, float& lo, float& hi) {
    asm("mov.b64 {%0, %1}, %2;" : "=f"(lo), "=f"(hi) : "l"(v));
}
__device__ __forceinline__ ull pkdup(float x) {
    ull d;
    asm("mov.b64 %0, {%1, %1};" : "=l"(d) : "f"(x));
    return d;
}

__global__ void __launch_bounds__(NTHREADS, 1)
rnncf_kernel(const float* __restrict__ lead, const float* __restrict__ cur,
             const float* __restrict__ w1g, const float* __restrict__ b1g,
             const float* __restrict__ w2g, const float* __restrict__ b2g,
             const float* __restrict__ wd2g, const float* __restrict__ bd2g,
             const float* __restrict__ wd1g, const float* __restrict__ bd1g,
             float* __restrict__ out)
{
    extern __shared__ float sm[];
    const int tid = threadIdx.x;

    // ---------- cooperative weight staging ----------
    for (int i = tid; i < 288; i += NTHREADS) sm[W1_OFF + i] = w1g[i];
    for (int i = tid; i < 32;  i += NTHREADS) sm[B1_OFF + i] = b1g[i];
    {
        float2* b2p_s = (float2*)(sm + B2P_OFF);
        for (int i = tid; i < 32; i += NTHREADS)
            b2p_s[i] = make_float2(b2g[i], b2g[i + 32]);
        float4* w2x_s = (float4*)(sm + W2X_OFF);
        for (int i = tid; i < 1024; i += NTHREADS) {
            int ci = i >> 5, c = i & 31;
            w2x_s[i] = make_float4(w2g[ci * 64 + c],        w2g[ci * 64 + c + 32],
                                   w2g[(32 + ci) * 64 + c], w2g[(32 + ci) * 64 + c + 32]);
        }
        float4* w2k2_s = (float4*)(sm + W2K2_OFF);
        for (int i = tid; i < 512; i += NTHREADS) {
            int cp = i >> 5, c = i & 31;
            w2k2_s[i] = make_float4(w2g[(64 + 2 * cp) * 64 + c],     w2g[(64 + 2 * cp) * 64 + c + 32],
                                    w2g[(64 + 2 * cp + 1) * 64 + c], w2g[(64 + 2 * cp + 1) * 64 + c + 32]);
        }
        float4* wdx_s = (float4*)(sm + WD2X_OFF);
        for (int i = tid; i < 960; i += NTHREADS) {
            int q = i / 192, r = i - q * 192;
            int jj = r >> 5, c = r & 31;
            int ii = jj * 64 + c;
            wdx_s[i] = make_float4(wd2g[ii * 10 + 2 * q],        wd2g[ii * 10 + 2 * q + 1],
                                   wd2g[(ii + 32) * 10 + 2 * q], wd2g[(ii + 32) * 10 + 2 * q + 1]);
        }
    }
    for (int i = tid; i < 10; i += NTHREADS) sm[BD2_OFF + i] = bd2g[i];
    for (int i = tid; i < 10; i += NTHREADS) sm[WD1_OFF + i] = wd1g[i];
    if (tid == 0) sm[BD1_OFF] = bd1g[0];
    for (int i = tid; i < 14 * 27 * 8; i += NTHREADS) sm[XBUF_OFF + i] = 0.0f;
    __syncthreads();

    const int wid = tid >> 5, lane = tid & 31;
    const int quad = blockIdx.x * WARPS_PER_CTA + wid;
    if (quad >= NQUAD) return;

    float* xbuf0 = sm + XBUF_OFF + (wid * 2 + 0) * (27 * 8);
    float* xbuf1 = sm + XBUF_OFF + (wid * 2 + 1) * (27 * 8);
    float2* pab0 = (float2*)(sm + PAB_OFF) + (wid * 2 + 0) * (13 * 32);
    float2* pab1 = (float2*)(sm + PAB_OFF) + (wid * 2 + 1) * (13 * 32);
    const ulonglong2* qv0 = (const ulonglong2*)pab0;
    const ulonglong2* qv1 = (const ulonglong2*)pab1;
    // circular odd-parity state (16 slots per array)
    ull* ScLo0 = (ull*)(sm + S_OFF) + (wid * 2 + 0) * (2 * 16 * 32);
    ull* ScHi0 = ScLo0 + 16 * 32;
    ull* ScLo1 = (ull*)(sm + S_OFF) + (wid * 2 + 1) * (2 * 16 * 32);
    ull* ScHi1 = ScLo1 + 16 * 32;
    const float4* w2xf   = (const float4*)(sm + W2X_OFF);
    const float4* w2k2f4 = (const float4*)(sm + W2K2_OFF);
    const ulonglong2* wdx = (const ulonglong2*)(sm + WD2X_OFF);

    const float2* lead2base = (const float2*)lead + (size_t)(4 * quad) * LEADLEN;
    float2*       out2base  = (float2*)out + (size_t)(4 * quad) * NT;

    // hoisted packed biases
    ull b1d, b2lo, b2hi;
    b1d = pkdup(sm[B1_OFF + lane]);
    {
        float2 b2v = ((const float2*)(sm + B2P_OFF))[lane];
        b2lo = pkdup(b2v.x);
        b2hi = pkdup(b2v.y);
    }

    // ---------- initial windows: lane i (<25) holds column i, packed {A,B} ----------
    float2 xw0[2], xw1[2], xw2[2];
    #pragma unroll
    for (int s = 0; s < 2; ++s) {
        xw0[s] = make_float2(0.f, 0.f);
        xw1[s] = make_float2(0.f, 0.f);
        xw2[s] = make_float2(0.f, 0.f);
    }
    float p24v[4], s24v[4];
    {
        float tp[4] = {0.f, 0.f, 0.f, 0.f}, ts[4] = {0.f, 0.f, 0.f, 0.f};
        if (lane < PAST) {
            const float2* cur2base = (const float2*)cur + (size_t)(4 * quad) * PAST;
            #pragma unroll
            for (int i = 0; i < 4; ++i) {
                float2 cs = cur2base[i * PAST + lane];
                float2 ld = lead2base[i * LEADLEN + lane];
                float X0 = (ld.x - cs.x) * (1.0f / 200.0f);
                float X1 = cs.y * (1.0f / 40.0f);
                float X2 = ld.y * (1.0f / 40.0f);
                int s = i >> 1;
                if ((i & 1) == 0) { xw0[s].x = X0; xw1[s].x = X1; xw2[s].x = X2; }
                else              { xw0[s].y = X0; xw1[s].y = X1; xw2[s].y = X2; }
                tp[i] = cs.x; ts[i] = cs.y;
            }
        }
        #pragma unroll
        for (int i = 0; i < 4; ++i) {
            p24v[i] = __shfl_sync(0xffffffffu, tp[i], 24);
            s24v[i] = __shfl_sync(0xffffffffu, ts[i], 24);
        }
    }
    float2 ldnv[4];
    #pragma unroll
    for (int i = 0; i < 4; ++i) ldnv[i] = make_float2(0.f, 0.f);

    // ---------- helpers ----------
    auto publish = [&]() {
        if (lane < PAST) {
            *(float4*)(xbuf0 + (lane + 1) * 8)     = make_float4(xw0[0].x, xw0[0].y, xw1[0].x, xw1[0].y);
            *(float2*)(xbuf0 + (lane + 1) * 8 + 4) = xw2[0];
            *(float4*)(xbuf1 + (lane + 1) * 8)     = make_float4(xw0[1].x, xw0[1].y, xw1[1].x, xw1[1].y);
            *(float2*)(xbuf1 + (lane + 1) * 8 + 4) = xw2[1];
        }
        __syncwarp();
    };

    // conv1 position with locally-loaded weights
    auto conv1_full = [&](const float* xb, float2* pd) {
        ull w1d[9];
        #pragma unroll
        for (int i = 0; i < 9; ++i) w1d[i] = pkdup(sm[W1_OFF + i * 32 + lane]);
        auto c1p = [&](ulonglong2 a01, ull a2, ulonglong2 b01, ull b2_,
                       ulonglong2 c01, ull c2) -> ull {
            ull h = b1d;
            h = ffma2(a01.x, w1d[0], h); h = ffma2(a01.y, w1d[1], h); h = ffma2(a2,  w1d[2], h);
            h = ffma2(b01.x, w1d[3], h); h = ffma2(b01.y, w1d[4], h); h = ffma2(b2_, w1d[5], h);
            h = ffma2(c01.x, w1d[6], h); h = ffma2(c01.y, w1d[7], h); h = ffma2(c2,  w1d[8], h);
            return h;
        };
        ulonglong2 a01 = *(const ulonglong2*)(xb);
        ull        a2  = *(const ull*)(xb + 4);
        ulonglong2 b01 = *(const ulonglong2*)(xb + 8);
        ull        b2_ = *(const ull*)(xb + 12);
        #pragma unroll
        for (int m = 0; m < 12; ++m) {
            ulonglong2 c01 = *(const ulonglong2*)(xb + (2 * m + 2) * 8);
            ull        c2  = *(const ull*)(xb + (2 * m + 2) * 8 + 4);
            ulonglong2 d01 = *(const ulonglong2*)(xb + (2 * m + 3) * 8);
            ull        d2  = *(const ull*)(xb + (2 * m + 3) * 8 + 4);
            ull h0 = c1p(a01, a2, b01, b2_, c01, c2);
            ull h1 = c1p(b01, b2_, c01, c2, d01, d2);
            float f0A, f0B, f1A, f1B;
            unpk(h0, f0A, f0B); unpk(h1, f1A, f1B);
            pd[m * 32 + lane] = make_float2(fmaxf(fmaxf(f0A, 0.f), fmaxf(f1A, 0.f)),
                                            fmaxf(fmaxf(f0B, 0.f), fmaxf(f1B, 0.f)));
            a01 = c01; a2 = c2; b01 = d01; b2_ = d2;
        }
        ulonglong2 c01 = *(const ulonglong2*)(xb + 26 * 8);
        ull        c2  = *(const ull*)(xb + 26 * 8 + 4);
        ull h0 = c1p(a01, a2, b01, b2_, c01, c2);
        float f0A, f0B;
        unpk(h0, f0A, f0B);
        pd[12 * 32 + lane] = make_float2(fmaxf(f0A, 0.f), fmaxf(f0B, 0.f));
    };

    auto conv1_inc = [&](const float* xb, float2* pd) {    // boundary slots 0..2, 9..12
        ull w1d[9];
        #pragma unroll
        for (int i = 0; i < 9; ++i) w1d[i] = pkdup(sm[W1_OFF + i * 32 + lane]);
        auto c1p = [&](ulonglong2 a01, ull a2, ulonglong2 b01, ull b2_,
                       ulonglong2 c01, ull c2) -> ull {
            ull h = b1d;
            h = ffma2(a01.x, w1d[0], h); h = ffma2(a01.y, w1d[1], h); h = ffma2(a2,  w1d[2], h);
            h = ffma2(b01.x, w1d[3], h); h = ffma2(b01.y, w1d[4], h); h = ffma2(b2_, w1d[5], h);
            h = ffma2(c01.x, w1d[6], h); h = ffma2(c01.y, w1d[7], h); h = ffma2(c2,  w1d[8], h);
            return h;
        };
        auto pool2w = [&](ull h0, ull h1) -> float2 {
            float f0A, f0B, f1A, f1B;
            unpk(h0, f0A, f0B); unpk(h1, f1A, f1B);
            return make_float2(fmaxf(fmaxf(f0A, 0.f), fmaxf(f1A, 0.f)),
                               fmaxf(fmaxf(f0B, 0.f), fmaxf(f1B, 0.f)));
        };
        {
            ulonglong2 a01 = *(const ulonglong2*)(xb);
            ull        a2  = *(const ull*)(xb + 4);
            ulonglong2 b01 = *(const ulonglong2*)(xb + 8);
            ull        b2_ = *(const ull*)(xb + 12);
            #pragma unroll
            for (int m = 0; m < 3; ++m) {
                ulonglong2 c01 = *(const ulonglong2*)(xb + (2 * m + 2) * 8);
                ull        c2  = *(const ull*)(xb + (2 * m + 2) * 8 + 4);
                ulonglong2 d01 = *(const ulonglong2*)(xb + (2 * m + 3) * 8);
                ull        d2  = *(const ull*)(xb + (2 * m + 3) * 8 + 4);
                ull h0 = c1p(a01, a2, b01, b2_, c01, c2);
                ull h1 = c1p(b01, b2_, c01, c2, d01, d2);
                pd[m * 32 + lane] = pool2w(h0, h1);
                a01 = c01; a2 = c2; b01 = d01; b2_ = d2;
            }
        }
        {
            ulonglong2 a01 = *(const ulonglong2*)(xb + 18 * 8);
            ull        a2  = *(const ull*)(xb + 18 * 8 + 4);
            ulonglong2 b01 = *(const ulonglong2*)(xb + 19 * 8);
            ull        b2_ = *(const ull*)(xb + 19 * 8 + 4);
            #pragma unroll
            for (int m = 9; m < 12; ++m) {
                ulonglong2 c01 = *(const ulonglong2*)(xb + (2 * m + 2) * 8);
                ull        c2  = *(const ull*)(xb + (2 * m + 2) * 8 + 4);
                ulonglong2 d01 = *(const ulonglong2*)(xb + (2 * m + 3) * 8);
                ull        d2  = *(const ull*)(xb + (2 * m + 3) * 8 + 4);
                ull h0 = c1p(a01, a2, b01, b2_, c01, c2);
                ull h1 = c1p(b01, b2_, c01, c2, d01, d2);
                pd[m * 32 + lane] = pool2w(h0, h1);
                a01 = c01; a2 = c2; b01 = d01; b2_ = d2;
            }
            ulonglong2 c01 = *(const ulonglong2*)(xb + 26 * 8);
            ull        c2  = *(const ull*)(xb + 26 * 8 + 4);
            ull h0 = c1p(a01, a2, b01, b2_, c01, c2);
            float f0A, f0B;
            unpk(h0, f0A, f0B);
            pd[12 * 32 + lane] = make_float2(fmaxf(f0A, 0.f), fmaxf(f0B, 0.f));
        }
    };

    // seeds: all 11 conv2 positions for one set
    auto conv2_full = [&](const ulonglong2* q, ull* Lo, ull* Hi) {
        #pragma unroll
        for (int j = 0; j < 11; ++j) { Lo[j] = b2lo; Hi[j] = b2hi; }
        #pragma unroll 1
        for (int cp = 0; cp < 16; ++cp) {
            float4 wa0 = w2xf[(2 * cp)     * 32 + lane];
            float4 wa1 = w2xf[(2 * cp + 1) * 32 + lane];
            float4 kk  = w2k2f4[cp * 32 + lane];
            ull d00 = pkdup(wa0.x), d01 = pkdup(wa0.y), d10 = pkdup(wa0.z), d11 = pkdup(wa0.w);
            ull e00 = pkdup(wa1.x), e01 = pkdup(wa1.y), e10 = pkdup(wa1.z), e11 = pkdup(wa1.w);
            ull d20 = pkdup(kk.x),  d21 = pkdup(kk.y),  e20 = pkdup(kk.z),  e21 = pkdup(kk.w);
            #pragma unroll
            for (int m = 0; m < 13; ++m) {
                ulonglong2 qp = q[m * 16 + cp];
                if (m <= 10) {
                    Lo[m] = ffma2(qp.x, d00, Lo[m]); Lo[m] = ffma2(qp.y, e00, Lo[m]);
                    Hi[m] = ffma2(qp.x, d01, Hi[m]); Hi[m] = ffma2(qp.y, e01, Hi[m]);
                }
                if (m >= 1 && m <= 11) {
                    Lo[m-1] = ffma2(qp.x, d10, Lo[m-1]); Lo[m-1] = ffma2(qp.y, e10, Lo[m-1]);
                    Hi[m-1] = ffma2(qp.x, d11, Hi[m-1]); Hi[m-1] = ffma2(qp.y, e11, Hi[m-1]);
                }
                if (m >= 2) {
                    Lo[m-2] = ffma2(qp.x, d20, Lo[m-2]); Lo[m-2] = ffma2(qp.y, e20, Lo[m-2]);
                    Hi[m-2] = ffma2(qp.x, d21, Hi[m-2]); Hi[m-2] = ffma2(qp.y, e21, Hi[m-2]);
                }
            }
        }
    };

    // incremental: fresh positions {0,9,10}, both sets, weights loaded once
    auto conv2_inc2 = [&](ull (&nlo)[2][3], ull (&nhi)[2][3]) {
        #pragma unroll
        for (int s = 0; s < 2; ++s) {
            nlo[s][0] = nlo[s][1] = nlo[s][2] = b2lo;
            nhi[s][0] = nhi[s][1] = nhi[s][2] = b2hi;
        }
        #pragma unroll 4
        for (int cp = 0; cp < 16; ++cp) {
            float4 wa0 = w2xf[(2 * cp)     * 32 + lane];
            float4 wa1 = w2xf[(2 * cp + 1) * 32 + lane];
            float4 kk  = w2k2f4[cp * 32 + lane];
            ull d00 = pkdup(wa0.x), d01 = pkdup(wa0.y), d10 = pkdup(wa0.z), d11 = pkdup(wa0.w);
            ull e00 = pkdup(wa1.x), e01 = pkdup(wa1.y), e10 = pkdup(wa1.z), e11 = pkdup(wa1.w);
            ull d20 = pkdup(kk.x),  d21 = pkdup(kk.y),  e20 = pkdup(kk.z),  e21 = pkdup(kk.w);
            #pragma unroll
            for (int s = 0; s < 2; ++s) {
                const ulonglong2* q = s ? qv1 : qv0;
                ulonglong2 q0 = q[0 * 16 + cp], q1 = q[1 * 16 + cp], q2 = q[2 * 16 + cp];
                nlo[s][0] = ffma2(q0.x, d00, nlo[s][0]); nlo[s][0] = ffma2(q0.y, e00, nlo[s][0]);
                nhi[s][0] = ffma2(q0.x, d01, nhi[s][0]); nhi[s][0] = ffma2(q0.y, e01, nhi[s][0]);
                nlo[s][0] = ffma2(q1.x, d10, nlo[s][0]); nlo[s][0] = ffma2(q1.y, e10, nlo[s][0]);
                nhi[s][0] = ffma2(q1.x, d11, nhi[s][0]); nhi[s][0] = ffma2(q1.y, e11, nhi[s][0]);
                nlo[s][0] = ffma2(q2.x, d20, nlo[s][0]); nlo[s][0] = ffma2(q2.y, e20, nlo[s][0]);
                nhi[s][0] = ffma2(q2.x, d21, nhi[s][0]); nhi[s][0] = ffma2(q2.y, e21, nhi[s][0]);

                ulonglong2 q9  = q[9 * 16 + cp],  q10 = q[10 * 16 + cp];
                ulonglong2 q11 = q[11 * 16 + cp], q12 = q[12 * 16 + cp];
                nlo[s][1] = ffma2(q9.x,  d00, nlo[s][1]); nlo[s][1] = ffma2(q9.y,  e00, nlo[s][1]);
                nhi[s][1] = ffma2(q9.x,  d01, nhi[s][1]); nhi[s][1] = ffma2(q9.y,  e01, nhi[s][1]);
                nlo[s][1] = ffma2(q10.x, d10, nlo[s][1]); nlo[s][1] = ffma2(q10.y, e10, nlo[s][1]);
                nhi[s][1] = ffma2(q10.x, d11, nhi[s][1]); nhi[s][1] = ffma2(q10.y, e11, nhi[s][1]);
                nlo[s][1] = ffma2(q11.x, d20, nlo[s][1]); nlo[s][1] = ffma2(q11.y, e20, nlo[s][1]);
                nhi[s][1] = ffma2(q11.x, d21, nhi[s][1]); nhi[s][1] = ffma2(q11.y, e21, nhi[s][1]);

                nlo[s][2] = ffma2(q10.x, d00, nlo[s][2]); nlo[s][2] = ffma2(q10.y, e00, nlo[s][2]);
                nhi[s][2] = ffma2(q10.x, d01, nhi[s][2]); nhi[s][2] = ffma2(q10.y, e01, nhi[s][2]);
                nlo[s][2] = ffma2(q11.x, d10, nlo[s][2]); nlo[s][2] = ffma2(q11.y, e10, nlo[s][2]);
                nhi[s][2] = ffma2(q11.x, d11, nhi[s][2]); nhi[s][2] = ffma2(q11.y, e11, nhi[s][2]);
                nlo[s][2] = ffma2(q12.x, d20, nlo[s][2]); nlo[s][2] = ffma2(q12.y, e20, nlo[s][2]);
                nhi[s][2] = ffma2(q12.x, d21, nhi[s][2]); nhi[s][2] = ffma2(q12.y, e21, nhi[s][2]);
            }
        }
    };

    // merged tail: pool2 + dense2 (shared weight loads) + 4-way parity reduce +
    // single dense1 + recurrence for all 4 vehicles
    auto tail4 = [&](auto&& gLo0, auto&& gHi0, auto&& gLo1, auto&& gHi1, int t) {
        ull sA0[5] = {0,0,0,0,0}, sB0[5] = {0,0,0,0,0};
        ull sA1[5] = {0,0,0,0,0}, sB1[5] = {0,0,0,0,0};
        #pragma unroll
        for (int jj = 0; jj < 6; ++jj) {
            ull fapA0, fbpA0, fapB0, fbpB0, fapA1, fbpA1, fapB1, fbpB1;
            float aA, aB, bA, bB;
            if (jj < 5) {
                unpk(gLo0(2 * jj), aA, aB); unpk(gLo0(2 * jj + 1), bA, bB);
                fapA0 = pkdup(fmaxf(fmaxf(aA, 0.f), fmaxf(bA, 0.f)));
                fapB0 = pkdup(fmaxf(fmaxf(aB, 0.f), fmaxf(bB, 0.f)));
                unpk(gHi0(2 * jj), aA, aB); unpk(gHi0(2 * jj + 1), bA, bB);
                fbpA0 = pkdup(fmaxf(fmaxf(aA, 0.f), fmaxf(bA, 0.f)));
                fbpB0 = pkdup(fmaxf(fmaxf(aB, 0.f), fmaxf(bB, 0.f)));
                unpk(gLo1(2 * jj), aA, aB); unpk(gLo1(2 * jj + 1), bA, bB);
                fapA1 = pkdup(fmaxf(fmaxf(aA, 0.f), fmaxf(bA, 0.f)));
                fapB1 = pkdup(fmaxf(fmaxf(aB, 0.f), fmaxf(bB, 0.f)));
                unpk(gHi1(2 * jj), aA, aB); unpk(gHi1(2 * jj + 1), bA, bB);
                fbpA1 = pkdup(fmaxf(fmaxf(aA, 0.f), fmaxf(bA, 0.f)));
                fbpB1 = pkdup(fmaxf(fmaxf(aB, 0.f), fmaxf(bB, 0.f)));
            } else {
                unpk(gLo0(10), aA, aB);
                fapA0 = pkdup(fmaxf(aA, 0.f)); fapB0 = pkdup(fmaxf(aB, 0.f));
                unpk(gHi0(10), aA, aB);
                fbpA0 = pkdup(fmaxf(aA, 0.f)); fbpB0 = pkdup(fmaxf(aB, 0.f));
                unpk(gLo1(10), aA, aB);
                fapA1 = pkdup(fmaxf(aA, 0.f)); fapB1 = pkdup(fmaxf(aB, 0.f));
                unpk(gHi1(10), aA, aB);
                fbpA1 = pkdup(fmaxf(aA, 0.f)); fbpB1 = pkdup(fmaxf(aB, 0.f));
            }
            #pragma unroll
            for (int q = 0; q < 5; ++q) {
                ulonglong2 w = wdx[(q * 6 + jj) * 32 + lane];   // one load, 4 vehicles
                sA0[q] = ffma2(fapA0, w.x, sA0[q]); sA0[q] = ffma2(fbpA0, w.y, sA0[q]);
                sB0[q] = ffma2(fapB0, w.x, sB0[q]); sB0[q] = ffma2(fbpB0, w.y, sB0[q]);
                sA1[q] = ffma2(fapA1, w.x, sA1[q]); sA1[q] = ffma2(fbpA1, w.y, sA1[q]);
                sB1[q] = ffma2(fapB1, w.x, sB1[q]); sB1[q] = ffma2(fbpB1, w.y, sB1[q]);
            }
        }
        // 4-way parity-merged reduction: lane bit0 -> A/B, bit1 -> set
        const bool bit0 = (lane & 1), bit1 = (lane & 2);
        ull r0[5], r1[5], s5[5];
        #pragma unroll
        for (int q = 0; q < 5; ++q) {
            ull z = bit0 ? sB0[q] : sA0[q];
            ull x = bit0 ? sA0[q] : sB0[q];
            r0[q] = addf32x2(z, __shfl_xor_sync(0xffffffffu, x, 1));
            z = bit0 ? sB1[q] : sA1[q];
            x = bit0 ? sA1[q] : sB1[q];
            r1[q] = addf32x2(z, __shfl_xor_sync(0xffffffffu, x, 1));
        }
        #pragma unroll
        for (int q = 0; q < 5; ++q) {
            ull z = bit1 ? r1[q] : r0[q];
            ull x = bit1 ? r0[q] : r1[q];
            s5[q] = addf32x2(z, __shfl_xor_sync(0xffffffffu, x, 2));
        }
        #pragma unroll
        for (int off = 4; off <= 16; off <<= 1) {
            #pragma unroll
            for (int q = 0; q < 5; ++q)
                s5[q] = addf32x2(s5[q], __shfl_xor_sync(0xffffffffu, s5[q], off));
        }
        // dense1 once (lane L carries vehicle L&3)
        float d[10];
        #pragma unroll
        for (int q = 0; q < 5; ++q) unpk(s5[q], d[2 * q], d[2 * q + 1]);
        float y = sm[BD1_OFF];
        #pragma unroll
        for (int o = 0; o < 10; ++o)
            y = fmaf(fmaxf(d[o] + sm[BD2_OFF + o], 0.0f), sm[WD1_OFF + o], y);
        float accv = fmaf(10.0f, y, -6.0f);
        float av[4];
        #pragma unroll
        for (int i = 0; i < 4; ++i) av[i] = __shfl_sync(0xffffffffu, accv, i);

        float pp[4], ps[4];
        #pragma unroll
        for (int i = 0; i < 4; ++i) {
            pp[i] = fmaf(0.1f, s24v[i], p24v[i]);
            ps[i] = fmaf(0.1f, av[i],   s24v[i]);
            p24v[i] = pp[i]; s24v[i] = ps[i];
        }
        if (lane < 4) out2base[lane * NT + t] = make_float2(pp[lane], ps[lane]);

        #pragma unroll
        for (int s = 0; s < 2; ++s) {
            xw0[s].x = __shfl_down_sync(0xffffffffu, xw0[s].x, 1);
            xw0[s].y = __shfl_down_sync(0xffffffffu, xw0[s].y, 1);
            xw1[s].x = __shfl_down_sync(0xffffffffu, xw1[s].x, 1);
            xw1[s].y = __shfl_down_sync(0xffffffffu, xw1[s].y, 1);
            xw2[s].x = __shfl_down_sync(0xffffffffu, xw2[s].x, 1);
            xw2[s].y = __shfl_down_sync(0xffffffffu, xw2[s].y, 1);
            if (lane == 24) {
                int iA = 2 * s, iB = 2 * s + 1;
                xw0[s] = make_float2((ldnv[iA].x - pp[iA]) * (1.0f / 200.0f),
                                     (ldnv[iB].x - pp[iB]) * (1.0f / 200.0f));
                xw1[s] = make_float2(ps[iA] * (1.0f / 40.0f), ps[iB] * (1.0f / 40.0f));
                xw2[s] = make_float2(ldnv[iA].y * (1.0f / 40.0f), ldnv[iB].y * (1.0f / 40.0f));
            }
        }
    };

    // ---------- seed steps (full compute) ----------
    ull Rlo0[11], Rhi0[11], Rlo1[11], Rhi1[11];   // even-parity state (registers)
    if (lane == 24) {
        #pragma unroll
        for (int i = 0; i < 4; ++i) ldnv[i] = lead2base[i * LEADLEN + 0 + PAST];
    }
    publish();
    conv1_full(xbuf0, pab0); conv1_full(xbuf1, pab1);
    __syncwarp();
    conv2_full(qv0, Rlo0, Rhi0);
    conv2_full(qv1, Rlo1, Rhi1);
    tail4([&](int j){ return Rlo0[j]; }, [&](int j){ return Rhi0[j]; },
          [&](int j){ return Rlo1[j]; }, [&](int j){ return Rhi1[j]; }, 0);

    int baseO = 0;
    {
        if (lane == 24) {
            #pragma unroll
            for (int i = 0; i < 4; ++i) ldnv[i] = lead2base[i * LEADLEN + 1 + PAST];
        }
        publish();
        conv1_full(xbuf0, pab0); conv1_full(xbuf1, pab1);
        __syncwarp();
        ull Tlo[11], Thi[11];
        conv2_full(qv0, Tlo, Thi);
        #pragma unroll
        for (int j = 0; j < 11; ++j) { ScLo0[j * 32 + lane] = Tlo[j]; ScHi0[j * 32 + lane] = Thi[j]; }
        conv2_full(qv1, Tlo, Thi);
        #pragma unroll
        for (int j = 0; j < 11; ++j) { ScLo1[j * 32 + lane] = Tlo[j]; ScHi1[j * 32 + lane] = Thi[j]; }
        tail4([&](int j){ return ScLo0[((baseO + j) & 15) * 32 + lane]; },
              [&](int j){ return ScHi0[((baseO + j) & 15) * 32 + lane]; },
              [&](int j){ return ScLo1[((baseO + j) & 15) * 32 + lane]; },
              [&](int j){ return ScHi1[((baseO + j) & 15) * 32 + lane]; }, 1);
    }

    // ---------- main incremental loop ----------
    #pragma unroll 1
    for (int t = 2; t < NT; t += 2) {
        // even step t : register state
        if (lane == 24) {
            #pragma unroll
            for (int i = 0; i < 4; ++i) ldnv[i] = lead2base[i * LEADLEN + t + PAST];
        }
        publish();
        conv1_inc(xbuf0, pab0); conv1_inc(xbuf1, pab1);
        __syncwarp();
        {
            ull nlo[2][3], nhi[2][3];
            conv2_inc2(nlo, nhi);
            Rlo0[0] = nlo[0][0]; Rhi0[0] = nhi[0][0];
            Rlo1[0] = nlo[1][0]; Rhi1[0] = nhi[1][0];
            #pragma unroll
            for (int j = 1; j <= 8; ++j) {
                Rlo0[j] = Rlo0[j + 1]; Rhi0[j] = Rhi0[j + 1];
                Rlo1[j] = Rlo1[j + 1]; Rhi1[j] = Rhi1[j + 1];
            }
            Rlo0[9] = nlo[0][1]; Rlo0[10] = nlo[0][2];
            Rhi0[9] = nhi[0][1]; Rhi0[10] = nhi[0][2];
            Rlo1[9] = nlo[1][1]; Rlo1[10] = nlo[1][2];
            Rhi1[9] = nhi[1][1]; Rhi1[10] = nhi[1][2];
        }
        tail4([&](int j){ return Rlo0[j]; }, [&](int j){ return Rhi0[j]; },
              [&](int j){ return Rlo1[j]; }, [&](int j){ return Rhi1[j]; }, t);

        // odd step t+1 : circular smem state (base advance replaces the shift)
        #pragma unroll
        for (int i = 0; i < 4; ++i) ldnv[i] = make_float2(0.f, 0.f);
        if (lane == 24 && (t + 1) < NT - 1) {
            #pragma unroll
            for (int i = 0; i < 4; ++i) ldnv[i] = lead2base[i * LEADLEN + t + 1 + PAST];
        }
        publish();
        conv1_inc(xbuf0, pab0); conv1_inc(xbuf1, pab1);
        __syncwarp();
        {
            ull mlo[2][3], mhi[2][3];
            conv2_inc2(mlo, mhi);
            baseO = (baseO + 1) & 15;
            int i0 = ((baseO + 0) & 15) * 32 + lane;
            int i9 = ((baseO + 9) & 15) * 32 + lane;
            int iX = ((baseO + 10) & 15) * 32 + lane;
            ScLo0[i0] = mlo[0][0]; ScLo0[i9] = mlo[0][1]; ScLo0[iX] = mlo[0][2];
            ScHi0[i0] = mhi[0][0]; ScHi0[i9] = mhi[0][1]; ScHi0[iX] = mhi[0][2];
            ScLo1[i0] = mlo[1][0]; ScLo1[i9] = mlo[1][1]; ScLo1[iX] = mlo[1][2];
            ScHi1[i0] = mhi[1][0]; ScHi1[i9] = mhi[1][1]; ScHi1[iX] = mhi[1][2];
        }
        tail4([&](int j){ return ScLo0[((baseO + j) & 15) * 32 + lane]; },
              [&](int j){ return ScHi0[((baseO + j) & 15) * 32 + lane]; },
              [&](int j){ return ScLo1[((baseO + j) & 15) * 32 + lane]; },
              [&](int j){ return ScHi1[((baseO + j) & 15) * 32 + lane]; }, t + 1);
    }
}

extern "C" void kernel_launch(void* const* d_in, const int* in_sizes, int n_in,
                              void* d_out, int out_size)
{
    const float* lead = (const float*)d_in[0];   // (4096, 280, 2)
    const float* cur  = (const float*)d_in[1];   // (4096, 25, 2)
    // d_in[2] = mask (unused by the reference computation)
    const float* w1  = (const float*)d_in[3];
    const float* b1  = (const float*)d_in[4];
    const float* w2  = (const float*)d_in[5];
    const float* b2  = (const float*)d_in[6];
    const float* wd2 = (const float*)d_in[7];
    const float* bd2 = (const float*)d_in[8];
    const float* wd1 = (const float*)d_in[9];
    const float* bd1 = (const float*)d_in[10];
    float* out = (float*)d_out;                   // (4096, 256, 2)

    (void)in_sizes; (void)n_in; (void)out_size;

    size_t smem_bytes = (size_t)SMEM_FLOATS * sizeof(float);   // 214944 B
    cudaFuncSetAttribute(rnncf_kernel,
                         cudaFuncAttributeMaxDynamicSharedMemorySize,
                         (int)smem_bytes);
    rnncf_kernel<<<NCTA, NTHREADS, smem_bytes>>>(
        lead, cur, w1, b1, w2, b2, wd2, bd2, wd1, bd1, out);
}

// round 12
// speedup vs baseline: 3.7730x; 1.1259x over previous
#include <cuda_runtime.h>

#define NVEH 4096
#define NT 256
#define PAST 25
#define LEADLEN (NT + PAST - 1)   // 280
#define NQUAD (NVEH / 4)          // 1024
#define WARPS_PER_CTA 7
#define NCTA ((NQUAD + WARPS_PER_CTA - 1) / WARPS_PER_CTA)   // 147
#define NTHREADS (WARPS_PER_CTA * 32)                         // 224

typedef unsigned long long ull;

// ---- shared memory layout (float offsets) ----
#define W1_OFF    0        // 288  : conv1_w [3][3][32]
#define B1_OFF    288      // 32
#define B2P_OFF   320      // 64   : float2 {b2[c], b2[c+32]}
#define W2X_OFF   384      // 4096 : float4 [ci*32+c] = {w0[c], w0[c+32], w1[c], w1[c+32]}
#define W2K2_OFF  4480     // 2048 : float4 [cp*32+c] = {k2[2cp][c], k2[2cp][c+32], k2[2cp+1][c], k2[2cp+1][c+32]}
#define WD2X_OFF  6528     // 3840 : ull2 [(q*6+jj)*32+c] = {pair_i, pair_{i+32}}
#define BD2_OFF   10368    // 10
#define WD1_OFF   10378    // 10
#define BD1_OFF   10388    // 1 (+3 pad)
#define XBUF_OFF  10392    // 14 sets * 27 pos * 8 floats
#define PQ_OFF    13416    // pool1 circular: 14 sets * 2 parities * 13 slots * 32 * float2
#define SC_OFF    (PQ_OFF + 14 * 2 * 13 * 32 * 2)   // 36712 : conv2 odd state, 14 sets * 2 arr * 11 slots * 32 ull
#define SMEM_FLOATS (SC_OFF + 14 * 2 * 11 * 32 * 2) // 56424 floats = 225696 B

__device__ __forceinline__ ull ffma2(ull a, ull b, ull c) {
    ull d;
    asm("fma.rn.f32x2 %0, %1, %2, %3;" : "=l"(d) : "l"(a), "l"(b), "l"(c));
    return d;
}
__device__ __forceinline__ ull addf32x2(ull a, ull b) {
    ull d;
    asm("add.rn.f32x2 %0, %1, %2;" : "=l"(d) : "l"(a), "l"(b));
    return d;
}
__device__ __forceinline__ void unpk(ull v, float& lo, float& hi) {
    asm("mov.b64 {%0, %1}, %2;" : "=f"(lo), "=f"(hi) : "l"(v));
}
__device__ __forceinline__ ull pkdup(float x) {
    ull d;
    asm("mov.b64 %0, {%1, %1};" : "=l"(d) : "f"(x));
    return d;
}
__device__ __forceinline__ int wrap13(int x) { return x >= 13 ? x - 13 : x; }
__device__ __forceinline__ int wrap11(int x) { return x >= 11 ? x - 11 : x; }

__global__ void __launch_bounds__(NTHREADS, 1)
rnncf_kernel(const float* __restrict__ lead, const float* __restrict__ cur,
             const float* __restrict__ w1g, const float* __restrict__ b1g,
             const float* __restrict__ w2g, const float* __restrict__ b2g,
             const float* __restrict__ wd2g, const float* __restrict__ bd2g,
             const float* __restrict__ wd1g, const float* __restrict__ bd1g,
             float* __restrict__ out)
{
    extern __shared__ float sm[];
    const int tid = threadIdx.x;

    // ---------- cooperative weight staging ----------
    for (int i = tid; i < 288; i += NTHREADS) sm[W1_OFF + i] = w1g[i];
    for (int i = tid; i < 32;  i += NTHREADS) sm[B1_OFF + i] = b1g[i];
    {
        float2* b2p_s = (float2*)(sm + B2P_OFF);
        for (int i = tid; i < 32; i += NTHREADS)
            b2p_s[i] = make_float2(b2g[i], b2g[i + 32]);
        float4* w2x_s = (float4*)(sm + W2X_OFF);
        for (int i = tid; i < 1024; i += NTHREADS) {
            int ci = i >> 5, c = i & 31;
            w2x_s[i] = make_float4(w2g[ci * 64 + c],        w2g[ci * 64 + c + 32],
                                   w2g[(32 + ci) * 64 + c], w2g[(32 + ci) * 64 + c + 32]);
        }
        float4* w2k2_s = (float4*)(sm + W2K2_OFF);
        for (int i = tid; i < 512; i += NTHREADS) {
            int cp = i >> 5, c = i & 31;
            w2k2_s[i] = make_float4(w2g[(64 + 2 * cp) * 64 + c],     w2g[(64 + 2 * cp) * 64 + c + 32],
                                    w2g[(64 + 2 * cp + 1) * 64 + c], w2g[(64 + 2 * cp + 1) * 64 + c + 32]);
        }
        float4* wdx_s = (float4*)(sm + WD2X_OFF);
        for (int i = tid; i < 960; i += NTHREADS) {
            int q = i / 192, r = i - q * 192;
            int jj = r >> 5, c = r & 31;
            int ii = jj * 64 + c;
            wdx_s[i] = make_float4(wd2g[ii * 10 + 2 * q],        wd2g[ii * 10 + 2 * q + 1],
                                   wd2g[(ii + 32) * 10 + 2 * q], wd2g[(ii + 32) * 10 + 2 * q + 1]);
        }
    }
    for (int i = tid; i < 10; i += NTHREADS) sm[BD2_OFF + i] = bd2g[i];
    for (int i = tid; i < 10; i += NTHREADS) sm[WD1_OFF + i] = wd1g[i];
    if (tid == 0) sm[BD1_OFF] = bd1g[0];
    // zero xbuf: borders (pos 0 and 26) must stay zero (pad columns)
    for (int i = tid; i < 14 * 27 * 8; i += NTHREADS) sm[XBUF_OFF + i] = 0.0f;
    __syncthreads();

    const int wid = tid >> 5, lane = tid & 31;
    const int quad = blockIdx.x * WARPS_PER_CTA + wid;
    if (quad >= NQUAD) return;

    float* xbuf0 = sm + XBUF_OFF + (wid * 2 + 0) * (27 * 8);
    float* xbuf1 = sm + XBUF_OFF + (wid * 2 + 1) * (27 * 8);
    // pool1 circular buffers: [set][parity]
    float2* pqE0 = (float2*)(sm + PQ_OFF) + ((wid * 2 + 0) * 2 + 0) * (13 * 32);
    float2* pqO0 = (float2*)(sm + PQ_OFF) + ((wid * 2 + 0) * 2 + 1) * (13 * 32);
    float2* pqE1 = (float2*)(sm + PQ_OFF) + ((wid * 2 + 1) * 2 + 0) * (13 * 32);
    float2* pqO1 = (float2*)(sm + PQ_OFF) + ((wid * 2 + 1) * 2 + 1) * (13 * 32);
    const ulonglong2* qE0 = (const ulonglong2*)pqE0;
    const ulonglong2* qO0 = (const ulonglong2*)pqO0;
    const ulonglong2* qE1 = (const ulonglong2*)pqE1;
    const ulonglong2* qO1 = (const ulonglong2*)pqO1;
    // conv2 odd-parity circular state (11 slots)
    ull* ScLo0 = (ull*)(sm + SC_OFF) + (wid * 2 + 0) * (2 * 11 * 32);
    ull* ScHi0 = ScLo0 + 11 * 32;
    ull* ScLo1 = (ull*)(sm + SC_OFF) + (wid * 2 + 1) * (2 * 11 * 32);
    ull* ScHi1 = ScLo1 + 11 * 32;
    const float4* w2xf   = (const float4*)(sm + W2X_OFF);
    const float4* w2k2f4 = (const float4*)(sm + W2K2_OFF);
    const ulonglong2* wdx = (const ulonglong2*)(sm + WD2X_OFF);

    const float2* lead2base = (const float2*)lead + (size_t)(4 * quad) * LEADLEN;
    float2*       out2base  = (float2*)out + (size_t)(4 * quad) * NT;

    // hoisted packed constants
    ull w1d[9];
    #pragma unroll
    for (int i = 0; i < 9; ++i) w1d[i] = pkdup(sm[W1_OFF + i * 32 + lane]);
    const ull b1d = pkdup(sm[B1_OFF + lane]);
    ull b2lo, b2hi;
    {
        float2 b2v = ((const float2*)(sm + B2P_OFF))[lane];
        b2lo = pkdup(b2v.x);
        b2hi = pkdup(b2v.y);
    }

    // ---------- initial windows: lane i (<25) holds column i, packed {A,B} ----------
    float2 xw0[2], xw1[2], xw2[2];
    #pragma unroll
    for (int s = 0; s < 2; ++s) {
        xw0[s] = make_float2(0.f, 0.f);
        xw1[s] = make_float2(0.f, 0.f);
        xw2[s] = make_float2(0.f, 0.f);
    }
    float p24v[4], s24v[4];
    {
        float tp[4] = {0.f, 0.f, 0.f, 0.f}, ts[4] = {0.f, 0.f, 0.f, 0.f};
        if (lane < PAST) {
            const float2* cur2base = (const float2*)cur + (size_t)(4 * quad) * PAST;
            #pragma unroll
            for (int i = 0; i < 4; ++i) {
                float2 cs = cur2base[i * PAST + lane];
                float2 ld = lead2base[i * LEADLEN + lane];
                float X0 = (ld.x - cs.x) * (1.0f / 200.0f);
                float X1 = cs.y * (1.0f / 40.0f);
                float X2 = ld.y * (1.0f / 40.0f);
                int s = i >> 1;
                if ((i & 1) == 0) { xw0[s].x = X0; xw1[s].x = X1; xw2[s].x = X2; }
                else              { xw0[s].y = X0; xw1[s].y = X1; xw2[s].y = X2; }
                tp[i] = cs.x; ts[i] = cs.y;
            }
        }
        #pragma unroll
        for (int i = 0; i < 4; ++i) {
            p24v[i] = __shfl_sync(0xffffffffu, tp[i], 24);
            s24v[i] = __shfl_sync(0xffffffffu, ts[i], 24);
        }
    }
    float2 ldnv[4];
    #pragma unroll
    for (int i = 0; i < 4; ++i) ldnv[i] = make_float2(0.f, 0.f);

    // circular bases
    int bPe = 0, bPo = 0, bS = 0;
    int so7[7];      // pool1 read offsets (ulonglong2 units) for conv2_inc
    int sidx[11];    // conv2 odd-state read offsets (ull elements incl lane)

    // ---------- helpers ----------
    auto publish_full = [&]() {
        if (lane < PAST) {
            *(float4*)(xbuf0 + (lane + 1) * 8)     = make_float4(xw0[0].x, xw0[0].y, xw1[0].x, xw1[0].y);
            *(float2*)(xbuf0 + (lane + 1) * 8 + 4) = xw2[0];
            *(float4*)(xbuf1 + (lane + 1) * 8)     = make_float4(xw0[1].x, xw0[1].y, xw1[1].x, xw1[1].y);
            *(float2*)(xbuf1 + (lane + 1) * 8 + 4) = xw2[1];
        }
        __syncwarp();
    };
    auto publish_part = [&]() {   // only cols needed by fresh conv positions
        bool w = (lane < 3) || (lane >= 21 && lane < 25);
        if (w) {
            *(float4*)(xbuf0 + (lane + 1) * 8)     = make_float4(xw0[0].x, xw0[0].y, xw1[0].x, xw1[0].y);
            *(float2*)(xbuf0 + (lane + 1) * 8 + 4) = xw2[0];
            *(float4*)(xbuf1 + (lane + 1) * 8)     = make_float4(xw0[1].x, xw0[1].y, xw1[1].x, xw1[1].y);
            *(float2*)(xbuf1 + (lane + 1) * 8 + 4) = xw2[1];
        }
        __syncwarp();
    };

    auto c1p3 = [&](ulonglong2 a01, ull a2, ulonglong2 b01, ull b2_, ulonglong2 c01, ull c2) -> ull {
        ull h = b1d;
        h = ffma2(a01.x, w1d[0], h); h = ffma2(a01.y, w1d[1], h); h = ffma2(a2,  w1d[2], h);
        h = ffma2(b01.x, w1d[3], h); h = ffma2(b01.y, w1d[4], h); h = ffma2(b2_, w1d[5], h);
        h = ffma2(c01.x, w1d[6], h); h = ffma2(c01.y, w1d[7], h); h = ffma2(c2,  w1d[8], h);
        return h;
    };
    auto poolpair = [&](ull h0, ull h1) -> float2 {
        float f0A, f0B, f1A, f1B;
        unpk(h0, f0A, f0B); unpk(h1, f1A, f1B);
        return make_float2(fmaxf(fmaxf(f0A, 0.f), fmaxf(f1A, 0.f)),
                           fmaxf(fmaxf(f0B, 0.f), fmaxf(f1B, 0.f)));
    };
    auto poolone = [&](ull h0) -> float2 {
        float f0A, f0B;
        unpk(h0, f0A, f0B);
        return make_float2(fmaxf(f0A, 0.f), fmaxf(f0B, 0.f));
    };

    auto conv1_full = [&](const float* xb, float2* pd) {   // seeds: all 13 slots at base 0
        ulonglong2 a01 = *(const ulonglong2*)(xb);
        ull        a2  = *(const ull*)(xb + 4);
        ulonglong2 b01 = *(const ulonglong2*)(xb + 8);
        ull        b2_ = *(const ull*)(xb + 12);
        #pragma unroll
        for (int m = 0; m < 12; ++m) {
            ulonglong2 c01 = *(const ulonglong2*)(xb + (2 * m + 2) * 8);
            ull        c2  = *(const ull*)(xb + (2 * m + 2) * 8 + 4);
            ulonglong2 d01 = *(const ulonglong2*)(xb + (2 * m + 3) * 8);
            ull        d2  = *(const ull*)(xb + (2 * m + 3) * 8 + 4);
            ull h0 = c1p3(a01, a2, b01, b2_, c01, c2);
            ull h1 = c1p3(b01, b2_, c01, c2, d01, d2);
            pd[m * 32 + lane] = poolpair(h0, h1);
            a01 = c01; a2 = c2; b01 = d01; b2_ = d2;
        }
        ulonglong2 c01 = *(const ulonglong2*)(xb + 26 * 8);
        ull        c2  = *(const ull*)(xb + 26 * 8 + 4);
        pd[12 * 32 + lane] = poolone(c1p3(a01, a2, b01, b2_, c01, c2));
    };

    // steady-state conv1: only fresh conv positions {0,1,22,23,24} (pad taps skipped exactly)
    auto conv1_fresh = [&](const float* xb, float2* pd, int w0i, int w11i, int w12i) {
        ulonglong2 u1 = *(const ulonglong2*)(xb + 1 * 8);  ull v1 = *(const ull*)(xb + 1 * 8 + 4);   // col0
        ulonglong2 u2 = *(const ulonglong2*)(xb + 2 * 8);  ull v2 = *(const ull*)(xb + 2 * 8 + 4);   // col1
        ulonglong2 u3 = *(const ulonglong2*)(xb + 3 * 8);  ull v3 = *(const ull*)(xb + 3 * 8 + 4);   // col2
        ull h0 = b1d;   // conv pos 0: pad, c0, c1
        h0 = ffma2(u1.x, w1d[3], h0); h0 = ffma2(u1.y, w1d[4], h0); h0 = ffma2(v1, w1d[5], h0);
        h0 = ffma2(u2.x, w1d[6], h0); h0 = ffma2(u2.y, w1d[7], h0); h0 = ffma2(v2, w1d[8], h0);
        ull h1 = c1p3(u1, v1, u2, v2, u3, v3);   // conv pos 1
        pd[w0i * 32 + lane] = poolpair(h0, h1);

        ulonglong2 u22 = *(const ulonglong2*)(xb + 22 * 8); ull v22 = *(const ull*)(xb + 22 * 8 + 4); // col21
        ulonglong2 u23 = *(const ulonglong2*)(xb + 23 * 8); ull v23 = *(const ull*)(xb + 23 * 8 + 4); // col22
        ulonglong2 u24 = *(const ulonglong2*)(xb + 24 * 8); ull v24 = *(const ull*)(xb + 24 * 8 + 4); // col23
        ulonglong2 u25 = *(const ulonglong2*)(xb + 25 * 8); ull v25 = *(const ull*)(xb + 25 * 8 + 4); // col24
        ull g0 = c1p3(u22, v22, u23, v23, u24, v24);   // conv 22
        ull g1 = c1p3(u23, v23, u24, v24, u25, v25);   // conv 23
        ull g2 = b1d;   // conv 24: c23, c24, pad
        g2 = ffma2(u24.x, w1d[0], g2); g2 = ffma2(u24.y, w1d[1], g2); g2 = ffma2(v24, w1d[2], g2);
        g2 = ffma2(u25.x, w1d[3], g2); g2 = ffma2(u25.y, w1d[4], g2); g2 = ffma2(v25, w1d[5], g2);
        pd[w11i * 32 + lane] = poolpair(g0, g1);
        pd[w12i * 32 + lane] = poolone(g2);
    };

    // seeds: all 11 conv2 positions for one set (buffer at base 0)
    auto conv2_full = [&](const ulonglong2* q, ull* Lo, ull* Hi) {
        #pragma unroll
        for (int j = 0; j < 11; ++j) { Lo[j] = b2lo; Hi[j] = b2hi; }
        #pragma unroll 1
        for (int cp = 0; cp < 16; ++cp) {
            float4 wa0 = w2xf[(2 * cp)     * 32 + lane];
            float4 wa1 = w2xf[(2 * cp + 1) * 32 + lane];
            float4 kk  = w2k2f4[cp * 32 + lane];
            ull d00 = pkdup(wa0.x), d01 = pkdup(wa0.y), d10 = pkdup(wa0.z), d11 = pkdup(wa0.w);
            ull e00 = pkdup(wa1.x), e01 = pkdup(wa1.y), e10 = pkdup(wa1.z), e11 = pkdup(wa1.w);
            ull d20 = pkdup(kk.x),  d21 = pkdup(kk.y),  e20 = pkdup(kk.z),  e21 = pkdup(kk.w);
            #pragma unroll
            for (int m = 0; m < 13; ++m) {
                ulonglong2 qp = q[m * 16 + cp];
                if (m <= 10) {
                    Lo[m] = ffma2(qp.x, d00, Lo[m]); Lo[m] = ffma2(qp.y, e00, Lo[m]);
                    Hi[m] = ffma2(qp.x, d01, Hi[m]); Hi[m] = ffma2(qp.y, e01, Hi[m]);
                }
                if (m >= 1 && m <= 11) {
                    Lo[m-1] = ffma2(qp.x, d10, Lo[m-1]); Lo[m-1] = ffma2(qp.y, e10, Lo[m-1]);
                    Hi[m-1] = ffma2(qp.x, d11, Hi[m-1]); Hi[m-1] = ffma2(qp.y, e11, Hi[m-1]);
                }
                if (m >= 2) {
                    Lo[m-2] = ffma2(qp.x, d20, Lo[m-2]); Lo[m-2] = ffma2(qp.y, e20, Lo[m-2]);
                    Hi[m-2] = ffma2(qp.x, d21, Hi[m-2]); Hi[m-2] = ffma2(qp.y, e21, Hi[m-2]);
                }
            }
        }
    };

    // incremental: fresh conv2 positions {0,9,10}, both sets, reads via hoisted so7
    auto conv2_inc2 = [&](const ulonglong2* qs0, const ulonglong2* qs1,
                          ull (&nlo)[2][3], ull (&nhi)[2][3]) {
        #pragma unroll
        for (int s = 0; s < 2; ++s) {
            nlo[s][0] = nlo[s][1] = nlo[s][2] = b2lo;
            nhi[s][0] = nhi[s][1] = nhi[s][2] = b2hi;
        }
        #pragma unroll 4
        for (int cp = 0; cp < 16; ++cp) {
            float4 wa0 = w2xf[(2 * cp)     * 32 + lane];
            float4 wa1 = w2xf[(2 * cp + 1) * 32 + lane];
            float4 kk  = w2k2f4[cp * 32 + lane];
            ull d00 = pkdup(wa0.x), d01 = pkdup(wa0.y), d10 = pkdup(wa0.z), d11 = pkdup(wa0.w);
            ull e00 = pkdup(wa1.x), e01 = pkdup(wa1.y), e10 = pkdup(wa1.z), e11 = pkdup(wa1.w);
            ull d20 = pkdup(kk.x),  d21 = pkdup(kk.y),  e20 = pkdup(kk.z),  e21 = pkdup(kk.w);
            #pragma unroll
            for (int s = 0; s < 2; ++s) {
                const ulonglong2* q = s ? qs1 : qs0;
                ulonglong2 q0 = q[so7[0] + cp], q1 = q[so7[1] + cp], q2 = q[so7[2] + cp];
                nlo[s][0] = ffma2(q0.x, d00, nlo[s][0]); nlo[s][0] = ffma2(q0.y, e00, nlo[s][0]);
                nhi[s][0] = ffma2(q0.x, d01, nhi[s][0]); nhi[s][0] = ffma2(q0.y, e01, nhi[s][0]);
                nlo[s][0] = ffma2(q1.x, d10, nlo[s][0]); nlo[s][0] = ffma2(q1.y, e10, nlo[s][0]);
                nhi[s][0] = ffma2(q1.x, d11, nhi[s][0]); nhi[s][0] = ffma2(q1.y, e11, nhi[s][0]);
                nlo[s][0] = ffma2(q2.x, d20, nlo[s][0]); nlo[s][0] = ffma2(q2.y, e20, nlo[s][0]);
                nhi[s][0] = ffma2(q2.x, d21, nhi[s][0]); nhi[s][0] = ffma2(q2.y, e21, nhi[s][0]);

                ulonglong2 q9  = q[so7[3] + cp], q10 = q[so7[4] + cp];
                ulonglong2 q11 = q[so7[5] + cp], q12 = q[so7[6] + cp];
                nlo[s][1] = ffma2(q9.x,  d00, nlo[s][1]); nlo[s][1] = ffma2(q9.y,  e00, nlo[s][1]);
                nhi[s][1] = ffma2(q9.x,  d01, nhi[s][1]); nhi[s][1] = ffma2(q9.y,  e01, nhi[s][1]);
                nlo[s][1] = ffma2(q10.x, d10, nlo[s][1]); nlo[s][1] = ffma2(q10.y, e10, nlo[s][1]);
                nhi[s][1] = ffma2(q10.x, d11, nhi[s][1]); nhi[s][1] = ffma2(q10.y, e11, nhi[s][1]);
                nlo[s][1] = ffma2(q11.x, d20, nlo[s][1]); nlo[s][1] = ffma2(q11.y, e20, nlo[s][1]);
                nhi[s][1] = ffma2(q11.x, d21, nhi[s][1]); nhi[s][1] = ffma2(q11.y, e21, nhi[s][1]);

                nlo[s][2] = ffma2(q10.x, d00, nlo[s][2]); nlo[s][2] = ffma2(q10.y, e00, nlo[s][2]);
                nhi[s][2] = ffma2(q10.x, d01, nhi[s][2]); nhi[s][2] = ffma2(q10.y, e01, nhi[s][2]);
                nlo[s][2] = ffma2(q11.x, d10, nlo[s][2]); nlo[s][2] = ffma2(q11.y, e10, nlo[s][2]);
                nhi[s][2] = ffma2(q11.x, d11, nhi[s][2]); nhi[s][2] = ffma2(q11.y, e11, nhi[s][2]);
                nlo[s][2] = ffma2(q12.x, d20, nlo[s][2]); nlo[s][2] = ffma2(q12.y, e20, nlo[s][2]);
                nhi[s][2] = ffma2(q12.x, d21, nhi[s][2]); nhi[s][2] = ffma2(q12.y, e21, nhi[s][2]);
            }
        }
    };

    // merged tail for all 4 vehicles (unchanged from R11)
    auto tail4 = [&](auto&& gLo0, auto&& gHi0, auto&& gLo1, auto&& gHi1, int t) {
        ull sA0[5] = {0,0,0,0,0}, sB0[5] = {0,0,0,0,0};
        ull sA1[5] = {0,0,0,0,0}, sB1[5] = {0,0,0,0,0};
        #pragma unroll
        for (int jj = 0; jj < 6; ++jj) {
            ull fapA0, fbpA0, fapB0, fbpB0, fapA1, fbpA1, fapB1, fbpB1;
            float aA, aB, bA, bB;
            if (jj < 5) {
                unpk(gLo0(2 * jj), aA, aB); unpk(gLo0(2 * jj + 1), bA, bB);
                fapA0 = pkdup(fmaxf(fmaxf(aA, 0.f), fmaxf(bA, 0.f)));
                fapB0 = pkdup(fmaxf(fmaxf(aB, 0.f), fmaxf(bB, 0.f)));
                unpk(gHi0(2 * jj), aA, aB); unpk(gHi0(2 * jj + 1), bA, bB);
                fbpA0 = pkdup(fmaxf(fmaxf(aA, 0.f), fmaxf(bA, 0.f)));
                fbpB0 = pkdup(fmaxf(fmaxf(aB, 0.f), fmaxf(bB, 0.f)));
                unpk(gLo1(2 * jj), aA, aB); unpk(gLo1(2 * jj + 1), bA, bB);
                fapA1 = pkdup(fmaxf(fmaxf(aA, 0.f), fmaxf(bA, 0.f)));
                fapB1 = pkdup(fmaxf(fmaxf(aB, 0.f), fmaxf(bB, 0.f)));
                unpk(gHi1(2 * jj), aA, aB); unpk(gHi1(2 * jj + 1), bA, bB);
                fbpA1 = pkdup(fmaxf(fmaxf(aA, 0.f), fmaxf(bA, 0.f)));
                fbpB1 = pkdup(fmaxf(fmaxf(aB, 0.f), fmaxf(bB, 0.f)));
            } else {
                unpk(gLo0(10), aA, aB);
                fapA0 = pkdup(fmaxf(aA, 0.f)); fapB0 = pkdup(fmaxf(aB, 0.f));
                unpk(gHi0(10), aA, aB);
                fbpA0 = pkdup(fmaxf(aA, 0.f)); fbpB0 = pkdup(fmaxf(aB, 0.f));
                unpk(gLo1(10), aA, aB);
                fapA1 = pkdup(fmaxf(aA, 0.f)); fapB1 = pkdup(fmaxf(aB, 0.f));
                unpk(gHi1(10), aA, aB);
                fbpA1 = pkdup(fmaxf(aA, 0.f)); fbpB1 = pkdup(fmaxf(aB, 0.f));
            }
            #pragma unroll
            for (int q = 0; q < 5; ++q) {
                ulonglong2 w = wdx[(q * 6 + jj) * 32 + lane];   // one load, 4 vehicles
                sA0[q] = ffma2(fapA0, w.x, sA0[q]); sA0[q] = ffma2(fbpA0, w.y, sA0[q]);
                sB0[q] = ffma2(fapB0, w.x, sB0[q]); sB0[q] = ffma2(fbpB0, w.y, sB0[q]);
                sA1[q] = ffma2(fapA1, w.x, sA1[q]); sA1[q] = ffma2(fbpA1, w.y, sA1[q]);
                sB1[q] = ffma2(fapB1, w.x, sB1[q]); sB1[q] = ffma2(fbpB1, w.y, sB1[q]);
            }
        }
        const bool bit0 = (lane & 1), bit1 = (lane & 2);
        ull r0[5], r1[5], s5[5];
        #pragma unroll
        for (int q = 0; q < 5; ++q) {
            ull z = bit0 ? sB0[q] : sA0[q];
            ull x = bit0 ? sA0[q] : sB0[q];
            r0[q] = addf32x2(z, __shfl_xor_sync(0xffffffffu, x, 1));
            z = bit0 ? sB1[q] : sA1[q];
            x = bit0 ? sA1[q] : sB1[q];
            r1[q] = addf32x2(z, __shfl_xor_sync(0xffffffffu, x, 1));
        }
        #pragma unroll
        for (int q = 0; q < 5; ++q) {
            ull z = bit1 ? r1[q] : r0[q];
            ull x = bit1 ? r0[q] : r1[q];
            s5[q] = addf32x2(z, __shfl_xor_sync(0xffffffffu, x, 2));
        }
        #pragma unroll
        for (int off = 4; off <= 16; off <<= 1) {
            #pragma unroll
            for (int q = 0; q < 5; ++q)
                s5[q] = addf32x2(s5[q], __shfl_xor_sync(0xffffffffu, s5[q], off));
        }
        float d[10];
        #pragma unroll
        for (int q = 0; q < 5; ++q) unpk(s5[q], d[2 * q], d[2 * q + 1]);
        float y = sm[BD1_OFF];
        #pragma unroll
        for (int o = 0; o < 10; ++o)
            y = fmaf(fmaxf(d[o] + sm[BD2_OFF + o], 0.0f), sm[WD1_OFF + o], y);
        float accv = fmaf(10.0f, y, -6.0f);
        float av[4];
        #pragma unroll
        for (int i = 0; i < 4; ++i) av[i] = __shfl_sync(0xffffffffu, accv, i);

        float pp[4], ps[4];
        #pragma unroll
        for (int i = 0; i < 4; ++i) {
            pp[i] = fmaf(0.1f, s24v[i], p24v[i]);
            ps[i] = fmaf(0.1f, av[i],   s24v[i]);
            p24v[i] = pp[i]; s24v[i] = ps[i];
        }
        if (lane < 4) out2base[lane * NT + t] = make_float2(pp[lane], ps[lane]);

        #pragma unroll
        for (int s = 0; s < 2; ++s) {
            xw0[s].x = __shfl_down_sync(0xffffffffu, xw0[s].x, 1);
            xw0[s].y = __shfl_down_sync(0xffffffffu, xw0[s].y, 1);
            xw1[s].x = __shfl_down_sync(0xffffffffu, xw1[s].x, 1);
            xw1[s].y = __shfl_down_sync(0xffffffffu, xw1[s].y, 1);
            xw2[s].x = __shfl_down_sync(0xffffffffu, xw2[s].x, 1);
            xw2[s].y = __shfl_down_sync(0xffffffffu, xw2[s].y, 1);
            if (lane == 24) {
                int iA = 2 * s, iB = 2 * s + 1;
                xw0[s] = make_float2((ldnv[iA].x - pp[iA]) * (1.0f / 200.0f),
                                     (ldnv[iB].x - pp[iB]) * (1.0f / 200.0f));
                xw1[s] = make_float2(ps[iA] * (1.0f / 40.0f), ps[iB] * (1.0f / 40.0f));
                xw2[s] = make_float2(ldnv[iA].y * (1.0f / 40.0f), ldnv[iB].y * (1.0f / 40.0f));
            }
        }
    };

    // ---------- seed steps (full compute) ----------
    ull Rlo0[11], Rhi0[11], Rlo1[11], Rhi1[11];   // even-parity conv2 state (registers)
    if (lane == 24) {
        #pragma unroll
        for (int i = 0; i < 4; ++i) ldnv[i] = lead2base[i * LEADLEN + 0 + PAST];
    }
    publish_full();
    conv1_full(xbuf0, pqE0); conv1_full(xbuf1, pqE1);
    __syncwarp();
    conv2_full(qE0, Rlo0, Rhi0);
    conv2_full(qE1, Rlo1, Rhi1);
    tail4([&](int j){ return Rlo0[j]; }, [&](int j){ return Rhi0[j]; },
          [&](int j){ return Rlo1[j]; }, [&](int j){ return Rhi1[j]; }, 0);

    {
        if (lane == 24) {
            #pragma unroll
            for (int i = 0; i < 4; ++i) ldnv[i] = lead2base[i * LEADLEN + 1 + PAST];
        }
        publish_full();
        conv1_full(xbuf0, pqO0); conv1_full(xbuf1, pqO1);
        __syncwarp();
        ull Tlo[11], Thi[11];
        conv2_full(qO0, Tlo, Thi);
        #pragma unroll
        for (int j = 0; j < 11; ++j) { ScLo0[j * 32 + lane] = Tlo[j]; ScHi0[j * 32 + lane] = Thi[j]; }
        conv2_full(qO1, Tlo, Thi);
        #pragma unroll
        for (int j = 0; j < 11; ++j) { ScLo1[j * 32 + lane] = Tlo[j]; ScHi1[j * 32 + lane] = Thi[j]; }
        #pragma unroll
        for (int j = 0; j < 11; ++j) sidx[j] = j * 32 + lane;   // bS = 0
        tail4([&](int j){ return ScLo0[sidx[j]]; }, [&](int j){ return ScHi0[sidx[j]]; },
              [&](int j){ return ScLo1[sidx[j]]; }, [&](int j){ return ScHi1[sidx[j]]; }, 1);
    }

    // ---------- main incremental loop ----------
    #pragma unroll 1
    for (int t = 2; t < NT; t += 2) {
        // ===== even step t : register conv2 state, pool1-even circular =====
        if (lane == 24) {
            #pragma unroll
            for (int i = 0; i < 4; ++i) ldnv[i] = lead2base[i * LEADLEN + t + PAST];
        }
        bPe = wrap13(bPe + 1);
        {
            int w0i = bPe, w11i = wrap13(bPe + 11), w12i = wrap13(bPe + 12);
            publish_part();
            conv1_fresh(xbuf0, pqE0, w0i, w11i, w12i);
            conv1_fresh(xbuf1, pqE1, w0i, w11i, w12i);
            __syncwarp();
            so7[0] = bPe * 16;
            so7[1] = wrap13(bPe + 1) * 16;
            so7[2] = wrap13(bPe + 2) * 16;
            so7[3] = wrap13(bPe + 9) * 16;
            so7[4] = wrap13(bPe + 10) * 16;
            so7[5] = w11i * 16;
            so7[6] = w12i * 16;
        }
        {
            ull nlo[2][3], nhi[2][3];
            conv2_inc2(qE0, qE1, nlo, nhi);
            Rlo0[0] = nlo[0][0]; Rhi0[0] = nhi[0][0];
            Rlo1[0] = nlo[1][0]; Rhi1[0] = nhi[1][0];
            #pragma unroll
            for (int j = 1; j <= 8; ++j) {
                Rlo0[j] = Rlo0[j + 1]; Rhi0[j] = Rhi0[j + 1];
                Rlo1[j] = Rlo1[j + 1]; Rhi1[j] = Rhi1[j + 1];
            }
            Rlo0[9] = nlo[0][1]; Rlo0[10] = nlo[0][2];
            Rhi0[9] = nhi[0][1]; Rhi0[10] = nhi[0][2];
            Rlo1[9] = nlo[1][1]; Rlo1[10] = nlo[1][2];
            Rhi1[9] = nhi[1][1]; Rhi1[10] = nhi[1][2];
        }
        tail4([&](int j){ return Rlo0[j]; }, [&](int j){ return Rhi0[j]; },
              [&](int j){ return Rlo1[j]; }, [&](int j){ return Rhi1[j]; }, t);

        // ===== odd step t+1 : circular smem conv2 state, pool1-odd circular =====
        #pragma unroll
        for (int i = 0; i < 4; ++i) ldnv[i] = make_float2(0.f, 0.f);
        if (lane == 24 && (t + 1) < NT - 1) {
            #pragma unroll
            for (int i = 0; i < 4; ++i) ldnv[i] = lead2base[i * LEADLEN + t + 1 + PAST];
        }
        bPo = wrap13(bPo + 1);
        {
            int w0i = bPo, w11i = wrap13(bPo + 11), w12i = wrap13(bPo + 12);
            publish_part();
            conv1_fresh(xbuf0, pqO0, w0i, w11i, w12i);
            conv1_fresh(xbuf1, pqO1, w0i, w11i, w12i);
            __syncwarp();
            so7[0] = bPo * 16;
            so7[1] = wrap13(bPo + 1) * 16;
            so7[2] = wrap13(bPo + 2) * 16;
            so7[3] = wrap13(bPo + 9) * 16;
            so7[4] = wrap13(bPo + 10) * 16;
            so7[5] = w11i * 16;
            so7[6] = w12i * 16;
        }
        {
            ull mlo[2][3], mhi[2][3];
            conv2_inc2(qO0, qO1, mlo, mhi);
            bS = wrap11(bS + 1);
            int i0 = bS * 32 + lane;
            int i9 = wrap11(bS + 9) * 32 + lane;
            int iX = wrap11(bS + 10) * 32 + lane;
            ScLo0[i0] = mlo[0][0]; ScLo0[i9] = mlo[0][1]; ScLo0[iX] = mlo[0][2];
            ScHi0[i0] = mhi[0][0]; ScHi0[i9] = mhi[0][1]; ScHi0[iX] = mhi[0][2];
            ScLo1[i0] = mlo[1][0]; ScLo1[i9] = mlo[1][1]; ScLo1[iX] = mlo[1][2];
            ScHi1[i0] = mhi[1][0]; ScHi1[i9] = mhi[1][1]; ScHi1[iX] = mhi[1][2];
            #pragma unroll
            for (int j = 0; j < 11; ++j) sidx[j] = wrap11(bS + j) * 32 + lane;
        }
        tail4([&](int j){ return ScLo0[sidx[j]]; }, [&](int j){ return ScHi0[sidx[j]]; },
              [&](int j){ return ScLo1[sidx[j]]; }, [&](int j){ return ScHi1[sidx[j]]; }, t + 1);
    }
}

extern "C" void kernel_launch(void* const* d_in, const int* in_sizes, int n_in,
                              void* d_out, int out_size)
{
    const float* lead = (const float*)d_in[0];   // (4096, 280, 2)
    const float* cur  = (const float*)d_in[1];   // (4096, 25, 2)
    // d_in[2] = mask (unused by the reference computation)
    const float* w1  = (const float*)d_in[3];
    const float* b1  = (const float*)d_in[4];
    const float* w2  = (const float*)d_in[5];
    const float* b2  = (const float*)d_in[6];
    const float* wd2 = (const float*)d_in[7];
    const float* bd2 = (const float*)d_in[8];
    const float* wd1 = (const float*)d_in[9];
    const float* bd1 = (const float*)d_in[10];
    float* out = (float*)d_out;                   // (4096, 256, 2)

    (void)in_sizes; (void)n_in; (void)out_size;

    size_t smem_bytes = (size_t)SMEM_FLOATS * sizeof(float);   // 225696 B
    cudaFuncSetAttribute(rnncf_kernel,
                         cudaFuncAttributeMaxDynamicSharedMemorySize,
                         (int)smem_bytes);
    rnncf_kernel<<<NCTA, NTHREADS, smem_bytes>>>(
        lead, cur, w1, b1, w2, b2, wd2, bd2, wd1, bd1, out);
}

// round 13
// speedup vs baseline: 3.7755x; 1.0007x over previous
#include <cuda_runtime.h>

#define NVEH 4096
#define NT 256
#define PAST 25
#define LEADLEN (NT + PAST - 1)   // 280
#define NQUAD (NVEH / 4)          // 1024
#define WARPS_PER_CTA 7
#define NCTA ((NQUAD + WARPS_PER_CTA - 1) / WARPS_PER_CTA)   // 147
#define NTHREADS (WARPS_PER_CTA * 32)                         // 224

typedef unsigned long long ull;

// ---- shared memory layout (float offsets) ----
#define W1_OFF    0        // 288  : conv1_w [3][3][32]
#define B1_OFF    288      // 32
#define B2P_OFF   320      // 64   : float2 {b2[c], b2[c+32]}
#define W2X_OFF   384      // 4096 : float4 [ci*32+c] = {w0[c], w0[c+32], w1[c], w1[c+32]}
#define W2K2_OFF  4480     // 2048 : float4 [cp*32+c] = {k2[2cp][c], k2[2cp][c+32], k2[2cp+1][c], k2[2cp+1][c+32]}
#define WD2X_OFF  6528     // 3840 : ull2 [(q*6+jj)*32+c] = {pair_i, pair_{i+32}}
#define BD2_OFF   10368    // 10
#define WD1_OFF   10378    // 10
#define BD1_OFF   10388    // 1 (+3 pad)
#define XBUF_OFF  10392    // 14 sets * 27 pos * 8 floats
#define PQ_OFF    13416    // pool1 circular: 14 sets * 2 parities * 13 slots * 32 * float2
#define SC_OFF    (PQ_OFF + 14 * 2 * 13 * 32 * 2)   // 36712 : conv2 odd state, 14 sets * 2 arr * 11 slots * 32 ull
#define SMEM_FLOATS (SC_OFF + 14 * 2 * 11 * 32 * 2) // 56424 floats = 225696 B

__device__ __forceinline__ ull ffma2(ull a, ull b, ull c) {
    ull d;
    asm("fma.rn.f32x2 %0, %1, %2, %3;" : "=l"(d) : "l"(a), "l"(b), "l"(c));
    return d;
}
__device__ __forceinline__ ull addf32x2(ull a, ull b) {
    ull d;
    asm("add.rn.f32x2 %0, %1, %2;" : "=l"(d) : "l"(a), "l"(b));
    return d;
}
__device__ __forceinline__ void unpk(ull v, float& lo, float& hi) {
    asm("mov.b64 {%0, %1}, %2;" : "=f"(lo), "=f"(hi) : "l"(v));
}
__device__ __forceinline__ ull pkdup(float x) {
    ull d;
    asm("mov.b64 %0, {%1, %1};" : "=l"(d) : "f"(x));
    return d;
}
__device__ __forceinline__ int wrap13(int x) { return x >= 13 ? x - 13 : x; }
__device__ __forceinline__ int wrap11(int x) { return x >= 11 ? x - 11 : x; }

__global__ void __launch_bounds__(NTHREADS, 1)
rnncf_kernel(const float* __restrict__ lead, const float* __restrict__ cur,
             const float* __restrict__ w1g, const float* __restrict__ b1g,
             const float* __restrict__ w2g, const float* __restrict__ b2g,
             const float* __restrict__ wd2g, const float* __restrict__ bd2g,
             const float* __restrict__ wd1g, const float* __restrict__ bd1g,
             float* __restrict__ out)
{
    extern __shared__ float sm[];
    const int tid = threadIdx.x;

    // ---------- cooperative weight staging ----------
    for (int i = tid; i < 288; i += NTHREADS) sm[W1_OFF + i] = w1g[i];
    for (int i = tid; i < 32;  i += NTHREADS) sm[B1_OFF + i] = b1g[i];
    {
        float2* b2p_s = (float2*)(sm + B2P_OFF);
        for (int i = tid; i < 32; i += NTHREADS)
            b2p_s[i] = make_float2(b2g[i], b2g[i + 32]);
        float4* w2x_s = (float4*)(sm + W2X_OFF);
        for (int i = tid; i < 1024; i += NTHREADS) {
            int ci = i >> 5, c = i & 31;
            w2x_s[i] = make_float4(w2g[ci * 64 + c],        w2g[ci * 64 + c + 32],
                                   w2g[(32 + ci) * 64 + c], w2g[(32 + ci) * 64 + c + 32]);
        }
        float4* w2k2_s = (float4*)(sm + W2K2_OFF);
        for (int i = tid; i < 512; i += NTHREADS) {
            int cp = i >> 5, c = i & 31;
            w2k2_s[i] = make_float4(w2g[(64 + 2 * cp) * 64 + c],     w2g[(64 + 2 * cp) * 64 + c + 32],
                                    w2g[(64 + 2 * cp + 1) * 64 + c], w2g[(64 + 2 * cp + 1) * 64 + c + 32]);
        }
        float4* wdx_s = (float4*)(sm + WD2X_OFF);
        for (int i = tid; i < 960; i += NTHREADS) {
            int q = i / 192, r = i - q * 192;
            int jj = r >> 5, c = r & 31;
            int ii = jj * 64 + c;
            wdx_s[i] = make_float4(wd2g[ii * 10 + 2 * q],        wd2g[ii * 10 + 2 * q + 1],
                                   wd2g[(ii + 32) * 10 + 2 * q], wd2g[(ii + 32) * 10 + 2 * q + 1]);
        }
    }
    for (int i = tid; i < 10; i += NTHREADS) sm[BD2_OFF + i] = bd2g[i];
    for (int i = tid; i < 10; i += NTHREADS) sm[WD1_OFF + i] = wd1g[i];
    if (tid == 0) sm[BD1_OFF] = bd1g[0];
    // zero xbuf: borders (pos 0 and 26) must stay zero (pad columns)
    for (int i = tid; i < 14 * 27 * 8; i += NTHREADS) sm[XBUF_OFF + i] = 0.0f;
    __syncthreads();

    const int wid = tid >> 5, lane = tid & 31;
    const int quad = blockIdx.x * WARPS_PER_CTA + wid;
    if (quad >= NQUAD) return;

    float* xbuf0 = sm + XBUF_OFF + (wid * 2 + 0) * (27 * 8);
    float* xbuf1 = sm + XBUF_OFF + (wid * 2 + 1) * (27 * 8);
    // pool1 circular buffers: [set][parity]
    float2* pqE0 = (float2*)(sm + PQ_OFF) + ((wid * 2 + 0) * 2 + 0) * (13 * 32);
    float2* pqO0 = (float2*)(sm + PQ_OFF) + ((wid * 2 + 0) * 2 + 1) * (13 * 32);
    float2* pqE1 = (float2*)(sm + PQ_OFF) + ((wid * 2 + 1) * 2 + 0) * (13 * 32);
    float2* pqO1 = (float2*)(sm + PQ_OFF) + ((wid * 2 + 1) * 2 + 1) * (13 * 32);
    const ulonglong2* qE0 = (const ulonglong2*)pqE0;
    const ulonglong2* qO0 = (const ulonglong2*)pqO0;
    const ulonglong2* qE1 = (const ulonglong2*)pqE1;
    const ulonglong2* qO1 = (const ulonglong2*)pqO1;
    // conv2 odd-parity circular state (11 slots)
    ull* ScLo0 = (ull*)(sm + SC_OFF) + (wid * 2 + 0) * (2 * 11 * 32);
    ull* ScHi0 = ScLo0 + 11 * 32;
    ull* ScLo1 = (ull*)(sm + SC_OFF) + (wid * 2 + 1) * (2 * 11 * 32);
    ull* ScHi1 = ScLo1 + 11 * 32;
    const float4* w2xf   = (const float4*)(sm + W2X_OFF);
    const float4* w2k2f4 = (const float4*)(sm + W2K2_OFF);
    const ulonglong2* wdx = (const ulonglong2*)(sm + WD2X_OFF);

    const float2* lead2base = (const float2*)lead + (size_t)(4 * quad) * LEADLEN;
    float2*       out2base  = (float2*)out + (size_t)(4 * quad) * NT;

    // hoisted packed constants
    ull w1d[9];
    #pragma unroll
    for (int i = 0; i < 9; ++i) w1d[i] = pkdup(sm[W1_OFF + i * 32 + lane]);
    const ull b1d = pkdup(sm[B1_OFF + lane]);
    ull b2lo, b2hi;
    {
        float2 b2v = ((const float2*)(sm + B2P_OFF))[lane];
        b2lo = pkdup(b2v.x);
        b2hi = pkdup(b2v.y);
    }

    // ---------- initial windows: lane i (<25) holds column i, packed {A,B} ----------
    float2 xw0[2], xw1[2], xw2[2];
    #pragma unroll
    for (int s = 0; s < 2; ++s) {
        xw0[s] = make_float2(0.f, 0.f);
        xw1[s] = make_float2(0.f, 0.f);
        xw2[s] = make_float2(0.f, 0.f);
    }
    float p24v[4], s24v[4];
    {
        float tp[4] = {0.f, 0.f, 0.f, 0.f}, ts[4] = {0.f, 0.f, 0.f, 0.f};
        if (lane < PAST) {
            const float2* cur2base = (const float2*)cur + (size_t)(4 * quad) * PAST;
            #pragma unroll
            for (int i = 0; i < 4; ++i) {
                float2 cs = cur2base[i * PAST + lane];
                float2 ld = lead2base[i * LEADLEN + lane];
                float X0 = (ld.x - cs.x) * (1.0f / 200.0f);
                float X1 = cs.y * (1.0f / 40.0f);
                float X2 = ld.y * (1.0f / 40.0f);
                int s = i >> 1;
                if ((i & 1) == 0) { xw0[s].x = X0; xw1[s].x = X1; xw2[s].x = X2; }
                else              { xw0[s].y = X0; xw1[s].y = X1; xw2[s].y = X2; }
                tp[i] = cs.x; ts[i] = cs.y;
            }
        }
        #pragma unroll
        for (int i = 0; i < 4; ++i) {
            p24v[i] = __shfl_sync(0xffffffffu, tp[i], 24);
            s24v[i] = __shfl_sync(0xffffffffu, ts[i], 24);
        }
    }
    float2 ldnv[4];
    #pragma unroll
    for (int i = 0; i < 4; ++i) ldnv[i] = make_float2(0.f, 0.f);

    // circular bases
    int bPe = 0, bPo = 0, bS = 0;
    int so7[7];      // pool1 read offsets (ulonglong2 units) for conv2_inc

    // ---------- helpers ----------
    auto publish_full = [&]() {
        if (lane < PAST) {
            *(float4*)(xbuf0 + (lane + 1) * 8)     = make_float4(xw0[0].x, xw0[0].y, xw1[0].x, xw1[0].y);
            *(float2*)(xbuf0 + (lane + 1) * 8 + 4) = xw2[0];
            *(float4*)(xbuf1 + (lane + 1) * 8)     = make_float4(xw0[1].x, xw0[1].y, xw1[1].x, xw1[1].y);
            *(float2*)(xbuf1 + (lane + 1) * 8 + 4) = xw2[1];
        }
        __syncwarp();
    };
    auto publish_part = [&]() {   // only cols needed by fresh conv positions
        bool w = (lane < 3) || (lane >= 21 && lane < 25);
        if (w) {
            *(float4*)(xbuf0 + (lane + 1) * 8)     = make_float4(xw0[0].x, xw0[0].y, xw1[0].x, xw1[0].y);
            *(float2*)(xbuf0 + (lane + 1) * 8 + 4) = xw2[0];
            *(float4*)(xbuf1 + (lane + 1) * 8)     = make_float4(xw0[1].x, xw0[1].y, xw1[1].x, xw1[1].y);
            *(float2*)(xbuf1 + (lane + 1) * 8 + 4) = xw2[1];
        }
        __syncwarp();
    };

    auto c1p3 = [&](ulonglong2 a01, ull a2, ulonglong2 b01, ull b2_, ulonglong2 c01, ull c2) -> ull {
        ull h = b1d;
        h = ffma2(a01.x, w1d[0], h); h = ffma2(a01.y, w1d[1], h); h = ffma2(a2,  w1d[2], h);
        h = ffma2(b01.x, w1d[3], h); h = ffma2(b01.y, w1d[4], h); h = ffma2(b2_, w1d[5], h);
        h = ffma2(c01.x, w1d[6], h); h = ffma2(c01.y, w1d[7], h); h = ffma2(c2,  w1d[8], h);
        return h;
    };
    auto poolpair = [&](ull h0, ull h1) -> float2 {
        float f0A, f0B, f1A, f1B;
        unpk(h0, f0A, f0B); unpk(h1, f1A, f1B);
        return make_float2(fmaxf(fmaxf(f0A, 0.f), fmaxf(f1A, 0.f)),
                           fmaxf(fmaxf(f0B, 0.f), fmaxf(f1B, 0.f)));
    };
    auto poolone = [&](ull h0) -> float2 {
        float f0A, f0B;
        unpk(h0, f0A, f0B);
        return make_float2(fmaxf(f0A, 0.f), fmaxf(f0B, 0.f));
    };

    auto conv1_full = [&](const float* xb, float2* pd) {   // seeds: all 13 slots at base 0
        ulonglong2 a01 = *(const ulonglong2*)(xb);
        ull        a2  = *(const ull*)(xb + 4);
        ulonglong2 b01 = *(const ulonglong2*)(xb + 8);
        ull        b2_ = *(const ull*)(xb + 12);
        #pragma unroll
        for (int m = 0; m < 12; ++m) {
            ulonglong2 c01 = *(const ulonglong2*)(xb + (2 * m + 2) * 8);
            ull        c2  = *(const ull*)(xb + (2 * m + 2) * 8 + 4);
            ulonglong2 d01 = *(const ulonglong2*)(xb + (2 * m + 3) * 8);
            ull        d2  = *(const ull*)(xb + (2 * m + 3) * 8 + 4);
            ull h0 = c1p3(a01, a2, b01, b2_, c01, c2);
            ull h1 = c1p3(b01, b2_, c01, c2, d01, d2);
            pd[m * 32 + lane] = poolpair(h0, h1);
            a01 = c01; a2 = c2; b01 = d01; b2_ = d2;
        }
        ulonglong2 c01 = *(const ulonglong2*)(xb + 26 * 8);
        ull        c2  = *(const ull*)(xb + 26 * 8 + 4);
        pd[12 * 32 + lane] = poolone(c1p3(a01, a2, b01, b2_, c01, c2));
    };

    // steady-state conv1: only fresh conv positions {0,1,22,23,24}
    auto conv1_fresh = [&](const float* xb, float2* pd, int w0i, int w11i, int w12i) {
        ulonglong2 u1 = *(const ulonglong2*)(xb + 1 * 8);  ull v1 = *(const ull*)(xb + 1 * 8 + 4);   // col0
        ulonglong2 u2 = *(const ulonglong2*)(xb + 2 * 8);  ull v2 = *(const ull*)(xb + 2 * 8 + 4);   // col1
        ulonglong2 u3 = *(const ulonglong2*)(xb + 3 * 8);  ull v3 = *(const ull*)(xb + 3 * 8 + 4);   // col2
        ull h0 = b1d;   // conv pos 0: pad, c0, c1
        h0 = ffma2(u1.x, w1d[3], h0); h0 = ffma2(u1.y, w1d[4], h0); h0 = ffma2(v1, w1d[5], h0);
        h0 = ffma2(u2.x, w1d[6], h0); h0 = ffma2(u2.y, w1d[7], h0); h0 = ffma2(v2, w1d[8], h0);
        ull h1 = c1p3(u1, v1, u2, v2, u3, v3);   // conv pos 1
        pd[w0i * 32 + lane] = poolpair(h0, h1);

        ulonglong2 u22 = *(const ulonglong2*)(xb + 22 * 8); ull v22 = *(const ull*)(xb + 22 * 8 + 4); // col21
        ulonglong2 u23 = *(const ulonglong2*)(xb + 23 * 8); ull v23 = *(const ull*)(xb + 23 * 8 + 4); // col22
        ulonglong2 u24 = *(const ulonglong2*)(xb + 24 * 8); ull v24 = *(const ull*)(xb + 24 * 8 + 4); // col23
        ulonglong2 u25 = *(const ulonglong2*)(xb + 25 * 8); ull v25 = *(const ull*)(xb + 25 * 8 + 4); // col24
        ull g0 = c1p3(u22, v22, u23, v23, u24, v24);   // conv 22
        ull g1 = c1p3(u23, v23, u24, v24, u25, v25);   // conv 23
        ull g2 = b1d;   // conv 24: c23, c24, pad
        g2 = ffma2(u24.x, w1d[0], g2); g2 = ffma2(u24.y, w1d[1], g2); g2 = ffma2(v24, w1d[2], g2);
        g2 = ffma2(u25.x, w1d[3], g2); g2 = ffma2(u25.y, w1d[4], g2); g2 = ffma2(v25, w1d[5], g2);
        pd[w11i * 32 + lane] = poolpair(g0, g1);
        pd[w12i * 32 + lane] = poolone(g2);
    };

    // seeds: all 11 conv2 positions for one set (buffer at base 0)
    auto conv2_full = [&](const ulonglong2* q, ull* Lo, ull* Hi) {
        #pragma unroll
        for (int j = 0; j < 11; ++j) { Lo[j] = b2lo; Hi[j] = b2hi; }
        #pragma unroll 1
        for (int cp = 0; cp < 16; ++cp) {
            float4 wa0 = w2xf[(2 * cp)     * 32 + lane];
            float4 wa1 = w2xf[(2 * cp + 1) * 32 + lane];
            float4 kk  = w2k2f4[cp * 32 + lane];
            ull d00 = pkdup(wa0.x), d01 = pkdup(wa0.y), d10 = pkdup(wa0.z), d11 = pkdup(wa0.w);
            ull e00 = pkdup(wa1.x), e01 = pkdup(wa1.y), e10 = pkdup(wa1.z), e11 = pkdup(wa1.w);
            ull d20 = pkdup(kk.x),  d21 = pkdup(kk.y),  e20 = pkdup(kk.z),  e21 = pkdup(kk.w);
            #pragma unroll
            for (int m = 0; m < 13; ++m) {
                ulonglong2 qp = q[m * 16 + cp];
                if (m <= 10) {
                    Lo[m] = ffma2(qp.x, d00, Lo[m]); Lo[m] = ffma2(qp.y, e00, Lo[m]);
                    Hi[m] = ffma2(qp.x, d01, Hi[m]); Hi[m] = ffma2(qp.y, e01, Hi[m]);
                }
                if (m >= 1 && m <= 11) {
                    Lo[m-1] = ffma2(qp.x, d10, Lo[m-1]); Lo[m-1] = ffma2(qp.y, e10, Lo[m-1]);
                    Hi[m-1] = ffma2(qp.x, d11, Hi[m-1]); Hi[m-1] = ffma2(qp.y, e11, Hi[m-1]);
                }
                if (m >= 2) {
                    Lo[m-2] = ffma2(qp.x, d20, Lo[m-2]); Lo[m-2] = ffma2(qp.y, e20, Lo[m-2]);
                    Hi[m-2] = ffma2(qp.x, d21, Hi[m-2]); Hi[m-2] = ffma2(qp.y, e21, Hi[m-2]);
                }
            }
        }
    };

    // incremental: fresh conv2 positions {0,9,10}, both sets, reads via hoisted so7
    auto conv2_inc2 = [&](const ulonglong2* qs0, const ulonglong2* qs1,
                          ull (&nlo)[2][3], ull (&nhi)[2][3]) {
        #pragma unroll
        for (int s = 0; s < 2; ++s) {
            nlo[s][0] = nlo[s][1] = nlo[s][2] = b2lo;
            nhi[s][0] = nhi[s][1] = nhi[s][2] = b2hi;
        }
        #pragma unroll 4
        for (int cp = 0; cp < 16; ++cp) {
            float4 wa0 = w2xf[(2 * cp)     * 32 + lane];
            float4 wa1 = w2xf[(2 * cp + 1) * 32 + lane];
            float4 kk  = w2k2f4[cp * 32 + lane];
            ull d00 = pkdup(wa0.x), d01 = pkdup(wa0.y), d10 = pkdup(wa0.z), d11 = pkdup(wa0.w);
            ull e00 = pkdup(wa1.x), e01 = pkdup(wa1.y), e10 = pkdup(wa1.z), e11 = pkdup(wa1.w);
            ull d20 = pkdup(kk.x),  d21 = pkdup(kk.y),  e20 = pkdup(kk.z),  e21 = pkdup(kk.w);
            #pragma unroll
            for (int s = 0; s < 2; ++s) {
                const ulonglong2* q = s ? qs1 : qs0;
                ulonglong2 q0 = q[so7[0] + cp], q1 = q[so7[1] + cp], q2 = q[so7[2] + cp];
                nlo[s][0] = ffma2(q0.x, d00, nlo[s][0]); nlo[s][0] = ffma2(q0.y, e00, nlo[s][0]);
                nhi[s][0] = ffma2(q0.x, d01, nhi[s][0]); nhi[s][0] = ffma2(q0.y, e01, nhi[s][0]);
                nlo[s][0] = ffma2(q1.x, d10, nlo[s][0]); nlo[s][0] = ffma2(q1.y, e10, nlo[s][0]);
                nhi[s][0] = ffma2(q1.x, d11, nhi[s][0]); nhi[s][0] = ffma2(q1.y, e11, nhi[s][0]);
                nlo[s][0] = ffma2(q2.x, d20, nlo[s][0]); nlo[s][0] = ffma2(q2.y, e20, nlo[s][0]);
                nhi[s][0] = ffma2(q2.x, d21, nhi[s][0]); nhi[s][0] = ffma2(q2.y, e21, nhi[s][0]);

                ulonglong2 q9  = q[so7[3] + cp], q10 = q[so7[4] + cp];
                ulonglong2 q11 = q[so7[5] + cp], q12 = q[so7[6] + cp];
                nlo[s][1] = ffma2(q9.x,  d00, nlo[s][1]); nlo[s][1] = ffma2(q9.y,  e00, nlo[s][1]);
                nhi[s][1] = ffma2(q9.x,  d01, nhi[s][1]); nhi[s][1] = ffma2(q9.y,  e01, nhi[s][1]);
                nlo[s][1] = ffma2(q10.x, d10, nlo[s][1]); nlo[s][1] = ffma2(q10.y, e10, nlo[s][1]);
                nhi[s][1] = ffma2(q10.x, d11, nhi[s][1]); nhi[s][1] = ffma2(q10.y, e11, nhi[s][1]);
                nlo[s][1] = ffma2(q11.x, d20, nlo[s][1]); nlo[s][1] = ffma2(q11.y, e20, nlo[s][1]);
                nhi[s][1] = ffma2(q11.x, d21, nhi[s][1]); nhi[s][1] = ffma2(q11.y, e21, nhi[s][1]);

                nlo[s][2] = ffma2(q10.x, d00, nlo[s][2]); nlo[s][2] = ffma2(q10.y, e00, nlo[s][2]);
                nhi[s][2] = ffma2(q10.x, d01, nhi[s][2]); nhi[s][2] = ffma2(q10.y, e01, nhi[s][2]);
                nlo[s][2] = ffma2(q11.x, d10, nlo[s][2]); nlo[s][2] = ffma2(q11.y, e10, nlo[s][2]);
                nhi[s][2] = ffma2(q11.x, d11, nhi[s][2]); nhi[s][2] = ffma2(q11.y, e11, nhi[s][2]);
                nlo[s][2] = ffma2(q12.x, d20, nlo[s][2]); nlo[s][2] = ffma2(q12.y, e20, nlo[s][2]);
                nhi[s][2] = ffma2(q12.x, d21, nhi[s][2]); nhi[s][2] = ffma2(q12.y, e21, nhi[s][2]);
            }
        }
    };

    // merged tail for all 4 vehicles
    auto tail4 = [&](auto&& gLo0, auto&& gHi0, auto&& gLo1, auto&& gHi1, int t) {
        ull sA0[5] = {0,0,0,0,0}, sB0[5] = {0,0,0,0,0};
        ull sA1[5] = {0,0,0,0,0}, sB1[5] = {0,0,0,0,0};
        #pragma unroll
        for (int jj = 0; jj < 6; ++jj) {
            ull fapA0, fbpA0, fapB0, fbpB0, fapA1, fbpA1, fapB1, fbpB1;
            float aA, aB, bA, bB;
            if (jj < 5) {
                unpk(gLo0(2 * jj), aA, aB); unpk(gLo0(2 * jj + 1), bA, bB);
                fapA0 = pkdup(fmaxf(fmaxf(aA, 0.f), fmaxf(bA, 0.f)));
                fapB0 = pkdup(fmaxf(fmaxf(aB, 0.f), fmaxf(bB, 0.f)));
                unpk(gHi0(2 * jj), aA, aB); unpk(gHi0(2 * jj + 1), bA, bB);
                fbpA0 = pkdup(fmaxf(fmaxf(aA, 0.f), fmaxf(bA, 0.f)));
                fbpB0 = pkdup(fmaxf(fmaxf(aB, 0.f), fmaxf(bB, 0.f)));
                unpk(gLo1(2 * jj), aA, aB); unpk(gLo1(2 * jj + 1), bA, bB);
                fapA1 = pkdup(fmaxf(fmaxf(aA, 0.f), fmaxf(bA, 0.f)));
                fapB1 = pkdup(fmaxf(fmaxf(aB, 0.f), fmaxf(bB, 0.f)));
                unpk(gHi1(2 * jj), aA, aB); unpk(gHi1(2 * jj + 1), bA, bB);
                fbpA1 = pkdup(fmaxf(fmaxf(aA, 0.f), fmaxf(bA, 0.f)));
                fbpB1 = pkdup(fmaxf(fmaxf(aB, 0.f), fmaxf(bB, 0.f)));
            } else {
                unpk(gLo0(10), aA, aB);
                fapA0 = pkdup(fmaxf(aA, 0.f)); fapB0 = pkdup(fmaxf(aB, 0.f));
                unpk(gHi0(10), aA, aB);
                fbpA0 = pkdup(fmaxf(aA, 0.f)); fbpB0 = pkdup(fmaxf(aB, 0.f));
                unpk(gLo1(10), aA, aB);
                fapA1 = pkdup(fmaxf(aA, 0.f)); fapB1 = pkdup(fmaxf(aB, 0.f));
                unpk(gHi1(10), aA, aB);
                fbpA1 = pkdup(fmaxf(aA, 0.f)); fbpB1 = pkdup(fmaxf(aB, 0.f));
            }
            #pragma unroll
            for (int q = 0; q < 5; ++q) {
                ulonglong2 w = wdx[(q * 6 + jj) * 32 + lane];   // one load, 4 vehicles
                sA0[q] = ffma2(fapA0, w.x, sA0[q]); sA0[q] = ffma2(fbpA0, w.y, sA0[q]);
                sB0[q] = ffma2(fapB0, w.x, sB0[q]); sB0[q] = ffma2(fbpB0, w.y, sB0[q]);
                sA1[q] = ffma2(fapA1, w.x, sA1[q]); sA1[q] = ffma2(fbpA1, w.y, sA1[q]);
                sB1[q] = ffma2(fapB1, w.x, sB1[q]); sB1[q] = ffma2(fbpB1, w.y, sB1[q]);
            }
        }
        const bool bit0 = (lane & 1), bit1 = (lane & 2);
        ull r0[5], r1[5], s5[5];
        #pragma unroll
        for (int q = 0; q < 5; ++q) {
            ull z = bit0 ? sB0[q] : sA0[q];
            ull x = bit0 ? sA0[q] : sB0[q];
            r0[q] = addf32x2(z, __shfl_xor_sync(0xffffffffu, x, 1));
            z = bit0 ? sB1[q] : sA1[q];
            x = bit0 ? sA1[q] : sB1[q];
            r1[q] = addf32x2(z, __shfl_xor_sync(0xffffffffu, x, 1));
        }
        #pragma unroll
        for (int q = 0; q < 5; ++q) {
            ull z = bit1 ? r1[q] : r0[q];
            ull x = bit1 ? r0[q] : r1[q];
            s5[q] = addf32x2(z, __shfl_xor_sync(0xffffffffu, x, 2));
        }
        #pragma unroll
        for (int off = 4; off <= 16; off <<= 1) {
            #pragma unroll
            for (int q = 0; q < 5; ++q)
                s5[q] = addf32x2(s5[q], __shfl_xor_sync(0xffffffffu, s5[q], off));
        }
        float d[10];
        #pragma unroll
        for (int q = 0; q < 5; ++q) unpk(s5[q], d[2 * q], d[2 * q + 1]);
        float y = sm[BD1_OFF];
        #pragma unroll
        for (int o = 0; o < 10; ++o)
            y = fmaf(fmaxf(d[o] + sm[BD2_OFF + o], 0.0f), sm[WD1_OFF + o], y);
        float accv = fmaf(10.0f, y, -6.0f);
        float av[4];
        #pragma unroll
        for (int i = 0; i < 4; ++i) av[i] = __shfl_sync(0xffffffffu, accv, i);

        float pp[4], ps[4];
        #pragma unroll
        for (int i = 0; i < 4; ++i) {
            pp[i] = fmaf(0.1f, s24v[i], p24v[i]);
            ps[i] = fmaf(0.1f, av[i],   s24v[i]);
            p24v[i] = pp[i]; s24v[i] = ps[i];
        }
        if (lane < 4) out2base[lane * NT + t] = make_float2(pp[lane], ps[lane]);

        #pragma unroll
        for (int s = 0; s < 2; ++s) {
            xw0[s].x = __shfl_down_sync(0xffffffffu, xw0[s].x, 1);
            xw0[s].y = __shfl_down_sync(0xffffffffu, xw0[s].y, 1);
            xw1[s].x = __shfl_down_sync(0xffffffffu, xw1[s].x, 1);
            xw1[s].y = __shfl_down_sync(0xffffffffu, xw1[s].y, 1);
            xw2[s].x = __shfl_down_sync(0xffffffffu, xw2[s].x, 1);
            xw2[s].y = __shfl_down_sync(0xffffffffu, xw2[s].y, 1);
            if (lane == 24) {
                int iA = 2 * s, iB = 2 * s + 1;
                xw0[s] = make_float2((ldnv[iA].x - pp[iA]) * (1.0f / 200.0f),
                                     (ldnv[iB].x - pp[iB]) * (1.0f / 200.0f));
                xw1[s] = make_float2(ps[iA] * (1.0f / 40.0f), ps[iB] * (1.0f / 40.0f));
                xw2[s] = make_float2(ldnv[iA].y * (1.0f / 40.0f), ldnv[iB].y * (1.0f / 40.0f));
            }
        }
    };

    // ---------- seed steps (full compute) ----------
    ull Rlo0[11], Rhi0[11], Rlo1[11], Rhi1[11];   // even-parity conv2 state (registers)
    if (lane == 24) {
        #pragma unroll
        for (int i = 0; i < 4; ++i) ldnv[i] = lead2base[i * LEADLEN + 0 + PAST];
    }
    publish_full();
    conv1_full(xbuf0, pqE0); conv1_full(xbuf1, pqE1);
    __syncwarp();
    conv2_full(qE0, Rlo0, Rhi0);
    conv2_full(qE1, Rlo1, Rhi1);
    tail4([&](int j){ return Rlo0[j]; }, [&](int j){ return Rhi0[j]; },
          [&](int j){ return Rlo1[j]; }, [&](int j){ return Rhi1[j]; }, 0);

    {
        if (lane == 24) {
            #pragma unroll
            for (int i = 0; i < 4; ++i) ldnv[i] = lead2base[i * LEADLEN + 1 + PAST];
        }
        publish_full();
        conv1_full(xbuf0, pqO0); conv1_full(xbuf1, pqO1);
        __syncwarp();
        ull Tlo0[11], Thi0[11], Tlo1[11], Thi1[11];
        conv2_full(qO0, Tlo0, Thi0);
        conv2_full(qO1, Tlo1, Thi1);
        // tail from registers; write state afterward (bS = 0)
        tail4([&](int j){ return Tlo0[j]; }, [&](int j){ return Thi0[j]; },
              [&](int j){ return Tlo1[j]; }, [&](int j){ return Thi1[j]; }, 1);
        #pragma unroll
        for (int j = 0; j < 11; ++j) {
            ScLo0[j * 32 + lane] = Tlo0[j]; ScHi0[j * 32 + lane] = Thi0[j];
            ScLo1[j * 32 + lane] = Tlo1[j]; ScHi1[j * 32 + lane] = Thi1[j];
        }
    }

    // ---------- main incremental loop ----------
    #pragma unroll 1
    for (int t = 2; t < NT; t += 2) {
        // ===== even step t : register conv2 state, pool1-even circular =====
        if (lane == 24) {
            #pragma unroll
            for (int i = 0; i < 4; ++i) ldnv[i] = lead2base[i * LEADLEN + t + PAST];
        }
        bPe = wrap13(bPe + 1);
        {
            int w0i = bPe, w11i = wrap13(bPe + 11), w12i = wrap13(bPe + 12);
            publish_part();
            conv1_fresh(xbuf0, pqE0, w0i, w11i, w12i);
            conv1_fresh(xbuf1, pqE1, w0i, w11i, w12i);
            __syncwarp();
            so7[0] = bPe * 16;
            so7[1] = wrap13(bPe + 1) * 16;
            so7[2] = wrap13(bPe + 2) * 16;
            so7[3] = wrap13(bPe + 9) * 16;
            so7[4] = wrap13(bPe + 10) * 16;
            so7[5] = w11i * 16;
            so7[6] = w12i * 16;
        }
        {
            ull nlo[2][3], nhi[2][3];
            conv2_inc2(qE0, qE1, nlo, nhi);
            Rlo0[0] = nlo[0][0]; Rhi0[0] = nhi[0][0];
            Rlo1[0] = nlo[1][0]; Rhi1[0] = nhi[1][0];
            #pragma unroll
            for (int j = 1; j <= 8; ++j) {
                Rlo0[j] = Rlo0[j + 1]; Rhi0[j] = Rhi0[j + 1];
                Rlo1[j] = Rlo1[j + 1]; Rhi1[j] = Rhi1[j + 1];
            }
            Rlo0[9] = nlo[0][1]; Rlo0[10] = nlo[0][2];
            Rhi0[9] = nhi[0][1]; Rhi0[10] = nhi[0][2];
            Rlo1[9] = nlo[1][1]; Rlo1[10] = nlo[1][2];
            Rhi1[9] = nhi[1][1]; Rhi1[10] = nhi[1][2];
        }
        tail4([&](int j){ return Rlo0[j]; }, [&](int j){ return Rhi0[j]; },
              [&](int j){ return Rlo1[j]; }, [&](int j){ return Rhi1[j]; }, t);

        // ===== odd step t+1 : circular smem conv2 state, pool1-odd circular =====
        #pragma unroll
        for (int i = 0; i < 4; ++i) ldnv[i] = make_float2(0.f, 0.f);
        if (lane == 24 && (t + 1) < NT - 1) {
            #pragma unroll
            for (int i = 0; i < 4; ++i) ldnv[i] = lead2base[i * LEADLEN + t + 1 + PAST];
        }
        bPo = wrap13(bPo + 1);
        {
            int w0i = bPo, w11i = wrap13(bPo + 11), w12i = wrap13(bPo + 12);
            publish_part();
            conv1_fresh(xbuf0, pqO0, w0i, w11i, w12i);
            conv1_fresh(xbuf1, pqO1, w0i, w11i, w12i);
            __syncwarp();
            so7[0] = bPo * 16;
            so7[1] = wrap13(bPo + 1) * 16;
            so7[2] = wrap13(bPo + 2) * 16;
            so7[3] = wrap13(bPo + 9) * 16;
            so7[4] = wrap13(bPo + 10) * 16;
            so7[5] = w11i * 16;
            so7[6] = w12i * 16;
        }
        {
            ull mlo[2][3], mhi[2][3];
            conv2_inc2(qO0, qO1, mlo, mhi);
            bS = wrap11(bS + 1);
            // tail: fresh positions {0,9,10} forwarded from registers (no STS->LDS
            // roundtrip); old positions 1..8 read from circular smem state.
            tail4(
              [&](int j){ return j == 0 ? mlo[0][0] : (j == 9 ? mlo[0][1] : (j == 10 ? mlo[0][2]
                               : ScLo0[wrap11(bS + j) * 32 + lane])); },
              [&](int j){ return j == 0 ? mhi[0][0] : (j == 9 ? mhi[0][1] : (j == 10 ? mhi[0][2]
                               : ScHi0[wrap11(bS + j) * 32 + lane])); },
              [&](int j){ return j == 0 ? mlo[1][0] : (j == 9 ? mlo[1][1] : (j == 10 ? mlo[1][2]
                               : ScLo1[wrap11(bS + j) * 32 + lane])); },
              [&](int j){ return j == 0 ? mhi[1][0] : (j == 9 ? mhi[1][1] : (j == 10 ? mhi[1][2]
                               : ScHi1[wrap11(bS + j) * 32 + lane])); },
              t + 1);
            // deferred state writes (needed first at step t+3; slots disjoint from reads)
            int i0 = bS * 32 + lane;
            int i9 = wrap11(bS + 9) * 32 + lane;
            int iX = wrap11(bS + 10) * 32 + lane;
            ScLo0[i0] = mlo[0][0]; ScLo0[i9] = mlo[0][1]; ScLo0[iX] = mlo[0][2];
            ScHi0[i0] = mhi[0][0]; ScHi0[i9] = mhi[0][1]; ScHi0[iX] = mhi[0][2];
            ScLo1[i0] = mlo[1][0]; ScLo1[i9] = mlo[1][1]; ScLo1[iX] = mlo[1][2];
            ScHi1[i0] = mhi[1][0]; ScHi1[i9] = mhi[1][1]; ScHi1[iX] = mhi[1][2];
        }
    }
}

extern "C" void kernel_launch(void* const* d_in, const int* in_sizes, int n_in,
                              void* d_out, int out_size)
{
    const float* lead = (const float*)d_in[0];   // (4096, 280, 2)
    const float* cur  = (const float*)d_in[1];   // (4096, 25, 2)
    // d_in[2] = mask (unused by the reference computation)
    const float* w1  = (const float*)d_in[3];
    const float* b1  = (const float*)d_in[4];
    const float* w2  = (const float*)d_in[5];
    const float* b2  = (const float*)d_in[6];
    const float* wd2 = (const float*)d_in[7];
    const float* bd2 = (const float*)d_in[8];
    const float* wd1 = (const float*)d_in[9];
    const float* bd1 = (const float*)d_in[10];
    float* out = (float*)d_out;                   // (4096, 256, 2)

    (void)in_sizes; (void)n_in; (void)out_size;

    size_t smem_bytes = (size_t)SMEM_FLOATS * sizeof(float);   // 225696 B
    cudaFuncSetAttribute(rnncf_kernel,
                         cudaFuncAttributeMaxDynamicSharedMemorySize,
                         (int)smem_bytes);
    rnncf_kernel<<<NCTA, NTHREADS, smem_bytes>>>(
        lead, cur, w1, b1, w2, b2, wd2, bd2, wd1, bd1, out);
}